// round 7
// baseline (speedup 1.0000x reference)
#include <cuda_runtime.h>
#include <cuda_bf16.h>
#include <cfloat>
#include <math.h>

// ---------------- problem constants ----------------
#define BB 4
#define SS 1024
#define DD 2048
#define HQ 16
#define HKV 8
#define HD 128
#define GRP 2
#define EE 8
#define FE 1024
#define FS 8192
#define TT (BB*SS)
#define EPS 1e-6f

// ---------------- scratch layout (float units) ----------------
#define SZ_TD   ((size_t)TT*DD)        // 8.39M
#define SZ_TQ   ((size_t)TT*HQ*HD)     // 8.39M
#define SZ_TKV  ((size_t)TT*HKV*HD)    // 4.19M
#define SZ_TFS  ((size_t)TT*FS)        // 33.5M

#define OFF_LNXH  ((size_t)0)
#define OFF_LNXL  (OFF_LNXH + SZ_TD/2)
#define OFF_QF    (OFF_LNXL + SZ_TD/2)
#define OFF_KF    (OFF_QF   + SZ_TQ)
#define OFF_VF    (OFF_KF   + SZ_TKV)
#define OFF_QH    (OFF_VF   + SZ_TKV)
#define OFF_QL    (OFF_QH   + SZ_TQ/2)
#define OFF_KH    (OFF_QL   + SZ_TQ/2)
#define OFF_KL    (OFF_KH   + SZ_TKV/2)
#define OFF_VH    (OFF_KL   + SZ_TKV/2)
#define OFF_VL    (OFF_VH   + SZ_TKV/2)
#define OFF_OBH   (OFF_VL   + SZ_TKV/2)
#define OFF_OBL   (OFF_OBH  + SZ_TQ/2)
#define OFF_ATTN  (OFF_OBL  + SZ_TQ/2)
#define OFF_H     (OFF_ATTN + SZ_TD)
#define OFF_FFINH (OFF_H    + SZ_TD)
#define OFF_FFINL (OFF_FFINH+ SZ_TD/2)
#define OFF_G0H   (OFF_FFINL+ SZ_TD/2)
#define OFF_G0L   (OFF_G0H  + SZ_TFS/2)
#define OFF_SHB   (OFF_G0L  + SZ_TFS/2)
#define OFF_RINH  (OFF_SHB  + SZ_TD)
#define OFF_RINL  (OFF_RINH + SZ_TD/2)
#define OFF_GIN   (OFF_RINL + SZ_TD/2)
#define OFF_ROUT  (OFF_GIN  + SZ_TD)
#define OFF_EGH   (OFF_ROUT + SZ_TD)
#define OFF_EGL   (OFF_EGH  + SZ_TFS/2)
#define OFF_COMB  (OFF_EGL  + SZ_TFS/2)
#define OFF_PSUM  (OFF_COMB + (size_t)TT*EE)
// weights (split planes)
#define SZ_WQ  ((size_t)DD*HQ*HD)
#define SZ_WK  ((size_t)DD*HKV*HD)
#define SZ_WFF ((size_t)DD*FS)
#define SZ_EW  ((size_t)EE*DD*FE)
#define OFF_WQH   (OFF_PSUM + 8)
#define OFF_WQL   (OFF_WQH + SZ_WQ/2)
#define OFF_WKH   (OFF_WQL + SZ_WQ/2)
#define OFF_WKL   (OFF_WKH + SZ_WK/2)
#define OFF_WVH   (OFF_WKL + SZ_WK/2)
#define OFF_WVL   (OFF_WVH + SZ_WK/2)
#define OFF_WOH   (OFF_WVL + SZ_WK/2)
#define OFF_WOL   (OFF_WOH + SZ_WQ/2)
#define OFF_WI0H  (OFF_WOL + SZ_WQ/2)
#define OFF_WI0L  (OFF_WI0H + SZ_WFF/2)
#define OFF_WI1H  (OFF_WI0L + SZ_WFF/2)
#define OFF_WI1L  (OFF_WI1H + SZ_WFF/2)
#define OFF_SWOH  (OFF_WI1L + SZ_WFF/2)
#define OFF_SWOL  (OFF_SWOH + SZ_WFF/2)
#define OFF_EWI0H (OFF_SWOL + SZ_WFF/2)
#define OFF_EWI0L (OFF_EWI0H + SZ_EW/2)
#define OFF_EWI1H (OFF_EWI0L + SZ_EW/2)
#define OFF_EWI1L (OFF_EWI1H + SZ_EW/2)
#define OFF_EWOH  (OFF_EWI1L + SZ_EW/2)
#define OFF_EWOL  (OFF_EWOH + SZ_EW/2)
#define SCRATCH_TOTAL (OFF_EWOL + SZ_EW/2)

__device__ float g_scratch[SCRATCH_TOTAL];
__device__ int   g_iscratch[EE*TT + EE];

// ---------------- helpers ----------------
__device__ __forceinline__ float gelu_tanh(float v) {
    const float c = 0.7978845608028654f;
    float u = c * (v + 0.044715f * v * v * v);
    return 0.5f * v * (1.0f + tanhf(u));
}
__device__ __forceinline__ unsigned pack_bf16(float x, float y) {
    __nv_bfloat162 t = __floats2bfloat162_rn(x, y);
    return *reinterpret_cast<unsigned*>(&t);
}
__device__ __forceinline__ void split_pack(float x, float y,
                                           unsigned &hiW, unsigned &loW0) {
    __nv_bfloat16 bx = __float2bfloat16_rn(x);
    __nv_bfloat16 by = __float2bfloat16_rn(y);
    float hx = __bfloat162float(bx);
    float hy = __bfloat162float(by);
    __nv_bfloat162 h2; h2.x = bx; h2.y = by;
    hiW = *reinterpret_cast<unsigned*>(&h2);
    loW0 = pack_bf16(x - hx, y - hy);
}
__device__ __forceinline__ void cp16(unsigned dst, const void* src, int srcBytes) {
    asm volatile("cp.async.cg.shared.global [%0], [%1], 16, %2;"
                 :: "r"(dst), "l"(src), "r"(srcBytes));
}
#define CP_COMMIT() asm volatile("cp.async.commit_group;")
#define CP_WAIT0()  asm volatile("cp.async.wait_group 0;")

#define LDSM4(r0,r1,r2,r3,addr) \
    asm volatile("ldmatrix.sync.aligned.m8n8.x4.shared.b16 {%0,%1,%2,%3}, [%4];" \
                 : "=r"(r0),"=r"(r1),"=r"(r2),"=r"(r3) : "r"(addr))
#define LDSM4T(r0,r1,r2,r3,addr) \
    asm volatile("ldmatrix.sync.aligned.m8n8.x4.trans.shared.b16 {%0,%1,%2,%3}, [%4];" \
                 : "=r"(r0),"=r"(r1),"=r"(r2),"=r"(r3) : "r"(addr))
#define MMA_BF16(d0,d1,d2,d3,a0,a1,a2,a3,b0,b1) \
    asm volatile("mma.sync.aligned.m16n8k16.row.col.f32.bf16.bf16.f32 " \
                 "{%0,%1,%2,%3}, {%4,%5,%6,%7}, {%8,%9}, {%0,%1,%2,%3};" \
                 : "+f"(d0),"+f"(d1),"+f"(d2),"+f"(d3) \
                 : "r"(a0),"r"(a1),"r"(a2),"r"(a3),"r"(b0),"r"(b1))

// ---------------- split (f32 -> bf16 hi/lo planes) ----------------
__global__ void split_kernel(const float2* __restrict__ in,
                             unsigned* __restrict__ hi,
                             unsigned* __restrict__ lo, size_t nWords)
{
    size_t i = (size_t)blockIdx.x * 256 + threadIdx.x;
    if (i < nWords) {
        float2 v = in[i];
        unsigned h, l;
        split_pack(v.x, v.y, h, l);
        hi[i] = h; lo[i] = l;
    }
}

// ---------------- RMS norm over D=2048 ----------------
// If outH: writes packed hi/lo planes. Else writes f32 out.
__global__ void rms_kernel(const float* __restrict__ in,
                           const float* __restrict__ scale, float cmul,
                           const float* __restrict__ res1,
                           const float* __restrict__ res2,
                           const float* __restrict__ scalarPtr,
                           float* __restrict__ out,
                           unsigned* __restrict__ outH,
                           unsigned* __restrict__ outL)
{
    int row = blockIdx.x;
    int tid = threadIdx.x;
    const float* xr = in + (size_t)row * DD;
    float ss = 0.f;
    for (int d = tid; d < DD; d += 256) { float v = xr[d]; ss += v * v; }
    for (int o = 16; o > 0; o >>= 1) ss += __shfl_xor_sync(0xffffffffu, ss, o);
    __shared__ float wsum[8];
    if ((tid & 31) == 0) wsum[tid >> 5] = ss;
    __syncthreads();
    float tot = 0.f;
    #pragma unroll
    for (int w = 0; w < 8; w++) tot += wsum[w];
    float inv = rsqrtf(tot * (1.0f / DD) + EPS);
    float sc = scalarPtr ? *scalarPtr : 1.0f;
    if (outH) {
        for (int d = 2 * tid; d < DD; d += 512) {
            float y0 = xr[d] * inv, y1 = xr[d + 1] * inv;
            if (scale) { y0 *= scale[d]; y1 *= scale[d + 1]; }
            y0 *= cmul; y1 *= cmul;
            unsigned h, l;
            split_pack(y0, y1, h, l);
            size_t w = (size_t)row * (DD / 2) + d / 2;
            outH[w] = h; outL[w] = l;
        }
    } else {
        for (int d = tid; d < DD; d += 256) {
            float y = xr[d] * inv;
            if (scale) y *= scale[d];
            y *= cmul;
            if (res1) y += res1[(size_t)row * DD + d];
            if (res2) y += res2[(size_t)row * DD + d];
            out[(size_t)row * DD + d] = y * sc;
        }
    }
}

// ---------------- per-head RMS (+ RoPE) -> packed planes ----------------
__global__ void head_norm_rope_kernel(const float* __restrict__ in,
                                      unsigned* __restrict__ outH,
                                      unsigned* __restrict__ outL,
                                      const float* __restrict__ scale,
                                      const int* __restrict__ positions,
                                      int H, int doRope)
{
    int idx = blockIdx.x;
    int tid = threadIdx.x;
    int s = (idx / H) % SS;
    int b = idx / (H * SS);
    const float* xr = in + (size_t)idx * HD;
    float v = xr[tid];
    float ss = v * v;
    for (int o = 16; o > 0; o >>= 1) ss += __shfl_xor_sync(0xffffffffu, ss, o);
    __shared__ float wsum[4];
    __shared__ float tmp[HD];
    if ((tid & 31) == 0) wsum[tid >> 5] = ss;
    __syncthreads();
    float tot = wsum[0] + wsum[1] + wsum[2] + wsum[3];
    float y = v * rsqrtf(tot * (1.0f / HD) + EPS) * scale[tid];
    if (doRope) {
        tmp[tid] = y;
        __syncthreads();
        int pos = positions[b * SS + s];
        int j = tid & 63;
        float invf = powf(10000.0f, -(float)j / 64.0f);
        float ang = (float)pos * invf;
        float sn, cs;
        sincosf(ang, &sn, &cs);
        float x1 = tmp[j], x2 = tmp[64 + j];
        y = (tid < 64) ? (x1 * cs - x2 * sn) : (x2 * cs + x1 * sn);
        __syncthreads();
    }
    tmp[tid] = y;
    __syncthreads();
    if (tid < 64) {
        unsigned h, l;
        split_pack(tmp[2 * tid], tmp[2 * tid + 1], h, l);
        size_t w = (size_t)idx * 64 + tid;
        outH[w] = h; outL[w] = l;
    }
}

// ---------------- tensor-core flash attention (cp.async pipelined) -------
#define ATQ 128
#define AKT 64
#define AST 68
#define AQ_WORDS (ATQ*AST)     // per plane
#define AKV_WORDS (AKT*AST)
#define AKV_STAGE_BYTES (4*AKV_WORDS*4)
#define ATT_SMEM_BYTES ((2*AQ_WORDS + 8*AKV_WORDS)*4)   // Q 2 planes + 2 stages x 4 planes

__global__ void __launch_bounds__(256, 1)
fattn_kernel(const unsigned* __restrict__ qh, const unsigned* __restrict__ ql,
             const unsigned* __restrict__ kh, const unsigned* __restrict__ kl,
             const unsigned* __restrict__ vh, const unsigned* __restrict__ vl,
             unsigned* __restrict__ obh, unsigned* __restrict__ obl)
{
    extern __shared__ __align__(16) unsigned att_smem[];
    int b = blockIdx.z, h = blockIdx.y;
    int q0 = blockIdx.x * ATQ;
    int hkv = h / GRP;
    int tid = threadIdx.x, wid = tid >> 5, lane = tid & 31;
    int gid = lane >> 2, tgid = lane & 3;
    int l15 = lane & 15, lHi8 = (lane >> 4) << 3;

    unsigned smemBase = (unsigned)__cvta_generic_to_shared(att_smem);
    unsigned qBaseH = smemBase;
    unsigned qBaseL = smemBase + AQ_WORDS * 4;
    unsigned kvBase0 = smemBase + 2 * AQ_WORDS * 4;

    // ---- Q fill: 4096 chunks of 16B across 2 planes ----
    #pragma unroll
    for (int p = 0; p < 16; p++) {
        int ci = tid + p * 256;
        int plane = ci >> 11, rem = ci & 2047;
        int row = rem >> 4, c = rem & 15;
        const unsigned* src = (plane ? ql : qh)
            + ((size_t)(b * SS + q0 + row) * HQ + h) * 64 + c * 4;
        unsigned dst = (plane ? qBaseL : qBaseH) + (row * AST + c * 4) * 4;
        cp16(dst, src, 16);
    }

    int ntiles = (q0 >> 6) + 2;
    // KV fill for stage st, tile start j0
    auto fillKV = [&](int st, int j0) {
        unsigned base = kvBase0 + st * AKV_STAGE_BYTES;
        #pragma unroll
        for (int p = 0; p < 16; p++) {
            int ci = tid + p * 256;
            int plane = ci >> 10, rem = ci & 1023;
            int row = rem >> 4, c = rem & 15;
            const unsigned* gp = (plane & 2) ? ((plane & 1) ? vl : vh)
                                             : ((plane & 1) ? kl : kh);
            const unsigned* src = gp + ((size_t)(b * SS + j0 + row) * HKV + hkv) * 64 + c * 4;
            unsigned dst = base + plane * (AKV_WORDS * 4) + (row * AST + c * 4) * 4;
            cp16(dst, src, 16);
        }
        CP_COMMIT();
    };

    fillKV(0, 0);
    CP_WAIT0();
    __syncthreads();

    float oacc[16][4];
    #pragma unroll
    for (int i = 0; i < 16; i++)
        #pragma unroll
        for (int c = 0; c < 4; c++) oacc[i][c] = 0.f;
    float m0 = -1e30f, m1 = -1e30f, l0r = 0.f, l1r = 0.f;

    int rowbase = q0 + wid * 16;
    int kKey = (lane & 7) + ((lane >> 4) << 3);
    int kDimOff = (lane & 8) ? 8 : 0;

    for (int jt = 0;;) {
        int j0 = jt * AKT;
        if (jt + 1 < ntiles) fillKV((jt + 1) & 1, (jt + 1) * AKT);

        if (j0 <= rowbase + 15) {
            unsigned base = kvBase0 + (jt & 1) * AKV_STAGE_BYTES;
            unsigned kBaseH = base;
            unsigned kBaseL = base + AKV_WORDS * 4;
            unsigned vBaseH = base + 2 * AKV_WORDS * 4;
            unsigned vBaseL = base + 3 * AKV_WORDS * 4;

            float s[8][4];
            #pragma unroll
            for (int nf = 0; nf < 8; nf++)
                #pragma unroll
                for (int c = 0; c < 4; c++) s[nf][c] = 0.f;

            #pragma unroll
            for (int kt = 0; kt < 8; kt++) {
                unsigned qhf[4], qlf[4];
                unsigned qoff = (unsigned)((wid * 16 + l15) * (AST * 4) + (kt * 16 + lHi8) * 2);
                LDSM4(qhf[0], qhf[1], qhf[2], qhf[3], qBaseH + qoff);
                LDSM4(qlf[0], qlf[1], qlf[2], qlf[3], qBaseL + qoff);
                int kdd = kt * 16 + kDimOff;
                #pragma unroll
                for (int g2 = 0; g2 < 4; g2++) {
                    unsigned koff = (unsigned)((g2 * 16 + kKey) * (AST * 4) + kdd * 2);
                    unsigned kh0, kh1, kh2, kh3, klo0, klo1, klo2, klo3;
                    LDSM4(kh0, kh1, kh2, kh3, kBaseH + koff);
                    LDSM4(klo0, klo1, klo2, klo3, kBaseL + koff);
                    int n0 = 2 * g2, n1 = 2 * g2 + 1;
                    MMA_BF16(s[n0][0], s[n0][1], s[n0][2], s[n0][3],
                             qlf[0], qlf[1], qlf[2], qlf[3], kh0, kh1);
                    MMA_BF16(s[n0][0], s[n0][1], s[n0][2], s[n0][3],
                             qhf[0], qhf[1], qhf[2], qhf[3], klo0, klo1);
                    MMA_BF16(s[n0][0], s[n0][1], s[n0][2], s[n0][3],
                             qhf[0], qhf[1], qhf[2], qhf[3], kh0, kh1);
                    MMA_BF16(s[n1][0], s[n1][1], s[n1][2], s[n1][3],
                             qlf[0], qlf[1], qlf[2], qlf[3], kh2, kh3);
                    MMA_BF16(s[n1][0], s[n1][1], s[n1][2], s[n1][3],
                             qhf[0], qhf[1], qhf[2], qhf[3], klo2, klo3);
                    MMA_BF16(s[n1][0], s[n1][1], s[n1][2], s[n1][3],
                             qhf[0], qhf[1], qhf[2], qhf[3], kh2, kh3);
                }
            }

            int r0 = rowbase + gid, r1 = r0 + 8;
            if (j0 + AKT - 1 > rowbase) {
                #pragma unroll
                for (int nf = 0; nf < 8; nf++) {
                    int c0 = j0 + nf * 8 + 2 * tgid;
                    if (c0 > r0)     s[nf][0] = -1e30f;
                    if (c0 + 1 > r0) s[nf][1] = -1e30f;
                    if (c0 > r1)     s[nf][2] = -1e30f;
                    if (c0 + 1 > r1) s[nf][3] = -1e30f;
                }
            }

            float t0 = -1e30f, t1 = -1e30f;
            #pragma unroll
            for (int nf = 0; nf < 8; nf++) {
                t0 = fmaxf(t0, fmaxf(s[nf][0], s[nf][1]));
                t1 = fmaxf(t1, fmaxf(s[nf][2], s[nf][3]));
            }
            t0 = fmaxf(t0, __shfl_xor_sync(0xffffffffu, t0, 1));
            t0 = fmaxf(t0, __shfl_xor_sync(0xffffffffu, t0, 2));
            t1 = fmaxf(t1, __shfl_xor_sync(0xffffffffu, t1, 1));
            t1 = fmaxf(t1, __shfl_xor_sync(0xffffffffu, t1, 2));
            float mn0 = fmaxf(m0, t0), mn1 = fmaxf(m1, t1);
            float a0 = __expf(m0 - mn0), a1 = __expf(m1 - mn1);
            m0 = mn0; m1 = mn1;
            float rs0 = 0.f, rs1 = 0.f;
            #pragma unroll
            for (int nf = 0; nf < 8; nf++) {
                s[nf][0] = __expf(s[nf][0] - mn0);
                s[nf][1] = __expf(s[nf][1] - mn0);
                s[nf][2] = __expf(s[nf][2] - mn1);
                s[nf][3] = __expf(s[nf][3] - mn1);
                rs0 += s[nf][0] + s[nf][1];
                rs1 += s[nf][2] + s[nf][3];
            }
            rs0 += __shfl_xor_sync(0xffffffffu, rs0, 1);
            rs0 += __shfl_xor_sync(0xffffffffu, rs0, 2);
            rs1 += __shfl_xor_sync(0xffffffffu, rs1, 1);
            rs1 += __shfl_xor_sync(0xffffffffu, rs1, 2);
            l0r = l0r * a0 + rs0;
            l1r = l1r * a1 + rs1;
            #pragma unroll
            for (int nv = 0; nv < 16; nv++) {
                oacc[nv][0] *= a0; oacc[nv][1] *= a0;
                oacc[nv][2] *= a1; oacc[nv][3] *= a1;
            }

            #pragma unroll
            for (int t = 0; t < 4; t++) {
                unsigned ph[4], pl[4];
                split_pack(s[2 * t][0],     s[2 * t][1],     ph[0], pl[0]);
                split_pack(s[2 * t][2],     s[2 * t][3],     ph[1], pl[1]);
                split_pack(s[2 * t + 1][0], s[2 * t + 1][1], ph[2], pl[2]);
                split_pack(s[2 * t + 1][2], s[2 * t + 1][3], ph[3], pl[3]);
                unsigned vf[16][2];
                int krow = t * 16 + l15;
                #pragma unroll
                for (int np = 0; np < 8; np++) {
                    unsigned voff = (unsigned)(krow * (AST * 4) + (np * 16 + lHi8) * 2);
                    LDSM4T(vf[2 * np][0], vf[2 * np][1], vf[2 * np + 1][0], vf[2 * np + 1][1],
                           vBaseH + voff);
                }
                #pragma unroll
                for (int nv = 0; nv < 16; nv++) {
                    MMA_BF16(oacc[nv][0], oacc[nv][1], oacc[nv][2], oacc[nv][3],
                             pl[0], pl[1], pl[2], pl[3], vf[nv][0], vf[nv][1]);
                    MMA_BF16(oacc[nv][0], oacc[nv][1], oacc[nv][2], oacc[nv][3],
                             ph[0], ph[1], ph[2], ph[3], vf[nv][0], vf[nv][1]);
                }
                #pragma unroll
                for (int np = 0; np < 8; np++) {
                    unsigned voff = (unsigned)(krow * (AST * 4) + (np * 16 + lHi8) * 2);
                    LDSM4T(vf[2 * np][0], vf[2 * np][1], vf[2 * np + 1][0], vf[2 * np + 1][1],
                           vBaseL + voff);
                }
                #pragma unroll
                for (int nv = 0; nv < 16; nv++) {
                    MMA_BF16(oacc[nv][0], oacc[nv][1], oacc[nv][2], oacc[nv][3],
                             ph[0], ph[1], ph[2], ph[3], vf[nv][0], vf[nv][1]);
                }
            }
        }

        if (++jt == ntiles) break;
        CP_WAIT0();
        __syncthreads();
    }

    int r0 = rowbase + gid, r1 = r0 + 8;
    float il0 = 1.f / l0r, il1 = 1.f / l1r;
    #pragma unroll
    for (int nv = 0; nv < 16; nv++) {
        int col = nv * 8 + 2 * tgid;
        unsigned hw, lw;
        split_pack(oacc[nv][0] * il0, oacc[nv][1] * il0, hw, lw);
        size_t w0 = ((size_t)(b * SS + r0) * HQ + h) * 64 + col / 2;
        obh[w0] = hw; obl[w0] = lw;
        split_pack(oacc[nv][2] * il1, oacc[nv][3] * il1, hw, lw);
        size_t w1 = ((size_t)(b * SS + r1) * HQ + h) * 64 + col / 2;
        obh[w1] = hw; obl[w1] = lw;
    }
}

// ================= bf16x3 GEMM (pre-split planes, cp.async 2-stage) =======
#define BAST 20
#define BBST 68
#define GA_WORDS (128*BAST)
#define GB_WORDS (32*BBST)
#define GSTAGE_WORDS (2*GA_WORDS + 2*GB_WORDS)
#define GEMM_DSMEM (2*GSTAGE_WORDS*4)

__global__ void __launch_bounds__(256, 2)
bf16_gemm_kernel(const unsigned* __restrict__ AhG, const unsigned* __restrict__ AlG,
                 const unsigned* __restrict__ BhG, const unsigned* __restrict__ BlG,
                 float* __restrict__ C,
                 int M, int N, int K,
                 const int* __restrict__ aIdxg,
                 const int* __restrict__ cIdxg,
                 const int* __restrict__ cntg,
                 const float* __restrict__ combine,
                 size_t aZW, size_t bZW, int idxZ)
{
    extern __shared__ __align__(16) unsigned dsm[];
    int z = blockIdx.z;
    const unsigned* Ah = AhG + (size_t)z * aZW;
    const unsigned* Al = AlG + (size_t)z * aZW;
    const unsigned* Bh = BhG + (size_t)z * bZW;
    const unsigned* Bl = BlG + (size_t)z * bZW;
    const int* aIdx = aIdxg ? aIdxg + (size_t)z * idxZ : nullptr;
    const int* cIdx = cIdxg ? cIdxg + (size_t)z * idxZ : nullptr;
    int Meff = cntg ? min(M, cntg[z]) : M;
    int bm = blockIdx.y * 128;
    int bn = blockIdx.x * 128;
    if (bm >= Meff) return;
    int Kw = K >> 1, Nw = N >> 1, bnw = bn >> 1;

    int tid = threadIdx.x;
    int wid = tid >> 5, lane = tid & 31;
    int gid = lane >> 2, tgid = lane & 3;
    int wm = (wid & 3) * 32;
    int wn = (wid >> 2) * 64;
    int l15 = lane & 15, lHi8 = (lane >> 4) << 3;

    // fill mapping
    int am = tid >> 1, ac = (tid & 1) * 2;
    int gr = bm + am;
    int ar = (gr < Meff) ? (aIdx ? aIdx[gr] : gr) : 0;
    int aValid = (gr < Meff) ? 16 : 0;
    const unsigned* aRowH = Ah + (size_t)ar * Kw;
    const unsigned* aRowL = Al + (size_t)ar * Kw;
    int bk = tid >> 3, bc = (2 * tid) & 15;

    unsigned smemBase = (unsigned)__cvta_generic_to_shared(dsm);

    auto fillStage = [&](int st, int k0) {
        int kw0 = k0 >> 1;
        unsigned base = smemBase + st * (GSTAGE_WORDS * 4);
        unsigned aHb = base, aLb = base + GA_WORDS * 4;
        unsigned bHb = aLb + GA_WORDS * 4, bLb = bHb + GB_WORDS * 4;
        #pragma unroll
        for (int c2 = 0; c2 < 2; c2++) {
            int c = ac + c2;
            unsigned d = (am * BAST + c * 4) * 4;
            cp16(aHb + d, aRowH + kw0 + c * 4, aValid);
            cp16(aLb + d, aRowL + kw0 + c * 4, aValid);
        }
        size_t bro = (size_t)(k0 + bk) * Nw + bnw;
        #pragma unroll
        for (int c2 = 0; c2 < 2; c2++) {
            int c = bc + c2;
            unsigned d = (bk * BBST + c * 4) * 4;
            cp16(bHb + d, Bh + bro + c * 4, 16);
            cp16(bLb + d, Bl + bro + c * 4, 16);
        }
        CP_COMMIT();
    };

    float acc[2][8][4];
    #pragma unroll
    for (int i = 0; i < 2; i++)
        #pragma unroll
        for (int j = 0; j < 8; j++)
            #pragma unroll
            for (int c = 0; c < 4; c++) acc[i][j][c] = 0.f;

    int KT = K >> 5;
    fillStage(0, 0);
    CP_WAIT0();
    __syncthreads();

    for (int kt = 0;;) {
        if (kt + 1 < KT) fillStage((kt + 1) & 1, (kt + 1) << 5);

        unsigned base = smemBase + (kt & 1) * (GSTAGE_WORDS * 4);
        unsigned aBaseH = base, aBaseL = base + GA_WORDS * 4;
        unsigned bBaseH = aBaseL + GA_WORDS * 4, bBaseL = bBaseH + GB_WORDS * 4;

        #pragma unroll
        for (int ks = 0; ks < 2; ks++) {
            int kk = ks * 16;
            unsigned ah[2][4], al[2][4];
            #pragma unroll
            for (int mf = 0; mf < 2; mf++) {
                int mrow = wm + mf * 16 + l15;
                unsigned off = (unsigned)(mrow * (BAST * 4) + (kk + lHi8) * 2);
                LDSM4(ah[mf][0], ah[mf][1], ah[mf][2], ah[mf][3], aBaseH + off);
                LDSM4(al[mf][0], al[mf][1], al[mf][2], al[mf][3], aBaseL + off);
            }
            unsigned bfr[8][2];
            int krow = kk + l15;
            #pragma unroll
            for (int nfp = 0; nfp < 4; nfp++) {
                int ncol = wn + nfp * 16 + lHi8;
                unsigned off = (unsigned)(krow * (BBST * 4) + ncol * 2);
                LDSM4T(bfr[2 * nfp][0], bfr[2 * nfp][1],
                       bfr[2 * nfp + 1][0], bfr[2 * nfp + 1][1], bBaseH + off);
            }
            #pragma unroll
            for (int mf = 0; mf < 2; mf++)
                #pragma unroll
                for (int nf = 0; nf < 8; nf++) {
                    MMA_BF16(acc[mf][nf][0], acc[mf][nf][1], acc[mf][nf][2], acc[mf][nf][3],
                             ah[mf][0], ah[mf][1], ah[mf][2], ah[mf][3],
                             bfr[nf][0], bfr[nf][1]);
                    MMA_BF16(acc[mf][nf][0], acc[mf][nf][1], acc[mf][nf][2], acc[mf][nf][3],
                             al[mf][0], al[mf][1], al[mf][2], al[mf][3],
                             bfr[nf][0], bfr[nf][1]);
                }
            #pragma unroll
            for (int nfp = 0; nfp < 4; nfp++) {
                int ncol = wn + nfp * 16 + lHi8;
                unsigned off = (unsigned)(krow * (BBST * 4) + ncol * 2);
                LDSM4T(bfr[2 * nfp][0], bfr[2 * nfp][1],
                       bfr[2 * nfp + 1][0], bfr[2 * nfp + 1][1], bBaseL + off);
            }
            #pragma unroll
            for (int mf = 0; mf < 2; mf++)
                #pragma unroll
                for (int nf = 0; nf < 8; nf++) {
                    MMA_BF16(acc[mf][nf][0], acc[mf][nf][1], acc[mf][nf][2], acc[mf][nf][3],
                             ah[mf][0], ah[mf][1], ah[mf][2], ah[mf][3],
                             bfr[nf][0], bfr[nf][1]);
                }
        }

        if (++kt == KT) break;
        CP_WAIT0();
        __syncthreads();
    }

    #pragma unroll
    for (int mf = 0; mf < 2; mf++) {
        #pragma unroll
        for (int half = 0; half < 2; half++) {
            int row = bm + wm + mf * 16 + gid + half * 8;
            if (row >= Meff) continue;
            int crow = cIdx ? cIdx[row] : row;
            float w = 1.f;
            if (combine) w = combine[crow * EE + z];
            #pragma unroll
            for (int nf = 0; nf < 8; nf++) {
                int col = bn + wn + nf * 8 + 2 * tgid;
                float v0 = acc[mf][nf][half * 2 + 0];
                float v1 = acc[mf][nf][half * 2 + 1];
                float* cp = C + (size_t)crow * N + col;
                if (combine) {
                    atomicAdd(cp, w * v0);
                    atomicAdd(cp + 1, w * v1);
                } else {
                    cp[0] = v0;
                    cp[1] = v1;
                }
            }
        }
    }
}

// ========== gated dual-B GEMM: out = gelu(A*B0)*(A*B1), packed output =====
__global__ void __launch_bounds__(256, 2)
bf16_gated_kernel(const unsigned* __restrict__ Ah, const unsigned* __restrict__ Al,
                  const unsigned* __restrict__ B0hG, const unsigned* __restrict__ B0lG,
                  const unsigned* __restrict__ B1hG, const unsigned* __restrict__ B1lG,
                  unsigned* __restrict__ ChG, unsigned* __restrict__ ClG,
                  int M, int Nout, int K,
                  const int* __restrict__ aIdxg,
                  const int* __restrict__ cntg,
                  size_t bZW, size_t cZW, int idxZ)
{
    extern __shared__ __align__(16) unsigned dsm[];
    int z = blockIdx.z;
    const unsigned* B0h = B0hG + (size_t)z * bZW;
    const unsigned* B0l = B0lG + (size_t)z * bZW;
    const unsigned* B1h = B1hG + (size_t)z * bZW;
    const unsigned* B1l = B1lG + (size_t)z * bZW;
    unsigned* Ch = ChG + (size_t)z * cZW;
    unsigned* Cl = ClG + (size_t)z * cZW;
    const int* aIdx = aIdxg ? aIdxg + (size_t)z * idxZ : nullptr;
    int Meff = cntg ? min(M, cntg[z]) : M;
    int bm = blockIdx.y * 128;
    int bnn = blockIdx.x * 64;
    if (bm >= Meff) return;
    int Kw = K >> 1, Nw = Nout >> 1, bnw = bnn >> 1;

    int tid = threadIdx.x;
    int wid = tid >> 5, lane = tid & 31;
    int gid = lane >> 2, tgid = lane & 3;
    int wm = (wid & 3) * 32;
    int wn32 = (wid >> 2) * 32;
    int l15 = lane & 15, lHi8 = (lane >> 4) << 3;

    int am = tid >> 1, ac = (tid & 1) * 2;
    int gr = bm + am;
    int ar = (gr < Meff) ? (aIdx ? aIdx[gr] : gr) : 0;
    int aValid = (gr < Meff) ? 16 : 0;
    const unsigned* aRowH = Ah + (size_t)ar * Kw;
    const unsigned* aRowL = Al + (size_t)ar * Kw;
    // B: 512 chunks/plane: row=ci>>4, rest=ci&15 -> srcSel=rest>>3, c=rest&7
    int bk = tid >> 3;
    int brest = (2 * tid) & 15;

    unsigned smemBase = (unsigned)__cvta_generic_to_shared(dsm);

    auto fillStage = [&](int st, int k0) {
        int kw0 = k0 >> 1;
        unsigned base = smemBase + st * (GSTAGE_WORDS * 4);
        unsigned aHb = base, aLb = base + GA_WORDS * 4;
        unsigned bHb = aLb + GA_WORDS * 4, bLb = bHb + GB_WORDS * 4;
        #pragma unroll
        for (int c2 = 0; c2 < 2; c2++) {
            int c = ac + c2;
            unsigned d = (am * BAST + c * 4) * 4;
            cp16(aHb + d, aRowH + kw0 + c * 4, aValid);
            cp16(aLb + d, aRowL + kw0 + c * 4, aValid);
        }
        size_t bro = (size_t)(k0 + bk) * Nw + bnw;
        #pragma unroll
        for (int c2 = 0; c2 < 2; c2++) {
            int cc = brest + c2;
            int srcSel = cc >> 3, c = cc & 7;
            unsigned d = (bk * BBST + srcSel * 32 + c * 4) * 4;
            cp16(bHb + d, (srcSel ? B1h : B0h) + bro + c * 4, 16);
            cp16(bLb + d, (srcSel ? B1l : B0l) + bro + c * 4, 16);
        }
        CP_COMMIT();
    };

    float acc0[2][4][4], acc1[2][4][4];
    #pragma unroll
    for (int i = 0; i < 2; i++)
        #pragma unroll
        for (int j = 0; j < 4; j++)
            #pragma unroll
            for (int c = 0; c < 4; c++) { acc0[i][j][c] = 0.f; acc1[i][j][c] = 0.f; }

    int KT = K >> 5;
    fillStage(0, 0);
    CP_WAIT0();
    __syncthreads();

    for (int kt = 0;;) {
        if (kt + 1 < KT) fillStage((kt + 1) & 1, (kt + 1) << 5);

        unsigned base = smemBase + (kt & 1) * (GSTAGE_WORDS * 4);
        unsigned aBaseH = base, aBaseL = base + GA_WORDS * 4;
        unsigned bBaseH = aBaseL + GA_WORDS * 4, bBaseL = bBaseH + GB_WORDS * 4;

        #pragma unroll
        for (int ks = 0; ks < 2; ks++) {
            int kk = ks * 16;
            unsigned ah[2][4], al[2][4];
            #pragma unroll
            for (int mf = 0; mf < 2; mf++) {
                int mrow = wm + mf * 16 + l15;
                unsigned off = (unsigned)(mrow * (BAST * 4) + (kk + lHi8) * 2);
                LDSM4(ah[mf][0], ah[mf][1], ah[mf][2], ah[mf][3], aBaseH + off);
                LDSM4(al[mf][0], al[mf][1], al[mf][2], al[mf][3], aBaseL + off);
            }
            int krow = kk + l15;
            #pragma unroll
            for (int which = 0; which < 2; which++) {
                unsigned bfr[4][2];
                int colbase = which * 64 + wn32;
                #pragma unroll
                for (int nfp = 0; nfp < 2; nfp++) {
                    int ncol = colbase + nfp * 16 + lHi8;
                    unsigned off = (unsigned)(krow * (BBST * 4) + ncol * 2);
                    LDSM4T(bfr[2 * nfp][0], bfr[2 * nfp][1],
                           bfr[2 * nfp + 1][0], bfr[2 * nfp + 1][1], bBaseH + off);
                }
                #pragma unroll
                for (int mf = 0; mf < 2; mf++)
                    #pragma unroll
                    for (int nf = 0; nf < 4; nf++) {
                        float* a = which ? acc1[mf][nf] : acc0[mf][nf];
                        MMA_BF16(a[0], a[1], a[2], a[3],
                                 ah[mf][0], ah[mf][1], ah[mf][2], ah[mf][3],
                                 bfr[nf][0], bfr[nf][1]);
                        MMA_BF16(a[0], a[1], a[2], a[3],
                                 al[mf][0], al[mf][1], al[mf][2], al[mf][3],
                                 bfr[nf][0], bfr[nf][1]);
                    }
                #pragma unroll
                for (int nfp = 0; nfp < 2; nfp++) {
                    int ncol = colbase + nfp * 16 + lHi8;
                    unsigned off = (unsigned)(krow * (BBST * 4) + ncol * 2);
                    LDSM4T(bfr[2 * nfp][0], bfr[2 * nfp][1],
                           bfr[2 * nfp + 1][0], bfr[2 * nfp + 1][1], bBaseL + off);
                }
                #pragma unroll
                for (int mf = 0; mf < 2; mf++)
                    #pragma unroll
                    for (int nf = 0; nf < 4; nf++) {
                        float* a = which ? acc1[mf][nf] : acc0[mf][nf];
                        MMA_BF16(a[0], a[1], a[2], a[3],
                                 ah[mf][0], ah[mf][1], ah[mf][2], ah[mf][3],
                                 bfr[nf][0], bfr[nf][1]);
                    }
            }
        }

        if (++kt == KT) break;
        CP_WAIT0();
        __syncthreads();
    }

    #pragma unroll
    for (int mf = 0; mf < 2; mf++) {
        #pragma unroll
        for (int half = 0; half < 2; half++) {
            int row = bm + wm + mf * 16 + gid + half * 8;
            if (row >= Meff) continue;
            #pragma unroll
            for (int nf = 0; nf < 4; nf++) {
                int col = bnn + wn32 + nf * 8 + 2 * tgid;
                float g0v = gelu_tanh(acc0[mf][nf][half * 2 + 0]) * acc1[mf][nf][half * 2 + 0];
                float g1v = gelu_tanh(acc0[mf][nf][half * 2 + 1]) * acc1[mf][nf][half * 2 + 1];
                unsigned hw, lw;
                split_pack(g0v, g1v, hw, lw);
                size_t w = (size_t)row * Nw + (col >> 1);
                Ch[w] = hw; Cl[w] = lw;
            }
        }
    }
}

// ---------------- router ----------------
__global__ void router_kernel(const float* __restrict__ gin,
                              const float* __restrict__ wg,
                              float* __restrict__ combine,
                              int* __restrict__ cnt,
                              int* __restrict__ idx,
                              float* __restrict__ psum)
{
    int tok = blockIdx.x;
    int tid = threadIdx.x;
    float s[EE] = {};
    const float* g = gin + (size_t)tok * DD;
    for (int d = tid; d < DD; d += 256) {
        float gv = g[d];
        const float* w = wg + d * EE;
        #pragma unroll
        for (int e = 0; e < EE; e++) s[e] += gv * w[e];
    }
    __shared__ float sh[256][EE];
    #pragma unroll
    for (int e = 0; e < EE; e++) sh[tid][e] = s[e];
    __syncthreads();
    for (int str = 128; str > 0; str >>= 1) {
        if (tid < str) {
            #pragma unroll
            for (int e = 0; e < EE; e++) sh[tid][e] += sh[tid + str][e];
        }
        __syncthreads();
    }
    if (tid == 0) {
        float pe[EE];
        float mx = -FLT_MAX;
        #pragma unroll
        for (int e = 0; e < EE; e++) mx = fmaxf(mx, sh[0][e]);
        float sum = 0.f;
        #pragma unroll
        for (int e = 0; e < EE; e++) { pe[e] = expf(sh[0][e] - mx); sum += pe[e]; }
        float inv = 1.0f / sum;
        #pragma unroll
        for (int e = 0; e < EE; e++) { pe[e] *= inv; atomicAdd(&psum[e], pe[e]); }
        int i0 = 0;
        #pragma unroll
        for (int e = 1; e < EE; e++) if (pe[e] > pe[i0]) i0 = e;
        int i1 = (i0 == 0) ? 1 : 0;
        #pragma unroll
        for (int e = 0; e < EE; e++) if (e != i0 && e != i1 && pe[e] > pe[i1]) i1 = e;
        float tot = pe[i0] + pe[i1];
        float w0 = pe[i0] / tot, w1 = pe[i1] / tot;
        float* crow = combine + (size_t)tok * EE;
        #pragma unroll
        for (int e = 0; e < EE; e++) crow[e] = 0.f;
        crow[i0] = w0; crow[i1] = w1;
        int p0 = atomicAdd(&cnt[i0], 1); idx[i0 * TT + p0] = tok;
        int p1 = atomicAdd(&cnt[i1], 1); idx[i1 * TT + p1] = tok;
    }
}

__global__ void lb_kernel(const int* __restrict__ cnt, const float* __restrict__ psum,
                          float* __restrict__ out)
{
    float lb = 0.f;
    #pragma unroll
    for (int e = 0; e < EE; e++)
        lb += ((float)cnt[e] / (float)TT) * (psum[e] / (float)TT);
    out[0] = lb * ((float)(EE * EE) / (float)EE);
}

// ==================== host launcher ====================
extern "C" void kernel_launch(void* const* d_in, const int* in_sizes, int n_in,
                              void* d_out, int out_size)
{
    const int*   positions       = (const int*)  d_in[0];
    const float* x               = (const float*)d_in[1];
    const float* pre_attn_scale  = (const float*)d_in[2];
    const float* wq              = (const float*)d_in[3];
    const float* wk              = (const float*)d_in[4];
    const float* wv              = (const float*)d_in[5];
    const float* wo              = (const float*)d_in[6];
    const float* q_norm_scale    = (const float*)d_in[7];
    const float* k_norm_scale    = (const float*)d_in[8];
    const float* v_norm_scale    = (const float*)d_in[9];
    const float* post_attn_scale = (const float*)d_in[10];
    const float* pre_ffw_scale   = (const float*)d_in[11];
    const float* shared_wi0      = (const float*)d_in[12];
    const float* shared_wi1      = (const float*)d_in[13];
    const float* shared_wo       = (const float*)d_in[14];
    const float* post_ff1_scale  = (const float*)d_in[15];
    const float* pre_ff2_scale   = (const float*)d_in[16];
    const float* router_scale    = (const float*)d_in[17];
    const float* w_gate          = (const float*)d_in[18];
    const float* ewi0            = (const float*)d_in[19];
    const float* ewi1            = (const float*)d_in[20];
    const float* ewo             = (const float*)d_in[21];
    const float* post_ff2_scale  = (const float*)d_in[22];
    const float* layer_scalar    = (const float*)d_in[23];
    float* out = (float*)d_out;

    static int smemConfigured = 0;
    if (!smemConfigured) {
        cudaFuncSetAttribute(fattn_kernel,
                             cudaFuncAttributeMaxDynamicSharedMemorySize, ATT_SMEM_BYTES);
        cudaFuncSetAttribute(bf16_gemm_kernel,
                             cudaFuncAttributeMaxDynamicSharedMemorySize, GEMM_DSMEM);
        cudaFuncSetAttribute(bf16_gated_kernel,
                             cudaFuncAttributeMaxDynamicSharedMemorySize, GEMM_DSMEM);
        smemConfigured = 1;
    }

    float* sc = nullptr;
    int*   isc = nullptr;
    cudaGetSymbolAddress((void**)&sc, g_scratch);
    cudaGetSymbolAddress((void**)&isc, g_iscratch);

    unsigned* U = (unsigned*)sc;
    auto uptr = [&](size_t off) { return U + off; };   // off in float units == word units

    unsigned* lnxH = uptr(OFF_LNXH); unsigned* lnxL = uptr(OFF_LNXL);
    float* qf = sc + OFF_QF; float* kf = sc + OFF_KF; float* vf = sc + OFF_VF;
    unsigned* qsh = uptr(OFF_QH); unsigned* qsl = uptr(OFF_QL);
    unsigned* ksh = uptr(OFF_KH); unsigned* ksl = uptr(OFF_KL);
    unsigned* vsh = uptr(OFF_VH); unsigned* vsl = uptr(OFF_VL);
    unsigned* obh = uptr(OFF_OBH); unsigned* obl = uptr(OFF_OBL);
    float* attnb = sc + OFF_ATTN; float* hb = sc + OFF_H;
    unsigned* ffinH = uptr(OFF_FFINH); unsigned* ffinL = uptr(OFF_FFINL);
    unsigned* g0H = uptr(OFF_G0H); unsigned* g0L = uptr(OFF_G0L);
    float* shb = sc + OFF_SHB;
    unsigned* rinH = uptr(OFF_RINH); unsigned* rinL = uptr(OFF_RINL);
    float* gin = sc + OFF_GIN; float* routb = sc + OFF_ROUT;
    unsigned* egH = uptr(OFF_EGH); unsigned* egL = uptr(OFF_EGL);
    float* comb = sc + OFF_COMB; float* psum = sc + OFF_PSUM;
    int* idx = isc; int* cnt = isc + EE * TT;

    auto split = [&](const float* src, size_t nElts, size_t offH, size_t offL) {
        size_t nW = nElts / 2;
        split_kernel<<<(unsigned)((nW + 255) / 256), 256>>>(
            (const float2*)src, uptr(offH), uptr(offL), nW);
    };

    // ---- weight pre-split ----
    split(wq, SZ_WQ, OFF_WQH, OFF_WQL);
    split(wk, SZ_WK, OFF_WKH, OFF_WKL);
    split(wv, SZ_WK, OFF_WVH, OFF_WVL);
    split(wo, SZ_WQ, OFF_WOH, OFF_WOL);
    split(shared_wi0, SZ_WFF, OFF_WI0H, OFF_WI0L);
    split(shared_wi1, SZ_WFF, OFF_WI1H, OFF_WI1L);
    split(shared_wo, SZ_WFF, OFF_SWOH, OFF_SWOL);
    split(ewi0, SZ_EW, OFF_EWI0H, OFF_EWI0L);
    split(ewi1, SZ_EW, OFF_EWI1H, OFF_EWI1L);
    split(ewo, SZ_EW, OFF_EWOH, OFF_EWOL);

    auto gemm = [&](const unsigned* Ah, const unsigned* Al,
                    size_t BhOff, size_t BlOff, float* C, int M, int N, int K,
                    const int* aI, const int* cI, const int* ct, const float* cw,
                    size_t aZW, size_t bZW, int nz) {
        dim3 grid(N / 128, (M + 127) / 128, nz);
        bf16_gemm_kernel<<<grid, 256, GEMM_DSMEM>>>(Ah, Al, uptr(BhOff), uptr(BlOff),
                                                    C, M, N, K, aI, cI, ct, cw,
                                                    aZW, bZW, TT);
    };

    // 1) pre-attn norm (packed out)
    rms_kernel<<<TT, 256>>>(x, pre_attn_scale, 1.f, nullptr, nullptr, nullptr,
                            nullptr, lnxH, lnxL);

    // 2) QKV projections (f32 out)
    gemm(lnxH, lnxL, OFF_WQH, OFF_WQL, qf, TT, HQ * HD, DD,
         nullptr, nullptr, nullptr, nullptr, 0, 0, 1);
    gemm(lnxH, lnxL, OFF_WKH, OFF_WKL, kf, TT, HKV * HD, DD,
         nullptr, nullptr, nullptr, nullptr, 0, 0, 1);
    gemm(lnxH, lnxL, OFF_WVH, OFF_WVL, vf, TT, HKV * HD, DD,
         nullptr, nullptr, nullptr, nullptr, 0, 0, 1);

    // 3) per-head norms + rope -> packed q/k/v planes
    head_norm_rope_kernel<<<TT * HQ, HD>>>(qf, qsh, qsl, q_norm_scale, positions, HQ, 1);
    head_norm_rope_kernel<<<TT * HKV, HD>>>(kf, ksh, ksl, k_norm_scale, positions, HKV, 1);
    head_norm_rope_kernel<<<TT * HKV, HD>>>(vf, vsh, vsl, v_norm_scale, positions, HKV, 0);

    // 4) attention -> packed ob planes
    {
        dim3 grid(SS / ATQ, HQ, BB);
        fattn_kernel<<<grid, 256, ATT_SMEM_BYTES>>>(qsh, qsl, ksh, ksl, vsh, vsl, obh, obl);
    }

    // 5) output projection + post-attn norm + residual
    gemm(obh, obl, OFF_WOH, OFF_WOL, attnb, TT, DD, HQ * HD,
         nullptr, nullptr, nullptr, nullptr, 0, 0, 1);
    rms_kernel<<<TT, 256>>>(attnb, post_attn_scale, 1.f, x, nullptr, nullptr,
                            hb, nullptr, nullptr);

    // 6) shared FFN
    rms_kernel<<<TT, 256>>>(hb, pre_ffw_scale, 1.f, nullptr, nullptr, nullptr,
                            nullptr, ffinH, ffinL);
    {
        dim3 grid(FS / 64, TT / 128, 1);
        bf16_gated_kernel<<<grid, 256, GEMM_DSMEM>>>(
            ffinH, ffinL, uptr(OFF_WI0H), uptr(OFF_WI0L), uptr(OFF_WI1H), uptr(OFF_WI1L),
            g0H, g0L, TT, FS, DD, nullptr, nullptr, 0, 0, TT);
    }
    gemm(g0H, g0L, OFF_SWOH, OFF_SWOL, shb, TT, DD, FS,
         nullptr, nullptr, nullptr, nullptr, 0, 0, 1);
    rms_kernel<<<TT, 256>>>(shb, post_ff1_scale, 1.f, nullptr, nullptr, nullptr,
                            shb, nullptr, nullptr);

    // 7) router inputs
    rms_kernel<<<TT, 256>>>(hb, pre_ff2_scale, 1.f, nullptr, nullptr, nullptr,
                            nullptr, rinH, rinL);
    rms_kernel<<<TT, 256>>>(hb, router_scale, 0.02209708691207961f,
                            nullptr, nullptr, nullptr, gin, nullptr, nullptr);

    // 8) router + batched MoE
    cudaMemsetAsync(cnt, 0, EE * sizeof(int));
    cudaMemsetAsync(psum, 0, EE * sizeof(float));
    cudaMemsetAsync(routb, 0, SZ_TD * sizeof(float));
    router_kernel<<<TT, 256>>>(gin, w_gate, comb, cnt, idx, psum);

    {
        dim3 grid(FE / 64, TT / 128, EE);
        bf16_gated_kernel<<<grid, 256, GEMM_DSMEM>>>(
            rinH, rinL, uptr(OFF_EWI0H), uptr(OFF_EWI0L), uptr(OFF_EWI1H), uptr(OFF_EWI1L),
            egH, egL, TT, FE, DD, idx, cnt,
            (size_t)DD * FE / 2, (size_t)TT * FE / 2, TT);
    }
    {
        dim3 grid(DD / 128, TT / 128, EE);
        bf16_gemm_kernel<<<grid, 256, GEMM_DSMEM>>>(
            egH, egL, uptr(OFF_EWOH), uptr(OFF_EWOL), routb, TT, DD, FE,
            nullptr, idx, cnt, comb,
            (size_t)TT * FE / 2, (size_t)FE * DD / 2, TT);
    }

    // 9) final combine
    rms_kernel<<<TT, 256>>>(routb, post_ff2_scale, 1.f, shb, hb, layer_scalar,
                            out, nullptr, nullptr);

    // 10) lb loss
    if (out_size > TT * DD) {
        lb_kernel<<<1, 1>>>(cnt, psum, out + (size_t)TT * DD);
    }
}

// round 11
// speedup vs baseline: 1.0160x; 1.0160x over previous
#include <cuda_runtime.h>
#include <cuda_bf16.h>
#include <cfloat>
#include <math.h>

// ---------------- problem constants ----------------
#define BB 4
#define SS 1024
#define DD 2048
#define HQ 16
#define HKV 8
#define HD 128
#define GRP 2
#define EE 8
#define FE 1024
#define FS 8192
#define TT (BB*SS)
#define EPS 1e-6f
#define NQKV 4096   // HQ*HD + HKV*HD + HKV*HD

// ---------------- scratch layout (word units) ----------------
#define SZ_TD   ((size_t)TT*DD)
#define SZ_TQ   ((size_t)TT*HQ*HD)
#define SZ_TKV  ((size_t)TT*HKV*HD)
#define SZ_TFS  ((size_t)TT*FS)

#define OFF_LNXH  ((size_t)0)
#define OFF_LNXL  (OFF_LNXH + SZ_TD/2)
#define OFF_QKVF  (OFF_LNXL + SZ_TD/2)                 // f32 [TT][4096]
#define OFF_QH    (OFF_QKVF + (size_t)TT*NQKV)
#define OFF_QL    (OFF_QH   + SZ_TQ/2)
#define OFF_KH    (OFF_QL   + SZ_TQ/2)
#define OFF_KL    (OFF_KH   + SZ_TKV/2)
#define OFF_VH    (OFF_KL   + SZ_TKV/2)
#define OFF_VL    (OFF_VH   + SZ_TKV/2)
#define OFF_OBH   (OFF_VL   + SZ_TKV/2)
#define OFF_OBL   (OFF_OBH  + SZ_TQ/2)
#define OFF_ATTN  (OFF_OBL  + SZ_TQ/2)
#define OFF_H     (OFF_ATTN + SZ_TD)
#define OFF_FFINH (OFF_H    + SZ_TD)
#define OFF_FFINL (OFF_FFINH+ SZ_TD/2)
#define OFF_G0H   (OFF_FFINL+ SZ_TD/2)
#define OFF_G0L   (OFF_G0H  + SZ_TFS/2)
#define OFF_SHB   (OFF_G0L  + SZ_TFS/2)
#define OFF_RINH  (OFF_SHB  + SZ_TD)
#define OFF_RINL  (OFF_RINH + SZ_TD/2)
#define OFF_GIN   (OFF_RINL + SZ_TD/2)
#define OFF_ROUT  (OFF_GIN  + SZ_TD)
#define OFF_EGH   (OFF_ROUT + SZ_TD)
#define OFF_EGL   (OFF_EGH  + SZ_TFS/2)
#define OFF_COMB  (OFF_EGL  + SZ_TFS/2)
#define OFF_PSUM  (OFF_COMB + (size_t)TT*EE)
// weights (split planes)
#define SZ_WQKV ((size_t)DD*NQKV)
#define SZ_WQ  ((size_t)DD*HQ*HD)
#define SZ_WFF ((size_t)DD*FS)
#define SZ_EW  ((size_t)EE*DD*FE)
#define OFF_WQKVH (OFF_PSUM + 8)
#define OFF_WQKVL (OFF_WQKVH + SZ_WQKV/2)
#define OFF_WOH   (OFF_WQKVL + SZ_WQKV/2)
#define OFF_WOL   (OFF_WOH + SZ_WQ/2)
#define OFF_WI0H  (OFF_WOL + SZ_WQ/2)
#define OFF_WI0L  (OFF_WI0H + SZ_WFF/2)
#define OFF_WI1H  (OFF_WI0L + SZ_WFF/2)
#define OFF_WI1L  (OFF_WI1H + SZ_WFF/2)
#define OFF_SWOH  (OFF_WI1L + SZ_WFF/2)
#define OFF_SWOL  (OFF_SWOH + SZ_WFF/2)
#define OFF_EWI0H (OFF_SWOL + SZ_WFF/2)
#define OFF_EWI0L (OFF_EWI0H + SZ_EW/2)
#define OFF_EWI1H (OFF_EWI0L + SZ_EW/2)
#define OFF_EWI1L (OFF_EWI1H + SZ_EW/2)
#define OFF_EWOH  (OFF_EWI1L + SZ_EW/2)
#define OFF_EWOL  (OFF_EWOH + SZ_EW/2)
#define SCRATCH_TOTAL (OFF_EWOL + SZ_EW/2)

__device__ float g_scratch[SCRATCH_TOTAL];
__device__ int   g_iscratch[EE*TT + EE];

// ---------------- helpers ----------------
__device__ __forceinline__ float gelu_tanh(float v) {
    const float c = 0.7978845608028654f;
    float u = c * (v + 0.044715f * v * v * v);
    return 0.5f * v * (1.0f + tanhf(u));
}
__device__ __forceinline__ unsigned pack_bf16(float x, float y) {
    __nv_bfloat162 t = __floats2bfloat162_rn(x, y);
    return *reinterpret_cast<unsigned*>(&t);
}
__device__ __forceinline__ void split_pack(float x, float y,
                                           unsigned &hiW, unsigned &loW0) {
    __nv_bfloat16 bx = __float2bfloat16_rn(x);
    __nv_bfloat16 by = __float2bfloat16_rn(y);
    float hx = __bfloat162float(bx);
    float hy = __bfloat162float(by);
    __nv_bfloat162 h2; h2.x = bx; h2.y = by;
    hiW = *reinterpret_cast<unsigned*>(&h2);
    loW0 = pack_bf16(x - hx, y - hy);
}
__device__ __forceinline__ void cp16(unsigned dst, const void* src, int srcBytes) {
    asm volatile("cp.async.cg.shared.global [%0], [%1], 16, %2;"
                 :: "r"(dst), "l"(src), "r"(srcBytes));
}
#define CP_COMMIT() asm volatile("cp.async.commit_group;")
#define CP_WAIT0()  asm volatile("cp.async.wait_group 0;")

#define LDSM4(r0,r1,r2,r3,addr) \
    asm volatile("ldmatrix.sync.aligned.m8n8.x4.shared.b16 {%0,%1,%2,%3}, [%4];" \
                 : "=r"(r0),"=r"(r1),"=r"(r2),"=r"(r3) : "r"(addr))
#define LDSM4T(r0,r1,r2,r3,addr) \
    asm volatile("ldmatrix.sync.aligned.m8n8.x4.trans.shared.b16 {%0,%1,%2,%3}, [%4];" \
                 : "=r"(r0),"=r"(r1),"=r"(r2),"=r"(r3) : "r"(addr))
#define MMA_BF16(d0,d1,d2,d3,a0,a1,a2,a3,b0,b1) \
    asm volatile("mma.sync.aligned.m16n8k16.row.col.f32.bf16.bf16.f32 " \
                 "{%0,%1,%2,%3}, {%4,%5,%6,%7}, {%8,%9}, {%0,%1,%2,%3};" \
                 : "+f"(d0),"+f"(d1),"+f"(d2),"+f"(d3) \
                 : "r"(a0),"r"(a1),"r"(a2),"r"(a3),"r"(b0),"r"(b1))

// ---------------- splits ----------------
__global__ void split_bf_kernel(const float2* __restrict__ in,
                                unsigned* __restrict__ hi,
                                unsigned* __restrict__ lo, size_t nWords)
{
    size_t i = (size_t)blockIdx.x * 256 + threadIdx.x;
    if (i < nWords) {
        float2 v = in[i];
        unsigned h, l;
        split_pack(v.x, v.y, h, l);
        hi[i] = h; lo[i] = l;
    }
}
// concat wq|wk|wv along N into [DD][4096] hi/lo planes (2048 words/row)
__global__ void split_qkv_kernel(const float* __restrict__ wq,
                                 const float* __restrict__ wk,
                                 const float* __restrict__ wv,
                                 unsigned* __restrict__ hi,
                                 unsigned* __restrict__ lo)
{
    size_t w = (size_t)blockIdx.x * 256 + threadIdx.x;
    if (w >= (size_t)DD * (NQKV / 2)) return;
    int d = (int)(w / (NQKV / 2));
    int n0 = 2 * (int)(w % (NQKV / 2));
    float x, y;
    if (n0 < 2048) {
        const float* p = wq + (size_t)d * 2048 + n0;
        x = p[0]; y = p[1];
    } else if (n0 < 3072) {
        const float* p = wk + (size_t)d * 1024 + (n0 - 2048);
        x = p[0]; y = p[1];
    } else {
        const float* p = wv + (size_t)d * 1024 + (n0 - 3072);
        x = p[0]; y = p[1];
    }
    unsigned h, l;
    split_pack(x, y, h, l);
    hi[w] = h; lo[w] = l;
}

// ---------------- RMS norm over D=2048 ----------------
__global__ void rms_kernel(const float* __restrict__ in,
                           const float* __restrict__ scale, float cmul,
                           const float* __restrict__ res1,
                           const float* __restrict__ res2,
                           const float* __restrict__ scalarPtr,
                           float* __restrict__ out,
                           unsigned* __restrict__ outH,
                           unsigned* __restrict__ outL)
{
    int row = blockIdx.x;
    int tid = threadIdx.x;
    const float* xr = in + (size_t)row * DD;
    float ss = 0.f;
    for (int d = tid; d < DD; d += 256) { float v = xr[d]; ss += v * v; }
    for (int o = 16; o > 0; o >>= 1) ss += __shfl_xor_sync(0xffffffffu, ss, o);
    __shared__ float wsum[8];
    if ((tid & 31) == 0) wsum[tid >> 5] = ss;
    __syncthreads();
    float tot = 0.f;
    #pragma unroll
    for (int w = 0; w < 8; w++) tot += wsum[w];
    float inv = rsqrtf(tot * (1.0f / DD) + EPS);
    float sc = scalarPtr ? *scalarPtr : 1.0f;
    if (outH) {
        for (int d = 2 * tid; d < DD; d += 512) {
            float y0 = xr[d] * inv, y1 = xr[d + 1] * inv;
            if (scale) { y0 *= scale[d]; y1 *= scale[d + 1]; }
            y0 *= cmul; y1 *= cmul;
            unsigned h, l;
            split_pack(y0, y1, h, l);
            size_t w = (size_t)row * (DD / 2) + d / 2;
            outH[w] = h; outL[w] = l;
        }
    } else {
        for (int d = tid; d < DD; d += 256) {
            float y = xr[d] * inv;
            if (scale) y *= scale[d];
            y *= cmul;
            if (res1) y += res1[(size_t)row * DD + d];
            if (res2) y += res2[(size_t)row * DD + d];
            out[(size_t)row * DD + d] = y * sc;
        }
    }
}

// ---------------- per-head RMS (+ RoPE) -> packed bf16 planes -------------
// reads in[tok*tokStride + colOff + h*HD + d], tok=idx/H, h=idx%H
__global__ void head_norm_rope_kernel(const float* __restrict__ in,
                                      int tokStride, int colOff,
                                      unsigned* __restrict__ outH,
                                      unsigned* __restrict__ outL,
                                      const float* __restrict__ scale,
                                      const int* __restrict__ positions,
                                      int H, int doRope)
{
    int idx = blockIdx.x;
    int tid = threadIdx.x;
    int tok = idx / H;
    int h = idx - tok * H;
    int s = tok % SS;
    int b = tok / SS;
    const float* xr = in + (size_t)tok * tokStride + colOff + h * HD;
    float v = xr[tid];
    float ss = v * v;
    for (int o = 16; o > 0; o >>= 1) ss += __shfl_xor_sync(0xffffffffu, ss, o);
    __shared__ float wsum[4];
    __shared__ float tmp[HD];
    if ((tid & 31) == 0) wsum[tid >> 5] = ss;
    __syncthreads();
    float tot = wsum[0] + wsum[1] + wsum[2] + wsum[3];
    float y = v * rsqrtf(tot * (1.0f / HD) + EPS) * scale[tid];
    if (doRope) {
        tmp[tid] = y;
        __syncthreads();
        int pos = positions[b * SS + s];
        int j = tid & 63;
        float invf = powf(10000.0f, -(float)j / 64.0f);
        float ang = (float)pos * invf;
        float sn, cs;
        sincosf(ang, &sn, &cs);
        float x1 = tmp[j], x2 = tmp[64 + j];
        y = (tid < 64) ? (x1 * cs - x2 * sn) : (x2 * cs + x1 * sn);
        __syncthreads();
    }
    tmp[tid] = y;
    __syncthreads();
    if (tid < 64) {
        unsigned h2, l2;
        split_pack(tmp[2 * tid], tmp[2 * tid + 1], h2, l2);
        size_t w = (size_t)idx * 64 + tid;
        outH[w] = h2; outL[w] = l2;
    }
}

// ---------------- tensor-core flash attention (cp.async pipelined) -------
#define ATQ 128
#define AKT 64
#define AST 68
#define AQ_WORDS (ATQ*AST)
#define AKV_WORDS (AKT*AST)
#define AKV_STAGE_BYTES (4*AKV_WORDS*4)
#define ATT_SMEM_BYTES ((2*AQ_WORDS + 8*AKV_WORDS)*4)

__global__ void __launch_bounds__(256, 1)
fattn_kernel(const unsigned* __restrict__ qh, const unsigned* __restrict__ ql,
             const unsigned* __restrict__ kh, const unsigned* __restrict__ kl,
             const unsigned* __restrict__ vh, const unsigned* __restrict__ vl,
             unsigned* __restrict__ obh, unsigned* __restrict__ obl)
{
    extern __shared__ __align__(16) unsigned att_smem[];
    int b = blockIdx.z, h = blockIdx.y;
    int q0 = blockIdx.x * ATQ;
    int hkv = h / GRP;
    int tid = threadIdx.x, wid = tid >> 5, lane = tid & 31;
    int gid = lane >> 2, tgid = lane & 3;
    int l15 = lane & 15, lHi8 = (lane >> 4) << 3;

    unsigned smemBase = (unsigned)__cvta_generic_to_shared(att_smem);
    unsigned qBaseH = smemBase;
    unsigned qBaseL = smemBase + AQ_WORDS * 4;
    unsigned kvBase0 = smemBase + 2 * AQ_WORDS * 4;

    #pragma unroll
    for (int p = 0; p < 16; p++) {
        int ci = tid + p * 256;
        int plane = ci >> 11, rem = ci & 2047;
        int row = rem >> 4, c = rem & 15;
        const unsigned* src = (plane ? ql : qh)
            + ((size_t)(b * SS + q0 + row) * HQ + h) * 64 + c * 4;
        unsigned dst = (plane ? qBaseL : qBaseH) + (row * AST + c * 4) * 4;
        cp16(dst, src, 16);
    }

    int ntiles = (q0 >> 6) + 2;
    auto fillKV = [&](int st, int j0) {
        unsigned base = kvBase0 + st * AKV_STAGE_BYTES;
        #pragma unroll
        for (int p = 0; p < 16; p++) {
            int ci = tid + p * 256;
            int plane = ci >> 10, rem = ci & 1023;
            int row = rem >> 4, c = rem & 15;
            const unsigned* gp = (plane & 2) ? ((plane & 1) ? vl : vh)
                                             : ((plane & 1) ? kl : kh);
            const unsigned* src = gp + ((size_t)(b * SS + j0 + row) * HKV + hkv) * 64 + c * 4;
            unsigned dst = base + plane * (AKV_WORDS * 4) + (row * AST + c * 4) * 4;
            cp16(dst, src, 16);
        }
        CP_COMMIT();
    };

    fillKV(0, 0);
    CP_WAIT0();
    __syncthreads();

    float oacc[16][4];
    #pragma unroll
    for (int i = 0; i < 16; i++)
        #pragma unroll
        for (int c = 0; c < 4; c++) oacc[i][c] = 0.f;
    float m0 = -1e30f, m1 = -1e30f, l0r = 0.f, l1r = 0.f;

    int rowbase = q0 + wid * 16;
    int kKey = (lane & 7) + ((lane >> 4) << 3);
    int kDimOff = (lane & 8) ? 8 : 0;

    for (int jt = 0;;) {
        int j0 = jt * AKT;
        if (jt + 1 < ntiles) fillKV((jt + 1) & 1, (jt + 1) * AKT);

        if (j0 <= rowbase + 15) {
            unsigned base = kvBase0 + (jt & 1) * AKV_STAGE_BYTES;
            unsigned kBaseH = base;
            unsigned kBaseL = base + AKV_WORDS * 4;
            unsigned vBaseH = base + 2 * AKV_WORDS * 4;
            unsigned vBaseL = base + 3 * AKV_WORDS * 4;

            float s[8][4];
            #pragma unroll
            for (int nf = 0; nf < 8; nf++)
                #pragma unroll
                for (int c = 0; c < 4; c++) s[nf][c] = 0.f;

            #pragma unroll
            for (int kt = 0; kt < 8; kt++) {
                unsigned qhf[4], qlf[4];
                unsigned qoff = (unsigned)((wid * 16 + l15) * (AST * 4) + (kt * 16 + lHi8) * 2);
                LDSM4(qhf[0], qhf[1], qhf[2], qhf[3], qBaseH + qoff);
                LDSM4(qlf[0], qlf[1], qlf[2], qlf[3], qBaseL + qoff);
                int kdd = kt * 16 + kDimOff;
                #pragma unroll
                for (int g2 = 0; g2 < 4; g2++) {
                    unsigned koff = (unsigned)((g2 * 16 + kKey) * (AST * 4) + kdd * 2);
                    unsigned kh0, kh1, kh2, kh3, klo0, klo1, klo2, klo3;
                    LDSM4(kh0, kh1, kh2, kh3, kBaseH + koff);
                    LDSM4(klo0, klo1, klo2, klo3, kBaseL + koff);
                    int n0 = 2 * g2, n1 = 2 * g2 + 1;
                    MMA_BF16(s[n0][0], s[n0][1], s[n0][2], s[n0][3],
                             qlf[0], qlf[1], qlf[2], qlf[3], kh0, kh1);
                    MMA_BF16(s[n0][0], s[n0][1], s[n0][2], s[n0][3],
                             qhf[0], qhf[1], qhf[2], qhf[3], klo0, klo1);
                    MMA_BF16(s[n0][0], s[n0][1], s[n0][2], s[n0][3],
                             qhf[0], qhf[1], qhf[2], qhf[3], kh0, kh1);
                    MMA_BF16(s[n1][0], s[n1][1], s[n1][2], s[n1][3],
                             qlf[0], qlf[1], qlf[2], qlf[3], kh2, kh3);
                    MMA_BF16(s[n1][0], s[n1][1], s[n1][2], s[n1][3],
                             qhf[0], qhf[1], qhf[2], qhf[3], klo2, klo3);
                    MMA_BF16(s[n1][0], s[n1][1], s[n1][2], s[n1][3],
                             qhf[0], qhf[1], qhf[2], qhf[3], kh2, kh3);
                }
            }

            int r0 = rowbase + gid, r1 = r0 + 8;
            if (j0 + AKT - 1 > rowbase) {
                #pragma unroll
                for (int nf = 0; nf < 8; nf++) {
                    int c0 = j0 + nf * 8 + 2 * tgid;
                    if (c0 > r0)     s[nf][0] = -1e30f;
                    if (c0 + 1 > r0) s[nf][1] = -1e30f;
                    if (c0 > r1)     s[nf][2] = -1e30f;
                    if (c0 + 1 > r1) s[nf][3] = -1e30f;
                }
            }

            float t0 = -1e30f, t1 = -1e30f;
            #pragma unroll
            for (int nf = 0; nf < 8; nf++) {
                t0 = fmaxf(t0, fmaxf(s[nf][0], s[nf][1]));
                t1 = fmaxf(t1, fmaxf(s[nf][2], s[nf][3]));
            }
            t0 = fmaxf(t0, __shfl_xor_sync(0xffffffffu, t0, 1));
            t0 = fmaxf(t0, __shfl_xor_sync(0xffffffffu, t0, 2));
            t1 = fmaxf(t1, __shfl_xor_sync(0xffffffffu, t1, 1));
            t1 = fmaxf(t1, __shfl_xor_sync(0xffffffffu, t1, 2));
            float mn0 = fmaxf(m0, t0), mn1 = fmaxf(m1, t1);
            float a0 = __expf(m0 - mn0), a1 = __expf(m1 - mn1);
            m0 = mn0; m1 = mn1;
            float rs0 = 0.f, rs1 = 0.f;
            #pragma unroll
            for (int nf = 0; nf < 8; nf++) {
                s[nf][0] = __expf(s[nf][0] - mn0);
                s[nf][1] = __expf(s[nf][1] - mn0);
                s[nf][2] = __expf(s[nf][2] - mn1);
                s[nf][3] = __expf(s[nf][3] - mn1);
                rs0 += s[nf][0] + s[nf][1];
                rs1 += s[nf][2] + s[nf][3];
            }
            rs0 += __shfl_xor_sync(0xffffffffu, rs0, 1);
            rs0 += __shfl_xor_sync(0xffffffffu, rs0, 2);
            rs1 += __shfl_xor_sync(0xffffffffu, rs1, 1);
            rs1 += __shfl_xor_sync(0xffffffffu, rs1, 2);
            l0r = l0r * a0 + rs0;
            l1r = l1r * a1 + rs1;
            #pragma unroll
            for (int nv = 0; nv < 16; nv++) {
                oacc[nv][0] *= a0; oacc[nv][1] *= a0;
                oacc[nv][2] *= a1; oacc[nv][3] *= a1;
            }

            #pragma unroll
            for (int t = 0; t < 4; t++) {
                unsigned ph[4], pl[4];
                split_pack(s[2 * t][0],     s[2 * t][1],     ph[0], pl[0]);
                split_pack(s[2 * t][2],     s[2 * t][3],     ph[1], pl[1]);
                split_pack(s[2 * t + 1][0], s[2 * t + 1][1], ph[2], pl[2]);
                split_pack(s[2 * t + 1][2], s[2 * t + 1][3], ph[3], pl[3]);
                unsigned vf[16][2];
                int krow = t * 16 + l15;
                #pragma unroll
                for (int np = 0; np < 8; np++) {
                    unsigned voff = (unsigned)(krow * (AST * 4) + (np * 16 + lHi8) * 2);
                    LDSM4T(vf[2 * np][0], vf[2 * np][1], vf[2 * np + 1][0], vf[2 * np + 1][1],
                           vBaseH + voff);
                }
                #pragma unroll
                for (int nv = 0; nv < 16; nv++) {
                    MMA_BF16(oacc[nv][0], oacc[nv][1], oacc[nv][2], oacc[nv][3],
                             pl[0], pl[1], pl[2], pl[3], vf[nv][0], vf[nv][1]);
                    MMA_BF16(oacc[nv][0], oacc[nv][1], oacc[nv][2], oacc[nv][3],
                             ph[0], ph[1], ph[2], ph[3], vf[nv][0], vf[nv][1]);
                }
                #pragma unroll
                for (int np = 0; np < 8; np++) {
                    unsigned voff = (unsigned)(krow * (AST * 4) + (np * 16 + lHi8) * 2);
                    LDSM4T(vf[2 * np][0], vf[2 * np][1], vf[2 * np + 1][0], vf[2 * np + 1][1],
                           vBaseL + voff);
                }
                #pragma unroll
                for (int nv = 0; nv < 16; nv++) {
                    MMA_BF16(oacc[nv][0], oacc[nv][1], oacc[nv][2], oacc[nv][3],
                             ph[0], ph[1], ph[2], ph[3], vf[nv][0], vf[nv][1]);
                }
            }
        }

        if (++jt == ntiles) break;
        CP_WAIT0();
        __syncthreads();
    }

    int r0 = rowbase + gid, r1 = r0 + 8;
    float il0 = 1.f / l0r, il1 = 1.f / l1r;
    #pragma unroll
    for (int nv = 0; nv < 16; nv++) {
        int col = nv * 8 + 2 * tgid;
        unsigned hw, lw;
        split_pack(oacc[nv][0] * il0, oacc[nv][1] * il0, hw, lw);
        size_t w0 = ((size_t)(b * SS + r0) * HQ + h) * 64 + col / 2;
        obh[w0] = hw; obl[w0] = lw;
        split_pack(oacc[nv][2] * il1, oacc[nv][3] * il1, hw, lw);
        size_t w1 = ((size_t)(b * SS + r1) * HQ + h) * 64 + col / 2;
        obh[w1] = hw; obl[w1] = lw;
    }
}

// ================= bf16x3 GEMM (pre-split planes, cp.async 2-stage) =======
#define BAST 20
#define BBST 68
#define GA_WORDS (128*BAST)
#define GB_WORDS (32*BBST)
#define GSTAGE_WORDS (2*GA_WORDS + 2*GB_WORDS)
#define GEMM_DSMEM (2*GSTAGE_WORDS*4)

__global__ void __launch_bounds__(256, 2)
bf16_gemm_kernel(const unsigned* __restrict__ AhG, const unsigned* __restrict__ AlG,
                 const unsigned* __restrict__ BhG, const unsigned* __restrict__ BlG,
                 float* __restrict__ C,
                 int M, int N, int K,
                 const int* __restrict__ aIdxg,
                 const int* __restrict__ cIdxg,
                 const int* __restrict__ cntg,
                 const float* __restrict__ combine,
                 size_t aZW, size_t bZW, int idxZ)
{
    extern __shared__ __align__(16) unsigned dsm[];
    int z = blockIdx.z;
    const unsigned* Ah = AhG + (size_t)z * aZW;
    const unsigned* Al = AlG + (size_t)z * aZW;
    const unsigned* Bh = BhG + (size_t)z * bZW;
    const unsigned* Bl = BlG + (size_t)z * bZW;
    const int* aIdx = aIdxg ? aIdxg + (size_t)z * idxZ : nullptr;
    const int* cIdx = cIdxg ? cIdxg + (size_t)z * idxZ : nullptr;
    int Meff = cntg ? min(M, cntg[z]) : M;
    int bm = blockIdx.y * 128;
    int bn = blockIdx.x * 128;
    if (bm >= Meff) return;
    int Kw = K >> 1, Nw = N >> 1, bnw = bn >> 1;

    int tid = threadIdx.x;
    int wid = tid >> 5, lane = tid & 31;
    int gid = lane >> 2, tgid = lane & 3;
    int wm = (wid & 3) * 32;
    int wn = (wid >> 2) * 64;
    int l15 = lane & 15, lHi8 = (lane >> 4) << 3;

    int am = tid >> 1, ac = (tid & 1) * 2;
    int gr = bm + am;
    int ar = (gr < Meff) ? (aIdx ? aIdx[gr] : gr) : 0;
    int aValid = (gr < Meff) ? 16 : 0;
    const unsigned* aRowH = Ah + (size_t)ar * Kw;
    const unsigned* aRowL = Al + (size_t)ar * Kw;
    int bk = tid >> 3, bc = (2 * tid) & 15;

    unsigned smemBase = (unsigned)__cvta_generic_to_shared(dsm);

    auto fillStage = [&](int st, int k0) {
        int kw0 = k0 >> 1;
        unsigned base = smemBase + st * (GSTAGE_WORDS * 4);
        unsigned aHb = base, aLb = base + GA_WORDS * 4;
        unsigned bHb = aLb + GA_WORDS * 4, bLb = bHb + GB_WORDS * 4;
        #pragma unroll
        for (int c2 = 0; c2 < 2; c2++) {
            int c = ac + c2;
            unsigned d = (am * BAST + c * 4) * 4;
            cp16(aHb + d, aRowH + kw0 + c * 4, aValid);
            cp16(aLb + d, aRowL + kw0 + c * 4, aValid);
        }
        size_t bro = (size_t)(k0 + bk) * Nw + bnw;
        #pragma unroll
        for (int c2 = 0; c2 < 2; c2++) {
            int c = bc + c2;
            unsigned d = (bk * BBST + c * 4) * 4;
            cp16(bHb + d, Bh + bro + c * 4, 16);
            cp16(bLb + d, Bl + bro + c * 4, 16);
        }
        CP_COMMIT();
    };

    float acc[2][8][4];
    #pragma unroll
    for (int i = 0; i < 2; i++)
        #pragma unroll
        for (int j = 0; j < 8; j++)
            #pragma unroll
            for (int c = 0; c < 4; c++) acc[i][j][c] = 0.f;

    int KT = K >> 5;
    fillStage(0, 0);
    CP_WAIT0();
    __syncthreads();

    for (int kt = 0;;) {
        if (kt + 1 < KT) fillStage((kt + 1) & 1, (kt + 1) << 5);

        unsigned base = smemBase + (kt & 1) * (GSTAGE_WORDS * 4);
        unsigned aBaseH = base, aBaseL = base + GA_WORDS * 4;
        unsigned bBaseH = aBaseL + GA_WORDS * 4, bBaseL = bBaseH + GB_WORDS * 4;

        #pragma unroll
        for (int ks = 0; ks < 2; ks++) {
            int kk = ks * 16;
            unsigned ah[2][4], al[2][4];
            #pragma unroll
            for (int mf = 0; mf < 2; mf++) {
                int mrow = wm + mf * 16 + l15;
                unsigned off = (unsigned)(mrow * (BAST * 4) + (kk + lHi8) * 2);
                LDSM4(ah[mf][0], ah[mf][1], ah[mf][2], ah[mf][3], aBaseH + off);
                LDSM4(al[mf][0], al[mf][1], al[mf][2], al[mf][3], aBaseL + off);
            }
            unsigned bfr[8][2];
            int krow = kk + l15;
            #pragma unroll
            for (int nfp = 0; nfp < 4; nfp++) {
                int ncol = wn + nfp * 16 + lHi8;
                unsigned off = (unsigned)(krow * (BBST * 4) + ncol * 2);
                LDSM4T(bfr[2 * nfp][0], bfr[2 * nfp][1],
                       bfr[2 * nfp + 1][0], bfr[2 * nfp + 1][1], bBaseH + off);
            }
            #pragma unroll
            for (int mf = 0; mf < 2; mf++)
                #pragma unroll
                for (int nf = 0; nf < 8; nf++) {
                    MMA_BF16(acc[mf][nf][0], acc[mf][nf][1], acc[mf][nf][2], acc[mf][nf][3],
                             ah[mf][0], ah[mf][1], ah[mf][2], ah[mf][3],
                             bfr[nf][0], bfr[nf][1]);
                    MMA_BF16(acc[mf][nf][0], acc[mf][nf][1], acc[mf][nf][2], acc[mf][nf][3],
                             al[mf][0], al[mf][1], al[mf][2], al[mf][3],
                             bfr[nf][0], bfr[nf][1]);
                }
            #pragma unroll
            for (int nfp = 0; nfp < 4; nfp++) {
                int ncol = wn + nfp * 16 + lHi8;
                unsigned off = (unsigned)(krow * (BBST * 4) + ncol * 2);
                LDSM4T(bfr[2 * nfp][0], bfr[2 * nfp][1],
                       bfr[2 * nfp + 1][0], bfr[2 * nfp + 1][1], bBaseL + off);
            }
            #pragma unroll
            for (int mf = 0; mf < 2; mf++)
                #pragma unroll
                for (int nf = 0; nf < 8; nf++) {
                    MMA_BF16(acc[mf][nf][0], acc[mf][nf][1], acc[mf][nf][2], acc[mf][nf][3],
                             ah[mf][0], ah[mf][1], ah[mf][2], ah[mf][3],
                             bfr[nf][0], bfr[nf][1]);
                }
        }

        if (++kt == KT) break;
        CP_WAIT0();
        __syncthreads();
    }

    #pragma unroll
    for (int mf = 0; mf < 2; mf++) {
        #pragma unroll
        for (int half = 0; half < 2; half++) {
            int row = bm + wm + mf * 16 + gid + half * 8;
            if (row >= Meff) continue;
            int crow = cIdx ? cIdx[row] : row;
            float w = 1.f;
            if (combine) w = combine[crow * EE + z];
            #pragma unroll
            for (int nf = 0; nf < 8; nf++) {
                int col = bn + wn + nf * 8 + 2 * tgid;
                float v0 = acc[mf][nf][half * 2 + 0];
                float v1 = acc[mf][nf][half * 2 + 1];
                float* cp = C + (size_t)crow * N + col;
                if (combine) {
                    atomicAdd(cp, w * v0);
                    atomicAdd(cp + 1, w * v1);
                } else {
                    cp[0] = v0;
                    cp[1] = v1;
                }
            }
        }
    }
}

// ========== gated dual-B GEMM: out = gelu(A*B0)*(A*B1), packed output =====
__global__ void __launch_bounds__(256, 2)
bf16_gated_kernel(const unsigned* __restrict__ Ah, const unsigned* __restrict__ Al,
                  const unsigned* __restrict__ B0hG, const unsigned* __restrict__ B0lG,
                  const unsigned* __restrict__ B1hG, const unsigned* __restrict__ B1lG,
                  unsigned* __restrict__ ChG, unsigned* __restrict__ ClG,
                  int M, int Nout, int K,
                  const int* __restrict__ aIdxg,
                  const int* __restrict__ cntg,
                  size_t bZW, size_t cZW, int idxZ)
{
    extern __shared__ __align__(16) unsigned dsm[];
    int z = blockIdx.z;
    const unsigned* B0h = B0hG + (size_t)z * bZW;
    const unsigned* B0l = B0lG + (size_t)z * bZW;
    const unsigned* B1h = B1hG + (size_t)z * bZW;
    const unsigned* B1l = B1lG + (size_t)z * bZW;
    unsigned* Ch = ChG + (size_t)z * cZW;
    unsigned* Cl = ClG + (size_t)z * cZW;
    const int* aIdx = aIdxg ? aIdxg + (size_t)z * idxZ : nullptr;
    int Meff = cntg ? min(M, cntg[z]) : M;
    int bm = blockIdx.y * 128;
    int bnn = blockIdx.x * 64;
    if (bm >= Meff) return;
    int Kw = K >> 1, Nw = Nout >> 1, bnw = bnn >> 1;

    int tid = threadIdx.x;
    int wid = tid >> 5, lane = tid & 31;
    int gid = lane >> 2, tgid = lane & 3;
    int wm = (wid & 3) * 32;
    int wn32 = (wid >> 2) * 32;
    int l15 = lane & 15, lHi8 = (lane >> 4) << 3;

    int am = tid >> 1, ac = (tid & 1) * 2;
    int gr = bm + am;
    int ar = (gr < Meff) ? (aIdx ? aIdx[gr] : gr) : 0;
    int aValid = (gr < Meff) ? 16 : 0;
    const unsigned* aRowH = Ah + (size_t)ar * Kw;
    const unsigned* aRowL = Al + (size_t)ar * Kw;
    int bk = tid >> 3;
    int brest = (2 * tid) & 15;

    unsigned smemBase = (unsigned)__cvta_generic_to_shared(dsm);

    auto fillStage = [&](int st, int k0) {
        int kw0 = k0 >> 1;
        unsigned base = smemBase + st * (GSTAGE_WORDS * 4);
        unsigned aHb = base, aLb = base + GA_WORDS * 4;
        unsigned bHb = aLb + GA_WORDS * 4, bLb = bHb + GB_WORDS * 4;
        #pragma unroll
        for (int c2 = 0; c2 < 2; c2++) {
            int c = ac + c2;
            unsigned d = (am * BAST + c * 4) * 4;
            cp16(aHb + d, aRowH + kw0 + c * 4, aValid);
            cp16(aLb + d, aRowL + kw0 + c * 4, aValid);
        }
        size_t bro = (size_t)(k0 + bk) * Nw + bnw;
        #pragma unroll
        for (int c2 = 0; c2 < 2; c2++) {
            int cc = brest + c2;
            int srcSel = cc >> 3, c = cc & 7;
            unsigned d = (bk * BBST + srcSel * 32 + c * 4) * 4;
            cp16(bHb + d, (srcSel ? B1h : B0h) + bro + c * 4, 16);
            cp16(bLb + d, (srcSel ? B1l : B0l) + bro + c * 4, 16);
        }
        CP_COMMIT();
    };

    float acc0[2][4][4], acc1[2][4][4];
    #pragma unroll
    for (int i = 0; i < 2; i++)
        #pragma unroll
        for (int j = 0; j < 4; j++)
            #pragma unroll
            for (int c = 0; c < 4; c++) { acc0[i][j][c] = 0.f; acc1[i][j][c] = 0.f; }

    int KT = K >> 5;
    fillStage(0, 0);
    CP_WAIT0();
    __syncthreads();

    for (int kt = 0;;) {
        if (kt + 1 < KT) fillStage((kt + 1) & 1, (kt + 1) << 5);

        unsigned base = smemBase + (kt & 1) * (GSTAGE_WORDS * 4);
        unsigned aBaseH = base, aBaseL = base + GA_WORDS * 4;
        unsigned bBaseH = aBaseL + GA_WORDS * 4, bBaseL = bBaseH + GB_WORDS * 4;

        #pragma unroll
        for (int ks = 0; ks < 2; ks++) {
            int kk = ks * 16;
            unsigned ah[2][4], al[2][4];
            #pragma unroll
            for (int mf = 0; mf < 2; mf++) {
                int mrow = wm + mf * 16 + l15;
                unsigned off = (unsigned)(mrow * (BAST * 4) + (kk + lHi8) * 2);
                LDSM4(ah[mf][0], ah[mf][1], ah[mf][2], ah[mf][3], aBaseH + off);
                LDSM4(al[mf][0], al[mf][1], al[mf][2], al[mf][3], aBaseL + off);
            }
            int krow = kk + l15;
            #pragma unroll
            for (int which = 0; which < 2; which++) {
                unsigned bfr[4][2];
                int colbase = which * 64 + wn32;
                #pragma unroll
                for (int nfp = 0; nfp < 2; nfp++) {
                    int ncol = colbase + nfp * 16 + lHi8;
                    unsigned off = (unsigned)(krow * (BBST * 4) + ncol * 2);
                    LDSM4T(bfr[2 * nfp][0], bfr[2 * nfp][1],
                           bfr[2 * nfp + 1][0], bfr[2 * nfp + 1][1], bBaseH + off);
                }
                #pragma unroll
                for (int mf = 0; mf < 2; mf++)
                    #pragma unroll
                    for (int nf = 0; nf < 4; nf++) {
                        float* a = which ? acc1[mf][nf] : acc0[mf][nf];
                        MMA_BF16(a[0], a[1], a[2], a[3],
                                 ah[mf][0], ah[mf][1], ah[mf][2], ah[mf][3],
                                 bfr[nf][0], bfr[nf][1]);
                        MMA_BF16(a[0], a[1], a[2], a[3],
                                 al[mf][0], al[mf][1], al[mf][2], al[mf][3],
                                 bfr[nf][0], bfr[nf][1]);
                    }
                #pragma unroll
                for (int nfp = 0; nfp < 2; nfp++) {
                    int ncol = colbase + nfp * 16 + lHi8;
                    unsigned off = (unsigned)(krow * (BBST * 4) + ncol * 2);
                    LDSM4T(bfr[2 * nfp][0], bfr[2 * nfp][1],
                           bfr[2 * nfp + 1][0], bfr[2 * nfp + 1][1], bBaseL + off);
                }
                #pragma unroll
                for (int mf = 0; mf < 2; mf++)
                    #pragma unroll
                    for (int nf = 0; nf < 4; nf++) {
                        float* a = which ? acc1[mf][nf] : acc0[mf][nf];
                        MMA_BF16(a[0], a[1], a[2], a[3],
                                 ah[mf][0], ah[mf][1], ah[mf][2], ah[mf][3],
                                 bfr[nf][0], bfr[nf][1]);
                    }
            }
        }

        if (++kt == KT) break;
        CP_WAIT0();
        __syncthreads();
    }

    #pragma unroll
    for (int mf = 0; mf < 2; mf++) {
        #pragma unroll
        for (int half = 0; half < 2; half++) {
            int row = bm + wm + mf * 16 + gid + half * 8;
            if (row >= Meff) continue;
            #pragma unroll
            for (int nf = 0; nf < 4; nf++) {
                int col = bnn + wn32 + nf * 8 + 2 * tgid;
                float g0v = gelu_tanh(acc0[mf][nf][half * 2 + 0]) * acc1[mf][nf][half * 2 + 0];
                float g1v = gelu_tanh(acc0[mf][nf][half * 2 + 1]) * acc1[mf][nf][half * 2 + 1];
                unsigned hw, lw;
                split_pack(g0v, g1v, hw, lw);
                size_t w = (size_t)row * Nw + (col >> 1);
                Ch[w] = hw; Cl[w] = lw;
            }
        }
    }
}

// ---------------- router ----------------
__global__ void router_kernel(const float* __restrict__ gin,
                              const float* __restrict__ wg,
                              float* __restrict__ combine,
                              int* __restrict__ cnt,
                              int* __restrict__ idx,
                              float* __restrict__ psum)
{
    int tok = blockIdx.x;
    int tid = threadIdx.x;
    float s[EE] = {};
    const float* g = gin + (size_t)tok * DD;
    for (int d = tid; d < DD; d += 256) {
        float gv = g[d];
        const float* w = wg + d * EE;
        #pragma unroll
        for (int e = 0; e < EE; e++) s[e] += gv * w[e];
    }
    __shared__ float sh[256][EE];
    #pragma unroll
    for (int e = 0; e < EE; e++) sh[tid][e] = s[e];
    __syncthreads();
    for (int str = 128; str > 0; str >>= 1) {
        if (tid < str) {
            #pragma unroll
            for (int e = 0; e < EE; e++) sh[tid][e] += sh[tid + str][e];
        }
        __syncthreads();
    }
    if (tid == 0) {
        float pe[EE];
        float mx = -FLT_MAX;
        #pragma unroll
        for (int e = 0; e < EE; e++) mx = fmaxf(mx, sh[0][e]);
        float sum = 0.f;
        #pragma unroll
        for (int e = 0; e < EE; e++) { pe[e] = expf(sh[0][e] - mx); sum += pe[e]; }
        float inv = 1.0f / sum;
        #pragma unroll
        for (int e = 0; e < EE; e++) { pe[e] *= inv; atomicAdd(&psum[e], pe[e]); }
        int i0 = 0;
        #pragma unroll
        for (int e = 1; e < EE; e++) if (pe[e] > pe[i0]) i0 = e;
        int i1 = (i0 == 0) ? 1 : 0;
        #pragma unroll
        for (int e = 0; e < EE; e++) if (e != i0 && e != i1 && pe[e] > pe[i1]) i1 = e;
        float tot = pe[i0] + pe[i1];
        float w0 = pe[i0] / tot, w1 = pe[i1] / tot;
        float* crow = combine + (size_t)tok * EE;
        #pragma unroll
        for (int e = 0; e < EE; e++) crow[e] = 0.f;
        crow[i0] = w0; crow[i1] = w1;
        int p0 = atomicAdd(&cnt[i0], 1); idx[i0 * TT + p0] = tok;
        int p1 = atomicAdd(&cnt[i1], 1); idx[i1 * TT + p1] = tok;
    }
}

__global__ void lb_kernel(const int* __restrict__ cnt, const float* __restrict__ psum,
                          float* __restrict__ out)
{
    float lb = 0.f;
    #pragma unroll
    for (int e = 0; e < EE; e++)
        lb += ((float)cnt[e] / (float)TT) * (psum[e] / (float)TT);
    out[0] = lb * ((float)(EE * EE) / (float)EE);
}

// ==================== host launcher ====================
extern "C" void kernel_launch(void* const* d_in, const int* in_sizes, int n_in,
                              void* d_out, int out_size)
{
    const int*   positions       = (const int*)  d_in[0];
    const float* x               = (const float*)d_in[1];
    const float* pre_attn_scale  = (const float*)d_in[2];
    const float* wq              = (const float*)d_in[3];
    const float* wk              = (const float*)d_in[4];
    const float* wv              = (const float*)d_in[5];
    const float* wo              = (const float*)d_in[6];
    const float* q_norm_scale    = (const float*)d_in[7];
    const float* k_norm_scale    = (const float*)d_in[8];
    const float* v_norm_scale    = (const float*)d_in[9];
    const float* post_attn_scale = (const float*)d_in[10];
    const float* pre_ffw_scale   = (const float*)d_in[11];
    const float* shared_wi0      = (const float*)d_in[12];
    const float* shared_wi1      = (const float*)d_in[13];
    const float* shared_wo       = (const float*)d_in[14];
    const float* post_ff1_scale  = (const float*)d_in[15];
    const float* pre_ff2_scale   = (const float*)d_in[16];
    const float* router_scale    = (const float*)d_in[17];
    const float* w_gate          = (const float*)d_in[18];
    const float* ewi0            = (const float*)d_in[19];
    const float* ewi1            = (const float*)d_in[20];
    const float* ewo             = (const float*)d_in[21];
    const float* post_ff2_scale  = (const float*)d_in[22];
    const float* layer_scalar    = (const float*)d_in[23];
    float* out = (float*)d_out;

    static int smemConfigured = 0;
    if (!smemConfigured) {
        cudaFuncSetAttribute(fattn_kernel,
                             cudaFuncAttributeMaxDynamicSharedMemorySize, ATT_SMEM_BYTES);
        cudaFuncSetAttribute(bf16_gemm_kernel,
                             cudaFuncAttributeMaxDynamicSharedMemorySize, GEMM_DSMEM);
        cudaFuncSetAttribute(bf16_gated_kernel,
                             cudaFuncAttributeMaxDynamicSharedMemorySize, GEMM_DSMEM);
        smemConfigured = 1;
    }

    float* sc = nullptr;
    int*   isc = nullptr;
    cudaGetSymbolAddress((void**)&sc, g_scratch);
    cudaGetSymbolAddress((void**)&isc, g_iscratch);

    unsigned* U = (unsigned*)sc;
    auto uptr = [&](size_t off) { return U + off; };

    unsigned* lnxH = uptr(OFF_LNXH); unsigned* lnxL = uptr(OFF_LNXL);
    float* qkvf = sc + OFF_QKVF;
    unsigned* qsh = uptr(OFF_QH); unsigned* qsl = uptr(OFF_QL);
    unsigned* ksh = uptr(OFF_KH); unsigned* ksl = uptr(OFF_KL);
    unsigned* vsh = uptr(OFF_VH); unsigned* vsl = uptr(OFF_VL);
    unsigned* obh = uptr(OFF_OBH); unsigned* obl = uptr(OFF_OBL);
    float* attnb = sc + OFF_ATTN; float* hb = sc + OFF_H;
    unsigned* ffinH = uptr(OFF_FFINH); unsigned* ffinL = uptr(OFF_FFINL);
    unsigned* g0H = uptr(OFF_G0H); unsigned* g0L = uptr(OFF_G0L);
    float* shb = sc + OFF_SHB;
    unsigned* rinH = uptr(OFF_RINH); unsigned* rinL = uptr(OFF_RINL);
    float* gin = sc + OFF_GIN; float* routb = sc + OFF_ROUT;
    unsigned* egH = uptr(OFF_EGH); unsigned* egL = uptr(OFF_EGL);
    float* comb = sc + OFF_COMB; float* psum = sc + OFF_PSUM;
    int* idx = isc; int* cnt = isc + EE * TT;

    auto splitBF = [&](const float* src, size_t nElts, size_t offH, size_t offL) {
        size_t nW = nElts / 2;
        split_bf_kernel<<<(unsigned)((nW + 255) / 256), 256>>>(
            (const float2*)src, uptr(offH), uptr(offL), nW);
    };

    // ---- weight pre-split ----
    split_qkv_kernel<<<(unsigned)(SZ_WQKV / 2 / 256), 256>>>(
        wq, wk, wv, uptr(OFF_WQKVH), uptr(OFF_WQKVL));
    splitBF(wo, SZ_WQ, OFF_WOH, OFF_WOL);
    splitBF(shared_wi0, SZ_WFF, OFF_WI0H, OFF_WI0L);
    splitBF(shared_wi1, SZ_WFF, OFF_WI1H, OFF_WI1L);
    splitBF(shared_wo, SZ_WFF, OFF_SWOH, OFF_SWOL);
    splitBF(ewi0, SZ_EW, OFF_EWI0H, OFF_EWI0L);
    splitBF(ewi1, SZ_EW, OFF_EWI1H, OFF_EWI1L);
    splitBF(ewo, SZ_EW, OFF_EWOH, OFF_EWOL);

    auto gemm = [&](const unsigned* Ah, const unsigned* Al,
                    size_t BhOff, size_t BlOff, float* C, int M, int N, int K,
                    const int* aI, const int* cI, const int* ct, const float* cw,
                    size_t aZW, size_t bZW, int nz) {
        dim3 grid(N / 128, (M + 127) / 128, nz);
        bf16_gemm_kernel<<<grid, 256, GEMM_DSMEM>>>(Ah, Al, uptr(BhOff), uptr(BlOff),
                                                    C, M, N, K, aI, cI, ct, cw,
                                                    aZW, bZW, TT);
    };

    // 1) pre-attn norm (packed out)
    rms_kernel<<<TT, 256>>>(x, pre_attn_scale, 1.f, nullptr, nullptr, nullptr,
                            nullptr, lnxH, lnxL);

    // 2) fused QKV projection (single N=4096 GEMM, f32 out)
    gemm(lnxH, lnxL, OFF_WQKVH, OFF_WQKVL, qkvf, TT, NQKV, DD,
         nullptr, nullptr, nullptr, nullptr, 0, 0, 1);

    // 3) per-head norms + rope -> packed q/k/v planes (reading fused layout)
    head_norm_rope_kernel<<<TT * HQ, HD>>>(qkvf, NQKV, 0, qsh, qsl,
                                           q_norm_scale, positions, HQ, 1);
    head_norm_rope_kernel<<<TT * HKV, HD>>>(qkvf, NQKV, 2048, ksh, ksl,
                                            k_norm_scale, positions, HKV, 1);
    head_norm_rope_kernel<<<TT * HKV, HD>>>(qkvf, NQKV, 3072, vsh, vsl,
                                            v_norm_scale, positions, HKV, 0);

    // 4) attention -> packed ob planes
    {
        dim3 grid(SS / ATQ, HQ, BB);
        fattn_kernel<<<grid, 256, ATT_SMEM_BYTES>>>(qsh, qsl, ksh, ksl, vsh, vsl, obh, obl);
    }

    // 5) output projection + post-attn norm + residual
    gemm(obh, obl, OFF_WOH, OFF_WOL, attnb, TT, DD, HQ * HD,
         nullptr, nullptr, nullptr, nullptr, 0, 0, 1);
    rms_kernel<<<TT, 256>>>(attnb, post_attn_scale, 1.f, x, nullptr, nullptr,
                            hb, nullptr, nullptr);

    // 6) shared FFN
    rms_kernel<<<TT, 256>>>(hb, pre_ffw_scale, 1.f, nullptr, nullptr, nullptr,
                            nullptr, ffinH, ffinL);
    {
        dim3 grid(FS / 64, TT / 128, 1);
        bf16_gated_kernel<<<grid, 256, GEMM_DSMEM>>>(
            ffinH, ffinL, uptr(OFF_WI0H), uptr(OFF_WI0L), uptr(OFF_WI1H), uptr(OFF_WI1L),
            g0H, g0L, TT, FS, DD, nullptr, nullptr, 0, 0, TT);
    }
    gemm(g0H, g0L, OFF_SWOH, OFF_SWOL, shb, TT, DD, FS,
         nullptr, nullptr, nullptr, nullptr, 0, 0, 1);
    rms_kernel<<<TT, 256>>>(shb, post_ff1_scale, 1.f, nullptr, nullptr, nullptr,
                            shb, nullptr, nullptr);

    // 7) router inputs
    rms_kernel<<<TT, 256>>>(hb, pre_ff2_scale, 1.f, nullptr, nullptr, nullptr,
                            nullptr, rinH, rinL);
    rms_kernel<<<TT, 256>>>(hb, router_scale, 0.02209708691207961f,
                            nullptr, nullptr, nullptr, gin, nullptr, nullptr);

    // 8) router + batched MoE
    cudaMemsetAsync(cnt, 0, EE * sizeof(int));
    cudaMemsetAsync(psum, 0, EE * sizeof(float));
    cudaMemsetAsync(routb, 0, SZ_TD * sizeof(float));
    router_kernel<<<TT, 256>>>(gin, w_gate, comb, cnt, idx, psum);

    {
        dim3 grid(FE / 64, TT / 128, EE);
        bf16_gated_kernel<<<grid, 256, GEMM_DSMEM>>>(
            rinH, rinL, uptr(OFF_EWI0H), uptr(OFF_EWI0L), uptr(OFF_EWI1H), uptr(OFF_EWI1L),
            egH, egL, TT, FE, DD, idx, cnt,
            (size_t)DD * FE / 2, (size_t)TT * FE / 2, TT);
    }
    {
        dim3 grid(DD / 128, TT / 128, EE);
        bf16_gemm_kernel<<<grid, 256, GEMM_DSMEM>>>(
            egH, egL, uptr(OFF_EWOH), uptr(OFF_EWOL), routb, TT, DD, FE,
            nullptr, idx, cnt, comb,
            (size_t)TT * FE / 2, (size_t)FE * DD / 2, TT);
    }

    // 9) final combine
    rms_kernel<<<TT, 256>>>(routb, post_ff2_scale, 1.f, shb, hb, layer_scalar,
                            out, nullptr, nullptr);

    // 10) lb loss
    if (out_size > TT * DD) {
        lb_kernel<<<1, 1>>>(cnt, psum, out + (size_t)TT * DD);
    }
}

// round 13
// speedup vs baseline: 1.0210x; 1.0050x over previous
#include <cuda_runtime.h>
#include <cuda_bf16.h>
#include <cfloat>
#include <math.h>

#define BB 4
#define SS 1024
#define DD 2048
#define HQ 16
#define HKV 8
#define HD 128
#define GRP 2
#define EE 8
#define FE 1024
#define FS 8192
#define TT (BB*SS)
#define EPS 1e-6f
#define NQKV 4096

#define SZ_TD   ((size_t)TT*DD)
#define SZ_TQ   ((size_t)TT*HQ*HD)
#define SZ_TKV  ((size_t)TT*HKV*HD)
#define SZ_TFS  ((size_t)TT*FS)

#define OFF_LNXH  ((size_t)0)
#define OFF_LNXL  (OFF_LNXH + SZ_TD/2)
#define OFF_QKVF  (OFF_LNXL + SZ_TD/2)
#define OFF_QH    (OFF_QKVF + (size_t)TT*NQKV)
#define OFF_QL    (OFF_QH   + SZ_TQ/2)
#define OFF_KH    (OFF_QL   + SZ_TQ/2)
#define OFF_KL    (OFF_KH   + SZ_TKV/2)
#define OFF_VH    (OFF_KL   + SZ_TKV/2)
#define OFF_VL    (OFF_VH   + SZ_TKV/2)
#define OFF_OBH   (OFF_VL   + SZ_TKV/2)
#define OFF_OBL   (OFF_OBH  + SZ_TQ/2)
#define OFF_ATTN  (OFF_OBL  + SZ_TQ/2)
#define OFF_H     (OFF_ATTN + SZ_TD)
#define OFF_FFINH (OFF_H    + SZ_TD)
#define OFF_FFINL (OFF_FFINH+ SZ_TD/2)
#define OFF_G0H   (OFF_FFINL+ SZ_TD/2)
#define OFF_G0L   (OFF_G0H  + SZ_TFS/2)
#define OFF_SHB   (OFF_G0L  + SZ_TFS/2)
#define OFF_RINH  (OFF_SHB  + SZ_TD)
#define OFF_RINL  (OFF_RINH + SZ_TD/2)
#define OFF_GIN   (OFF_RINL + SZ_TD/2)
#define OFF_ROUT  (OFF_GIN  + SZ_TD)
#define OFF_EGH   (OFF_ROUT + SZ_TD)
#define OFF_EGL   (OFF_EGH  + SZ_TFS/2)
#define OFF_COMB  (OFF_EGL  + SZ_TFS/2)
#define OFF_PSUM  (OFF_COMB + (size_t)TT*EE)
#define SZ_WQKV ((size_t)DD*NQKV)
#define SZ_WQ  ((size_t)DD*HQ*HD)
#define SZ_WFF ((size_t)DD*FS)
#define SZ_EW  ((size_t)EE*DD*FE)
#define OFF_WQKVH (OFF_PSUM + 8)
#define OFF_WQKVL (OFF_WQKVH + SZ_WQKV/2)
#define OFF_WOH   (OFF_WQKVL + SZ_WQKV/2)
#define OFF_WOL   (OFF_WOH + SZ_WQ/2)
#define OFF_WI0H  (OFF_WOL + SZ_WQ/2)
#define OFF_WI0L  (OFF_WI0H + SZ_WFF/2)
#define OFF_WI1H  (OFF_WI0L + SZ_WFF/2)
#define OFF_WI1L  (OFF_WI1H + SZ_WFF/2)
#define OFF_SWOH  (OFF_WI1L + SZ_WFF/2)
#define OFF_SWOL  (OFF_SWOH + SZ_WFF/2)
#define OFF_EWI0H (OFF_SWOL + SZ_WFF/2)
#define OFF_EWI0L (OFF_EWI0H + SZ_EW/2)
#define OFF_EWI1H (OFF_EWI0L + SZ_EW/2)
#define OFF_EWI1L (OFF_EWI1H + SZ_EW/2)
#define OFF_EWOH  (OFF_EWI1L + SZ_EW/2)
#define OFF_EWOL  (OFF_EWOH + SZ_EW/2)
#define SCRATCH_TOTAL (OFF_EWOL + SZ_EW/2)

__device__ float g_scratch[SCRATCH_TOTAL];
__device__ int   g_iscratch[EE*TT + EE];

__device__ __forceinline__ float gelu_tanh(float v) {
    const float c = 0.7978845608028654f;
    float u = c * (v + 0.044715f * v * v * v);
    return 0.5f * v * (1.0f + tanhf(u));
}
__device__ __forceinline__ unsigned pack_bf16(float x, float y) {
    __nv_bfloat162 t = __floats2bfloat162_rn(x, y);
    return *reinterpret_cast<unsigned*>(&t);
}
__device__ __forceinline__ void split_pack(float x, float y,
                                           unsigned &hiW, unsigned &loW0) {
    __nv_bfloat16 bx = __float2bfloat16_rn(x);
    __nv_bfloat16 by = __float2bfloat16_rn(y);
    float hx = __bfloat162float(bx);
    float hy = __bfloat162float(by);
    __nv_bfloat162 h2; h2.x = bx; h2.y = by;
    hiW = *reinterpret_cast<unsigned*>(&h2);
    loW0 = pack_bf16(x - hx, y - hy);
}
__device__ __forceinline__ void cp16(unsigned dst, const void* src, int srcBytes) {
    asm volatile("cp.async.cg.shared.global [%0], [%1], 16, %2;"
                 :: "r"(dst), "l"(src), "r"(srcBytes));
}
#define CP_COMMIT() asm volatile("cp.async.commit_group;")
#define CP_WAIT0()  asm volatile("cp.async.wait_group 0;")

#define LDSM4(r0,r1,r2,r3,addr) \
    asm volatile("ldmatrix.sync.aligned.m8n8.x4.shared.b16 {%0,%1,%2,%3}, [%4];" \
                 : "=r"(r0),"=r"(r1),"=r"(r2),"=r"(r3) : "r"(addr))
#define LDSM4T(r0,r1,r2,r3,addr) \
    asm volatile("ldmatrix.sync.aligned.m8n8.x4.trans.shared.b16 {%0,%1,%2,%3}, [%4];" \
                 : "=r"(r0),"=r"(r1),"=r"(r2),"=r"(r3) : "r"(addr))
#define MMA_BF16(d0,d1,d2,d3,a0,a1,a2,a3,b0,b1) \
    asm volatile("mma.sync.aligned.m16n8k16.row.col.f32.bf16.bf16.f32 " \
                 "{%0,%1,%2,%3}, {%4,%5,%6,%7}, {%8,%9}, {%0,%1,%2,%3};" \
                 : "+f"(d0),"+f"(d1),"+f"(d2),"+f"(d3) \
                 : "r"(a0),"r"(a1),"r"(a2),"r"(a3),"r"(b0),"r"(b1))

// ---------------- splits ----------------
__global__ void split_bf_kernel(const float2* __restrict__ in,
                                unsigned* __restrict__ hi,
                                unsigned* __restrict__ lo, size_t nWords)
{
    size_t i = (size_t)blockIdx.x * 256 + threadIdx.x;
    if (i < nWords) {
        float2 v = in[i];
        unsigned h, l;
        split_pack(v.x, v.y, h, l);
        hi[i] = h; lo[i] = l;
    }
}
__global__ void split_qkv_kernel(const float* __restrict__ wq,
                                 const float* __restrict__ wk,
                                 const float* __restrict__ wv,
                                 unsigned* __restrict__ hi,
                                 unsigned* __restrict__ lo)
{
    size_t w = (size_t)blockIdx.x * 256 + threadIdx.x;
    if (w >= (size_t)DD * (NQKV / 2)) return;
    int d = (int)(w / (NQKV / 2));
    int n0 = 2 * (int)(w % (NQKV / 2));
    float x, y;
    if (n0 < 2048)      { const float* p = wq + (size_t)d * 2048 + n0;          x = p[0]; y = p[1]; }
    else if (n0 < 3072) { const float* p = wk + (size_t)d * 1024 + (n0 - 2048); x = p[0]; y = p[1]; }
    else                { const float* p = wv + (size_t)d * 1024 + (n0 - 3072); x = p[0]; y = p[1]; }
    unsigned h, l;
    split_pack(x, y, h, l);
    hi[w] = h; lo[w] = l;
}

// ---------------- RMS norm (single output) ----------------
__global__ void rms_kernel(const float* __restrict__ in,
                           const float* __restrict__ scale, float cmul,
                           const float* __restrict__ res1,
                           const float* __restrict__ res2,
                           const float* __restrict__ scalarPtr,
                           float* __restrict__ out,
                           unsigned* __restrict__ outH,
                           unsigned* __restrict__ outL)
{
    int row = blockIdx.x;
    int tid = threadIdx.x;
    const float* xr = in + (size_t)row * DD;
    float ss = 0.f;
    for (int d = tid; d < DD; d += 256) { float v = xr[d]; ss += v * v; }
    for (int o = 16; o > 0; o >>= 1) ss += __shfl_xor_sync(0xffffffffu, ss, o);
    __shared__ float wsum[8];
    if ((tid & 31) == 0) wsum[tid >> 5] = ss;
    __syncthreads();
    float tot = 0.f;
    #pragma unroll
    for (int w = 0; w < 8; w++) tot += wsum[w];
    float inv = rsqrtf(tot * (1.0f / DD) + EPS);
    float sc = scalarPtr ? *scalarPtr : 1.0f;
    if (outH) {
        for (int d = 2 * tid; d < DD; d += 512) {
            float y0 = xr[d] * inv, y1 = xr[d + 1] * inv;
            if (scale) { y0 *= scale[d]; y1 *= scale[d + 1]; }
            y0 *= cmul; y1 *= cmul;
            unsigned h, l;
            split_pack(y0, y1, h, l);
            size_t w = (size_t)row * (DD / 2) + d / 2;
            outH[w] = h; outL[w] = l;
        }
    } else {
        for (int d = tid; d < DD; d += 256) {
            float y = xr[d] * inv;
            if (scale) y *= scale[d];
            y *= cmul;
            if (res1) y += res1[(size_t)row * DD + d];
            if (res2) y += res2[(size_t)row * DD + d];
            out[(size_t)row * DD + d] = y * sc;
        }
    }
}

// ---------------- dual RMS: rin (packed, pre_ff2_scale) + gin (f32, router) --
__global__ void rms_dual_kernel(const float* __restrict__ in,
                                const float* __restrict__ scaleA,   // pre_ff2
                                unsigned* __restrict__ outAH,
                                unsigned* __restrict__ outAL,
                                const float* __restrict__ scaleB,   // router
                                float cmulB,
                                float* __restrict__ outB)
{
    int row = blockIdx.x;
    int tid = threadIdx.x;
    const float* xr = in + (size_t)row * DD;
    float ss = 0.f;
    for (int d = tid; d < DD; d += 256) { float v = xr[d]; ss += v * v; }
    for (int o = 16; o > 0; o >>= 1) ss += __shfl_xor_sync(0xffffffffu, ss, o);
    __shared__ float wsum[8];
    if ((tid & 31) == 0) wsum[tid >> 5] = ss;
    __syncthreads();
    float tot = 0.f;
    #pragma unroll
    for (int w = 0; w < 8; w++) tot += wsum[w];
    float inv = rsqrtf(tot * (1.0f / DD) + EPS);
    for (int d = 2 * tid; d < DD; d += 512) {
        float x0 = xr[d], x1 = xr[d + 1];
        float a0 = x0 * inv * scaleA[d], a1 = x1 * inv * scaleA[d + 1];
        unsigned h, l;
        split_pack(a0, a1, h, l);
        size_t w = (size_t)row * (DD / 2) + d / 2;
        outAH[w] = h; outAL[w] = l;
        outB[(size_t)row * DD + d]     = x0 * inv * scaleB[d] * cmulB;
        outB[(size_t)row * DD + d + 1] = x1 * inv * scaleB[d + 1] * cmulB;
    }
}

// ---------------- per-head RMS (+ RoPE) ----------------
__global__ void head_norm_rope_kernel(const float* __restrict__ in,
                                      int tokStride, int colOff,
                                      unsigned* __restrict__ outH,
                                      unsigned* __restrict__ outL,
                                      const float* __restrict__ scale,
                                      const int* __restrict__ positions,
                                      int H, int doRope)
{
    int idx = blockIdx.x;
    int tid = threadIdx.x;
    int tok = idx / H;
    int h = idx - tok * H;
    int s = tok % SS;
    int b = tok / SS;
    const float* xr = in + (size_t)tok * tokStride + colOff + h * HD;
    float v = xr[tid];
    float ss = v * v;
    for (int o = 16; o > 0; o >>= 1) ss += __shfl_xor_sync(0xffffffffu, ss, o);
    __shared__ float wsum[4];
    __shared__ float tmp[HD];
    if ((tid & 31) == 0) wsum[tid >> 5] = ss;
    __syncthreads();
    float tot = wsum[0] + wsum[1] + wsum[2] + wsum[3];
    float y = v * rsqrtf(tot * (1.0f / HD) + EPS) * scale[tid];
    if (doRope) {
        tmp[tid] = y;
        __syncthreads();
        int pos = positions[b * SS + s];
        int j = tid & 63;
        float invf = powf(10000.0f, -(float)j / 64.0f);
        float ang = (float)pos * invf;
        float sn, cs;
        sincosf(ang, &sn, &cs);
        float x1 = tmp[j], x2 = tmp[64 + j];
        y = (tid < 64) ? (x1 * cs - x2 * sn) : (x2 * cs + x1 * sn);
        __syncthreads();
    }
    tmp[tid] = y;
    __syncthreads();
    if (tid < 64) {
        unsigned h2, l2;
        split_pack(tmp[2 * tid], tmp[2 * tid + 1], h2, l2);
        size_t w = (size_t)idx * 64 + tid;
        outH[w] = h2; outL[w] = l2;
    }
}

// ---------------- flash attention (heavy blocks scheduled first) ----------
#define ATQ 128
#define AKT 64
#define AST 68
#define AQ_WORDS (ATQ*AST)
#define AKV_WORDS (AKT*AST)
#define AKV_STAGE_BYTES (4*AKV_WORDS*4)
#define ATT_SMEM_BYTES ((2*AQ_WORDS + 8*AKV_WORDS)*4)

__global__ void __launch_bounds__(256, 1)
fattn_kernel(const unsigned* __restrict__ qh, const unsigned* __restrict__ ql,
             const unsigned* __restrict__ kh, const unsigned* __restrict__ kl,
             const unsigned* __restrict__ vh, const unsigned* __restrict__ vl,
             unsigned* __restrict__ obh, unsigned* __restrict__ obl)
{
    extern __shared__ __align__(16) unsigned att_smem[];
    int b = blockIdx.z, h = blockIdx.y;
    int q0 = (gridDim.x - 1 - blockIdx.x) * ATQ;   // heavy (large-q0) blocks first
    int hkv = h / GRP;
    int tid = threadIdx.x, wid = tid >> 5, lane = tid & 31;
    int gid = lane >> 2, tgid = lane & 3;
    int l15 = lane & 15, lHi8 = (lane >> 4) << 3;

    unsigned smemBase = (unsigned)__cvta_generic_to_shared(att_smem);
    unsigned qBaseH = smemBase;
    unsigned qBaseL = smemBase + AQ_WORDS * 4;
    unsigned kvBase0 = smemBase + 2 * AQ_WORDS * 4;

    #pragma unroll
    for (int p = 0; p < 16; p++) {
        int ci = tid + p * 256;
        int plane = ci >> 11, rem = ci & 2047;
        int row = rem >> 4, c = rem & 15;
        const unsigned* src = (plane ? ql : qh)
            + ((size_t)(b * SS + q0 + row) * HQ + h) * 64 + c * 4;
        unsigned dst = (plane ? qBaseL : qBaseH) + (row * AST + c * 4) * 4;
        cp16(dst, src, 16);
    }

    int ntiles = (q0 >> 6) + 2;
    auto fillKV = [&](int st, int j0) {
        unsigned base = kvBase0 + st * AKV_STAGE_BYTES;
        #pragma unroll
        for (int p = 0; p < 16; p++) {
            int ci = tid + p * 256;
            int plane = ci >> 10, rem = ci & 1023;
            int row = rem >> 4, c = rem & 15;
            const unsigned* gp = (plane & 2) ? ((plane & 1) ? vl : vh)
                                             : ((plane & 1) ? kl : kh);
            const unsigned* src = gp + ((size_t)(b * SS + j0 + row) * HKV + hkv) * 64 + c * 4;
            unsigned dst = base + plane * (AKV_WORDS * 4) + (row * AST + c * 4) * 4;
            cp16(dst, src, 16);
        }
        CP_COMMIT();
    };

    fillKV(0, 0);
    CP_WAIT0();
    __syncthreads();

    float oacc[16][4];
    #pragma unroll
    for (int i = 0; i < 16; i++)
        #pragma unroll
        for (int c = 0; c < 4; c++) oacc[i][c] = 0.f;
    float m0 = -1e30f, m1 = -1e30f, l0r = 0.f, l1r = 0.f;

    int rowbase = q0 + wid * 16;
    int kKey = (lane & 7) + ((lane >> 4) << 3);
    int kDimOff = (lane & 8) ? 8 : 0;

    for (int jt = 0;;) {
        int j0 = jt * AKT;
        if (jt + 1 < ntiles) fillKV((jt + 1) & 1, (jt + 1) * AKT);

        if (j0 <= rowbase + 15) {
            unsigned base = kvBase0 + (jt & 1) * AKV_STAGE_BYTES;
            unsigned kBaseH = base;
            unsigned kBaseL = base + AKV_WORDS * 4;
            unsigned vBaseH = base + 2 * AKV_WORDS * 4;
            unsigned vBaseL = base + 3 * AKV_WORDS * 4;

            float s[8][4];
            #pragma unroll
            for (int nf = 0; nf < 8; nf++)
                #pragma unroll
                for (int c = 0; c < 4; c++) s[nf][c] = 0.f;

            #pragma unroll
            for (int kt = 0; kt < 8; kt++) {
                unsigned qhf[4], qlf[4];
                unsigned qoff = (unsigned)((wid * 16 + l15) * (AST * 4) + (kt * 16 + lHi8) * 2);
                LDSM4(qhf[0], qhf[1], qhf[2], qhf[3], qBaseH + qoff);
                LDSM4(qlf[0], qlf[1], qlf[2], qlf[3], qBaseL + qoff);
                int kdd = kt * 16 + kDimOff;
                #pragma unroll
                for (int g2 = 0; g2 < 4; g2++) {
                    unsigned koff = (unsigned)((g2 * 16 + kKey) * (AST * 4) + kdd * 2);
                    unsigned kh0, kh1, kh2, kh3, klo0, klo1, klo2, klo3;
                    LDSM4(kh0, kh1, kh2, kh3, kBaseH + koff);
                    LDSM4(klo0, klo1, klo2, klo3, kBaseL + koff);
                    int n0 = 2 * g2, n1 = 2 * g2 + 1;
                    MMA_BF16(s[n0][0], s[n0][1], s[n0][2], s[n0][3],
                             qlf[0], qlf[1], qlf[2], qlf[3], kh0, kh1);
                    MMA_BF16(s[n0][0], s[n0][1], s[n0][2], s[n0][3],
                             qhf[0], qhf[1], qhf[2], qhf[3], klo0, klo1);
                    MMA_BF16(s[n0][0], s[n0][1], s[n0][2], s[n0][3],
                             qhf[0], qhf[1], qhf[2], qhf[3], kh0, kh1);
                    MMA_BF16(s[n1][0], s[n1][1], s[n1][2], s[n1][3],
                             qlf[0], qlf[1], qlf[2], qlf[3], kh2, kh3);
                    MMA_BF16(s[n1][0], s[n1][1], s[n1][2], s[n1][3],
                             qhf[0], qhf[1], qhf[2], qhf[3], klo2, klo3);
                    MMA_BF16(s[n1][0], s[n1][1], s[n1][2], s[n1][3],
                             qhf[0], qhf[1], qhf[2], qhf[3], kh2, kh3);
                }
            }

            int r0 = rowbase + gid, r1 = r0 + 8;
            if (j0 + AKT - 1 > rowbase) {
                #pragma unroll
                for (int nf = 0; nf < 8; nf++) {
                    int c0 = j0 + nf * 8 + 2 * tgid;
                    if (c0 > r0)     s[nf][0] = -1e30f;
                    if (c0 + 1 > r0) s[nf][1] = -1e30f;
                    if (c0 > r1)     s[nf][2] = -1e30f;
                    if (c0 + 1 > r1) s[nf][3] = -1e30f;
                }
            }

            float t0 = -1e30f, t1 = -1e30f;
            #pragma unroll
            for (int nf = 0; nf < 8; nf++) {
                t0 = fmaxf(t0, fmaxf(s[nf][0], s[nf][1]));
                t1 = fmaxf(t1, fmaxf(s[nf][2], s[nf][3]));
            }
            t0 = fmaxf(t0, __shfl_xor_sync(0xffffffffu, t0, 1));
            t0 = fmaxf(t0, __shfl_xor_sync(0xffffffffu, t0, 2));
            t1 = fmaxf(t1, __shfl_xor_sync(0xffffffffu, t1, 1));
            t1 = fmaxf(t1, __shfl_xor_sync(0xffffffffu, t1, 2));
            float mn0 = fmaxf(m0, t0), mn1 = fmaxf(m1, t1);
            float a0 = __expf(m0 - mn0), a1 = __expf(m1 - mn1);
            m0 = mn0; m1 = mn1;
            float rs0 = 0.f, rs1 = 0.f;
            #pragma unroll
            for (int nf = 0; nf < 8; nf++) {
                s[nf][0] = __expf(s[nf][0] - mn0);
                s[nf][1] = __expf(s[nf][1] - mn0);
                s[nf][2] = __expf(s[nf][2] - mn1);
                s[nf][3] = __expf(s[nf][3] - mn1);
                rs0 += s[nf][0] + s[nf][1];
                rs1 += s[nf][2] + s[nf][3];
            }
            rs0 += __shfl_xor_sync(0xffffffffu, rs0, 1);
            rs0 += __shfl_xor_sync(0xffffffffu, rs0, 2);
            rs1 += __shfl_xor_sync(0xffffffffu, rs1, 1);
            rs1 += __shfl_xor_sync(0xffffffffu, rs1, 2);
            l0r = l0r * a0 + rs0;
            l1r = l1r * a1 + rs1;
            #pragma unroll
            for (int nv = 0; nv < 16; nv++) {
                oacc[nv][0] *= a0; oacc[nv][1] *= a0;
                oacc[nv][2] *= a1; oacc[nv][3] *= a1;
            }

            #pragma unroll
            for (int t = 0; t < 4; t++) {
                unsigned ph[4], pl[4];
                split_pack(s[2 * t][0],     s[2 * t][1],     ph[0], pl[0]);
                split_pack(s[2 * t][2],     s[2 * t][3],     ph[1], pl[1]);
                split_pack(s[2 * t + 1][0], s[2 * t + 1][1], ph[2], pl[2]);
                split_pack(s[2 * t + 1][2], s[2 * t + 1][3], ph[3], pl[3]);
                unsigned vf[16][2];
                int krow = t * 16 + l15;
                #pragma unroll
                for (int np = 0; np < 8; np++) {
                    unsigned voff = (unsigned)(krow * (AST * 4) + (np * 16 + lHi8) * 2);
                    LDSM4T(vf[2 * np][0], vf[2 * np][1], vf[2 * np + 1][0], vf[2 * np + 1][1],
                           vBaseH + voff);
                }
                #pragma unroll
                for (int nv = 0; nv < 16; nv++) {
                    MMA_BF16(oacc[nv][0], oacc[nv][1], oacc[nv][2], oacc[nv][3],
                             pl[0], pl[1], pl[2], pl[3], vf[nv][0], vf[nv][1]);
                    MMA_BF16(oacc[nv][0], oacc[nv][1], oacc[nv][2], oacc[nv][3],
                             ph[0], ph[1], ph[2], ph[3], vf[nv][0], vf[nv][1]);
                }
                #pragma unroll
                for (int np = 0; np < 8; np++) {
                    unsigned voff = (unsigned)(krow * (AST * 4) + (np * 16 + lHi8) * 2);
                    LDSM4T(vf[2 * np][0], vf[2 * np][1], vf[2 * np + 1][0], vf[2 * np + 1][1],
                           vBaseL + voff);
                }
                #pragma unroll
                for (int nv = 0; nv < 16; nv++) {
                    MMA_BF16(oacc[nv][0], oacc[nv][1], oacc[nv][2], oacc[nv][3],
                             ph[0], ph[1], ph[2], ph[3], vf[nv][0], vf[nv][1]);
                }
            }
        }

        if (++jt == ntiles) break;
        CP_WAIT0();
        __syncthreads();
    }

    int r0 = rowbase + gid, r1 = r0 + 8;
    float il0 = 1.f / l0r, il1 = 1.f / l1r;
    #pragma unroll
    for (int nv = 0; nv < 16; nv++) {
        int col = nv * 8 + 2 * tgid;
        unsigned hw, lw;
        split_pack(oacc[nv][0] * il0, oacc[nv][1] * il0, hw, lw);
        size_t w0 = ((size_t)(b * SS + r0) * HQ + h) * 64 + col / 2;
        obh[w0] = hw; obl[w0] = lw;
        split_pack(oacc[nv][2] * il1, oacc[nv][3] * il1, hw, lw);
        size_t w1 = ((size_t)(b * SS + r1) * HQ + h) * 64 + col / 2;
        obh[w1] = hw; obl[w1] = lw;
    }
}

// ================= bf16x3 GEMM =================
#define BAST 20
#define BBST 68
#define GA_WORDS (128*BAST)
#define GB_WORDS (32*BBST)
#define GSTAGE_WORDS (2*GA_WORDS + 2*GB_WORDS)
#define GEMM_DSMEM (2*GSTAGE_WORDS*4)

__global__ void __launch_bounds__(256, 2)
bf16_gemm_kernel(const unsigned* __restrict__ AhG, const unsigned* __restrict__ AlG,
                 const unsigned* __restrict__ BhG, const unsigned* __restrict__ BlG,
                 float* __restrict__ C,
                 int M, int N, int K,
                 const int* __restrict__ aIdxg,
                 const int* __restrict__ cIdxg,
                 const int* __restrict__ cntg,
                 const float* __restrict__ combine,
                 size_t aZW, size_t bZW, int idxZ)
{
    extern __shared__ __align__(16) unsigned dsm[];
    int z = blockIdx.z;
    const unsigned* Ah = AhG + (size_t)z * aZW;
    const unsigned* Al = AlG + (size_t)z * aZW;
    const unsigned* Bh = BhG + (size_t)z * bZW;
    const unsigned* Bl = BlG + (size_t)z * bZW;
    const int* aIdx = aIdxg ? aIdxg + (size_t)z * idxZ : nullptr;
    const int* cIdx = cIdxg ? cIdxg + (size_t)z * idxZ : nullptr;
    int Meff = cntg ? min(M, cntg[z]) : M;
    int bm = blockIdx.y * 128;
    int bn = blockIdx.x * 128;
    if (bm >= Meff) return;
    int Kw = K >> 1, Nw = N >> 1, bnw = bn >> 1;

    int tid = threadIdx.x;
    int wid = tid >> 5, lane = tid & 31;
    int gid = lane >> 2, tgid = lane & 3;
    int wm = (wid & 3) * 32;
    int wn = (wid >> 2) * 64;
    int l15 = lane & 15, lHi8 = (lane >> 4) << 3;

    int am = tid >> 1, ac = (tid & 1) * 2;
    int gr = bm + am;
    int ar = (gr < Meff) ? (aIdx ? aIdx[gr] : gr) : 0;
    int aValid = (gr < Meff) ? 16 : 0;
    const unsigned* aRowH = Ah + (size_t)ar * Kw;
    const unsigned* aRowL = Al + (size_t)ar * Kw;
    int bk = tid >> 3, bc = (2 * tid) & 15;

    unsigned smemBase = (unsigned)__cvta_generic_to_shared(dsm);

    auto fillStage = [&](int st, int k0) {
        int kw0 = k0 >> 1;
        unsigned base = smemBase + st * (GSTAGE_WORDS * 4);
        unsigned aHb = base, aLb = base + GA_WORDS * 4;
        unsigned bHb = aLb + GA_WORDS * 4, bLb = bHb + GB_WORDS * 4;
        #pragma unroll
        for (int c2 = 0; c2 < 2; c2++) {
            int c = ac + c2;
            unsigned d = (am * BAST + c * 4) * 4;
            cp16(aHb + d, aRowH + kw0 + c * 4, aValid);
            cp16(aLb + d, aRowL + kw0 + c * 4, aValid);
        }
        size_t bro = (size_t)(k0 + bk) * Nw + bnw;
        #pragma unroll
        for (int c2 = 0; c2 < 2; c2++) {
            int c = bc + c2;
            unsigned d = (bk * BBST + c * 4) * 4;
            cp16(bHb + d, Bh + bro + c * 4, 16);
            cp16(bLb + d, Bl + bro + c * 4, 16);
        }
        CP_COMMIT();
    };

    float acc[2][8][4];
    #pragma unroll
    for (int i = 0; i < 2; i++)
        #pragma unroll
        for (int j = 0; j < 8; j++)
            #pragma unroll
            for (int c = 0; c < 4; c++) acc[i][j][c] = 0.f;

    int KT = K >> 5;
    fillStage(0, 0);
    CP_WAIT0();
    __syncthreads();

    for (int kt = 0;;) {
        if (kt + 1 < KT) fillStage((kt + 1) & 1, (kt + 1) << 5);

        unsigned base = smemBase + (kt & 1) * (GSTAGE_WORDS * 4);
        unsigned aBaseH = base, aBaseL = base + GA_WORDS * 4;
        unsigned bBaseH = aBaseL + GA_WORDS * 4, bBaseL = bBaseH + GB_WORDS * 4;

        #pragma unroll
        for (int ks = 0; ks < 2; ks++) {
            int kk = ks * 16;
            unsigned ah[2][4], al[2][4];
            #pragma unroll
            for (int mf = 0; mf < 2; mf++) {
                int mrow = wm + mf * 16 + l15;
                unsigned off = (unsigned)(mrow * (BAST * 4) + (kk + lHi8) * 2);
                LDSM4(ah[mf][0], ah[mf][1], ah[mf][2], ah[mf][3], aBaseH + off);
                LDSM4(al[mf][0], al[mf][1], al[mf][2], al[mf][3], aBaseL + off);
            }
            unsigned bfr[8][2];
            int krow = kk + l15;
            #pragma unroll
            for (int nfp = 0; nfp < 4; nfp++) {
                int ncol = wn + nfp * 16 + lHi8;
                unsigned off = (unsigned)(krow * (BBST * 4) + ncol * 2);
                LDSM4T(bfr[2 * nfp][0], bfr[2 * nfp][1],
                       bfr[2 * nfp + 1][0], bfr[2 * nfp + 1][1], bBaseH + off);
            }
            #pragma unroll
            for (int mf = 0; mf < 2; mf++)
                #pragma unroll
                for (int nf = 0; nf < 8; nf++) {
                    MMA_BF16(acc[mf][nf][0], acc[mf][nf][1], acc[mf][nf][2], acc[mf][nf][3],
                             ah[mf][0], ah[mf][1], ah[mf][2], ah[mf][3],
                             bfr[nf][0], bfr[nf][1]);
                    MMA_BF16(acc[mf][nf][0], acc[mf][nf][1], acc[mf][nf][2], acc[mf][nf][3],
                             al[mf][0], al[mf][1], al[mf][2], al[mf][3],
                             bfr[nf][0], bfr[nf][1]);
                }
            #pragma unroll
            for (int nfp = 0; nfp < 4; nfp++) {
                int ncol = wn + nfp * 16 + lHi8;
                unsigned off = (unsigned)(krow * (BBST * 4) + ncol * 2);
                LDSM4T(bfr[2 * nfp][0], bfr[2 * nfp][1],
                       bfr[2 * nfp + 1][0], bfr[2 * nfp + 1][1], bBaseL + off);
            }
            #pragma unroll
            for (int mf = 0; mf < 2; mf++)
                #pragma unroll
                for (int nf = 0; nf < 8; nf++) {
                    MMA_BF16(acc[mf][nf][0], acc[mf][nf][1], acc[mf][nf][2], acc[mf][nf][3],
                             ah[mf][0], ah[mf][1], ah[mf][2], ah[mf][3],
                             bfr[nf][0], bfr[nf][1]);
                }
        }

        if (++kt == KT) break;
        CP_WAIT0();
        __syncthreads();
    }

    #pragma unroll
    for (int mf = 0; mf < 2; mf++) {
        #pragma unroll
        for (int half = 0; half < 2; half++) {
            int row = bm + wm + mf * 16 + gid + half * 8;
            if (row >= Meff) continue;
            int crow = cIdx ? cIdx[row] : row;
            float w = 1.f;
            if (combine) w = combine[crow * EE + z];
            #pragma unroll
            for (int nf = 0; nf < 8; nf++) {
                int col = bn + wn + nf * 8 + 2 * tgid;
                float v0 = acc[mf][nf][half * 2 + 0];
                float v1 = acc[mf][nf][half * 2 + 1];
                float* cp = C + (size_t)crow * N + col;
                if (combine) {
                    atomicAdd(cp, w * v0);
                    atomicAdd(cp + 1, w * v1);
                } else {
                    cp[0] = v0;
                    cp[1] = v1;
                }
            }
        }
    }
}

// ========== gated dual-B bf16x3 GEMM ==========
__global__ void __launch_bounds__(256, 2)
bf16_gated_kernel(const unsigned* __restrict__ Ah, const unsigned* __restrict__ Al,
                  const unsigned* __restrict__ B0hG, const unsigned* __restrict__ B0lG,
                  const unsigned* __restrict__ B1hG, const unsigned* __restrict__ B1lG,
                  unsigned* __restrict__ ChG, unsigned* __restrict__ ClG,
                  int M, int Nout, int K,
                  const int* __restrict__ aIdxg,
                  const int* __restrict__ cntg,
                  size_t bZW, size_t cZW, int idxZ)
{
    extern __shared__ __align__(16) unsigned dsm[];
    int z = blockIdx.z;
    const unsigned* B0h = B0hG + (size_t)z * bZW;
    const unsigned* B0l = B0lG + (size_t)z * bZW;
    const unsigned* B1h = B1hG + (size_t)z * bZW;
    const unsigned* B1l = B1lG + (size_t)z * bZW;
    unsigned* Ch = ChG + (size_t)z * cZW;
    unsigned* Cl = ClG + (size_t)z * cZW;
    const int* aIdx = aIdxg ? aIdxg + (size_t)z * idxZ : nullptr;
    int Meff = cntg ? min(M, cntg[z]) : M;
    int bm = blockIdx.y * 128;
    int bnn = blockIdx.x * 64;
    if (bm >= Meff) return;
    int Kw = K >> 1, Nw = Nout >> 1, bnw = bnn >> 1;

    int tid = threadIdx.x;
    int wid = tid >> 5, lane = tid & 31;
    int gid = lane >> 2, tgid = lane & 3;
    int wm = (wid & 3) * 32;
    int wn32 = (wid >> 2) * 32;
    int l15 = lane & 15, lHi8 = (lane >> 4) << 3;

    int am = tid >> 1, ac = (tid & 1) * 2;
    int gr = bm + am;
    int ar = (gr < Meff) ? (aIdx ? aIdx[gr] : gr) : 0;
    int aValid = (gr < Meff) ? 16 : 0;
    const unsigned* aRowH = Ah + (size_t)ar * Kw;
    const unsigned* aRowL = Al + (size_t)ar * Kw;
    int bk = tid >> 3;
    int brest = (2 * tid) & 15;

    unsigned smemBase = (unsigned)__cvta_generic_to_shared(dsm);

    auto fillStage = [&](int st, int k0) {
        int kw0 = k0 >> 1;
        unsigned base = smemBase + st * (GSTAGE_WORDS * 4);
        unsigned aHb = base, aLb = base + GA_WORDS * 4;
        unsigned bHb = aLb + GA_WORDS * 4, bLb = bHb + GB_WORDS * 4;
        #pragma unroll
        for (int c2 = 0; c2 < 2; c2++) {
            int c = ac + c2;
            unsigned d = (am * BAST + c * 4) * 4;
            cp16(aHb + d, aRowH + kw0 + c * 4, aValid);
            cp16(aLb + d, aRowL + kw0 + c * 4, aValid);
        }
        size_t bro = (size_t)(k0 + bk) * Nw + bnw;
        #pragma unroll
        for (int c2 = 0; c2 < 2; c2++) {
            int cc = brest + c2;
            int srcSel = cc >> 3, c = cc & 7;
            unsigned d = (bk * BBST + srcSel * 32 + c * 4) * 4;
            cp16(bHb + d, (srcSel ? B1h : B0h) + bro + c * 4, 16);
            cp16(bLb + d, (srcSel ? B1l : B0l) + bro + c * 4, 16);
        }
        CP_COMMIT();
    };

    float acc0[2][4][4], acc1[2][4][4];
    #pragma unroll
    for (int i = 0; i < 2; i++)
        #pragma unroll
        for (int j = 0; j < 4; j++)
            #pragma unroll
            for (int c = 0; c < 4; c++) { acc0[i][j][c] = 0.f; acc1[i][j][c] = 0.f; }

    int KT = K >> 5;
    fillStage(0, 0);
    CP_WAIT0();
    __syncthreads();

    for (int kt = 0;;) {
        if (kt + 1 < KT) fillStage((kt + 1) & 1, (kt + 1) << 5);

        unsigned base = smemBase + (kt & 1) * (GSTAGE_WORDS * 4);
        unsigned aBaseH = base, aBaseL = base + GA_WORDS * 4;
        unsigned bBaseH = aBaseL + GA_WORDS * 4, bBaseL = bBaseH + GB_WORDS * 4;

        #pragma unroll
        for (int ks = 0; ks < 2; ks++) {
            int kk = ks * 16;
            unsigned ah[2][4], al[2][4];
            #pragma unroll
            for (int mf = 0; mf < 2; mf++) {
                int mrow = wm + mf * 16 + l15;
                unsigned off = (unsigned)(mrow * (BAST * 4) + (kk + lHi8) * 2);
                LDSM4(ah[mf][0], ah[mf][1], ah[mf][2], ah[mf][3], aBaseH + off);
                LDSM4(al[mf][0], al[mf][1], al[mf][2], al[mf][3], aBaseL + off);
            }
            int krow = kk + l15;
            #pragma unroll
            for (int which = 0; which < 2; which++) {
                unsigned bfr[4][2];
                int colbase = which * 64 + wn32;
                #pragma unroll
                for (int nfp = 0; nfp < 2; nfp++) {
                    int ncol = colbase + nfp * 16 + lHi8;
                    unsigned off = (unsigned)(krow * (BBST * 4) + ncol * 2);
                    LDSM4T(bfr[2 * nfp][0], bfr[2 * nfp][1],
                           bfr[2 * nfp + 1][0], bfr[2 * nfp + 1][1], bBaseH + off);
                }
                #pragma unroll
                for (int mf = 0; mf < 2; mf++)
                    #pragma unroll
                    for (int nf = 0; nf < 4; nf++) {
                        float* a = which ? acc1[mf][nf] : acc0[mf][nf];
                        MMA_BF16(a[0], a[1], a[2], a[3],
                                 ah[mf][0], ah[mf][1], ah[mf][2], ah[mf][3],
                                 bfr[nf][0], bfr[nf][1]);
                        MMA_BF16(a[0], a[1], a[2], a[3],
                                 al[mf][0], al[mf][1], al[mf][2], al[mf][3],
                                 bfr[nf][0], bfr[nf][1]);
                    }
                #pragma unroll
                for (int nfp = 0; nfp < 2; nfp++) {
                    int ncol = colbase + nfp * 16 + lHi8;
                    unsigned off = (unsigned)(krow * (BBST * 4) + ncol * 2);
                    LDSM4T(bfr[2 * nfp][0], bfr[2 * nfp][1],
                           bfr[2 * nfp + 1][0], bfr[2 * nfp + 1][1], bBaseL + off);
                }
                #pragma unroll
                for (int mf = 0; mf < 2; mf++)
                    #pragma unroll
                    for (int nf = 0; nf < 4; nf++) {
                        float* a = which ? acc1[mf][nf] : acc0[mf][nf];
                        MMA_BF16(a[0], a[1], a[2], a[3],
                                 ah[mf][0], ah[mf][1], ah[mf][2], ah[mf][3],
                                 bfr[nf][0], bfr[nf][1]);
                    }
            }
        }

        if (++kt == KT) break;
        CP_WAIT0();
        __syncthreads();
    }

    #pragma unroll
    for (int mf = 0; mf < 2; mf++) {
        #pragma unroll
        for (int half = 0; half < 2; half++) {
            int row = bm + wm + mf * 16 + gid + half * 8;
            if (row >= Meff) continue;
            #pragma unroll
            for (int nf = 0; nf < 4; nf++) {
                int col = bnn + wn32 + nf * 8 + 2 * tgid;
                float g0v = gelu_tanh(acc0[mf][nf][half * 2 + 0]) * acc1[mf][nf][half * 2 + 0];
                float g1v = gelu_tanh(acc0[mf][nf][half * 2 + 1]) * acc1[mf][nf][half * 2 + 1];
                unsigned hw, lw;
                split_pack(g0v, g1v, hw, lw);
                size_t w = (size_t)row * Nw + (col >> 1);
                Ch[w] = hw; Cl[w] = lw;
            }
        }
    }
}

// ---------------- router ----------------
__global__ void router_kernel(const float* __restrict__ gin,
                              const float* __restrict__ wg,
                              float* __restrict__ combine,
                              int* __restrict__ cnt,
                              int* __restrict__ idx,
                              float* __restrict__ psum)
{
    int tok = blockIdx.x;
    int tid = threadIdx.x;
    float s[EE] = {};
    const float* g = gin + (size_t)tok * DD;
    for (int d = tid; d < DD; d += 256) {
        float gv = g[d];
        const float* w = wg + d * EE;
        #pragma unroll
        for (int e = 0; e < EE; e++) s[e] += gv * w[e];
    }
    __shared__ float sh[256][EE];
    #pragma unroll
    for (int e = 0; e < EE; e++) sh[tid][e] = s[e];
    __syncthreads();
    for (int str = 128; str > 0; str >>= 1) {
        if (tid < str) {
            #pragma unroll
            for (int e = 0; e < EE; e++) sh[tid][e] += sh[tid + str][e];
        }
        __syncthreads();
    }
    if (tid == 0) {
        float pe[EE];
        float mx = -FLT_MAX;
        #pragma unroll
        for (int e = 0; e < EE; e++) mx = fmaxf(mx, sh[0][e]);
        float sum = 0.f;
        #pragma unroll
        for (int e = 0; e < EE; e++) { pe[e] = expf(sh[0][e] - mx); sum += pe[e]; }
        float inv = 1.0f / sum;
        #pragma unroll
        for (int e = 0; e < EE; e++) { pe[e] *= inv; atomicAdd(&psum[e], pe[e]); }
        int i0 = 0;
        #pragma unroll
        for (int e = 1; e < EE; e++) if (pe[e] > pe[i0]) i0 = e;
        int i1 = (i0 == 0) ? 1 : 0;
        #pragma unroll
        for (int e = 0; e < EE; e++) if (e != i0 && e != i1 && pe[e] > pe[i1]) i1 = e;
        float tot = pe[i0] + pe[i1];
        float w0 = pe[i0] / tot, w1 = pe[i1] / tot;
        float* crow = combine + (size_t)tok * EE;
        #pragma unroll
        for (int e = 0; e < EE; e++) crow[e] = 0.f;
        crow[i0] = w0; crow[i1] = w1;
        int p0 = atomicAdd(&cnt[i0], 1); idx[i0 * TT + p0] = tok;
        int p1 = atomicAdd(&cnt[i1], 1); idx[i1 * TT + p1] = tok;
    }
}

__global__ void lb_kernel(const int* __restrict__ cnt, const float* __restrict__ psum,
                          float* __restrict__ out)
{
    float lb = 0.f;
    #pragma unroll
    for (int e = 0; e < EE; e++)
        lb += ((float)cnt[e] / (float)TT) * (psum[e] / (float)TT);
    out[0] = lb * ((float)(EE * EE) / (float)EE);
}

// ==================== host launcher ====================
extern "C" void kernel_launch(void* const* d_in, const int* in_sizes, int n_in,
                              void* d_out, int out_size)
{
    const int*   positions       = (const int*)  d_in[0];
    const float* x               = (const float*)d_in[1];
    const float* pre_attn_scale  = (const float*)d_in[2];
    const float* wq              = (const float*)d_in[3];
    const float* wk              = (const float*)d_in[4];
    const float* wv              = (const float*)d_in[5];
    const float* wo              = (const float*)d_in[6];
    const float* q_norm_scale    = (const float*)d_in[7];
    const float* k_norm_scale    = (const float*)d_in[8];
    const float* v_norm_scale    = (const float*)d_in[9];
    const float* post_attn_scale = (const float*)d_in[10];
    const float* pre_ffw_scale   = (const float*)d_in[11];
    const float* shared_wi0      = (const float*)d_in[12];
    const float* shared_wi1      = (const float*)d_in[13];
    const float* shared_wo       = (const float*)d_in[14];
    const float* post_ff1_scale  = (const float*)d_in[15];
    const float* pre_ff2_scale   = (const float*)d_in[16];
    const float* router_scale    = (const float*)d_in[17];
    const float* w_gate          = (const float*)d_in[18];
    const float* ewi0            = (const float*)d_in[19];
    const float* ewi1            = (const float*)d_in[20];
    const float* ewo             = (const float*)d_in[21];
    const float* post_ff2_scale  = (const float*)d_in[22];
    const float* layer_scalar    = (const float*)d_in[23];
    float* out = (float*)d_out;

    static int smemConfigured = 0;
    if (!smemConfigured) {
        cudaFuncSetAttribute(fattn_kernel,
                             cudaFuncAttributeMaxDynamicSharedMemorySize, ATT_SMEM_BYTES);
        cudaFuncSetAttribute(bf16_gemm_kernel,
                             cudaFuncAttributeMaxDynamicSharedMemorySize, GEMM_DSMEM);
        cudaFuncSetAttribute(bf16_gated_kernel,
                             cudaFuncAttributeMaxDynamicSharedMemorySize, GEMM_DSMEM);
        smemConfigured = 1;
    }

    float* sc = nullptr;
    int*   isc = nullptr;
    cudaGetSymbolAddress((void**)&sc, g_scratch);
    cudaGetSymbolAddress((void**)&isc, g_iscratch);

    unsigned* U = (unsigned*)sc;
    auto uptr = [&](size_t off) { return U + off; };

    unsigned* lnxH = uptr(OFF_LNXH); unsigned* lnxL = uptr(OFF_LNXL);
    float* qkvf = sc + OFF_QKVF;
    unsigned* qsh = uptr(OFF_QH); unsigned* qsl = uptr(OFF_QL);
    unsigned* ksh = uptr(OFF_KH); unsigned* ksl = uptr(OFF_KL);
    unsigned* vsh = uptr(OFF_VH); unsigned* vsl = uptr(OFF_VL);
    unsigned* obh = uptr(OFF_OBH); unsigned* obl = uptr(OFF_OBL);
    float* attnb = sc + OFF_ATTN; float* hb = sc + OFF_H;
    unsigned* ffinH = uptr(OFF_FFINH); unsigned* ffinL = uptr(OFF_FFINL);
    unsigned* g0H = uptr(OFF_G0H); unsigned* g0L = uptr(OFF_G0L);
    float* shb = sc + OFF_SHB;
    unsigned* rinH = uptr(OFF_RINH); unsigned* rinL = uptr(OFF_RINL);
    float* gin = sc + OFF_GIN; float* routb = sc + OFF_ROUT;
    unsigned* egH = uptr(OFF_EGH); unsigned* egL = uptr(OFF_EGL);
    float* comb = sc + OFF_COMB; float* psum = sc + OFF_PSUM;
    int* idx = isc; int* cnt = isc + EE * TT;

    auto splitBF = [&](const float* src, size_t nElts, size_t offH, size_t offL) {
        size_t nW = nElts / 2;
        split_bf_kernel<<<(unsigned)((nW + 255) / 256), 256>>>(
            (const float2*)src, uptr(offH), uptr(offL), nW);
    };

    // weight pre-split
    split_qkv_kernel<<<(unsigned)(SZ_WQKV / 2 / 256), 256>>>(
        wq, wk, wv, uptr(OFF_WQKVH), uptr(OFF_WQKVL));
    splitBF(wo, SZ_WQ, OFF_WOH, OFF_WOL);
    splitBF(shared_wi0, SZ_WFF, OFF_WI0H, OFF_WI0L);
    splitBF(shared_wi1, SZ_WFF, OFF_WI1H, OFF_WI1L);
    splitBF(shared_wo, SZ_WFF, OFF_SWOH, OFF_SWOL);
    splitBF(ewi0, SZ_EW, OFF_EWI0H, OFF_EWI0L);
    splitBF(ewi1, SZ_EW, OFF_EWI1H, OFF_EWI1L);
    splitBF(ewo, SZ_EW, OFF_EWOH, OFF_EWOL);

    auto gemm = [&](const unsigned* Ah, const unsigned* Al,
                    size_t BhOff, size_t BlOff, float* C, int M, int N, int K,
                    const int* aI, const int* cI, const int* ct, const float* cw,
                    size_t aZW, size_t bZW, int nz) {
        dim3 grid(N / 128, (M + 127) / 128, nz);
        bf16_gemm_kernel<<<grid, 256, GEMM_DSMEM>>>(Ah, Al, uptr(BhOff), uptr(BlOff),
                                                    C, M, N, K, aI, cI, ct, cw,
                                                    aZW, bZW, TT);
    };

    // 1) pre-attn norm
    rms_kernel<<<TT, 256>>>(x, pre_attn_scale, 1.f, nullptr, nullptr, nullptr,
                            nullptr, lnxH, lnxL);
    // 2) fused QKV projection
    gemm(lnxH, lnxL, OFF_WQKVH, OFF_WQKVL, qkvf, TT, NQKV, DD,
         nullptr, nullptr, nullptr, nullptr, 0, 0, 1);
    // 3) per-head norms + rope
    head_norm_rope_kernel<<<TT * HQ, HD>>>(qkvf, NQKV, 0, qsh, qsl,
                                           q_norm_scale, positions, HQ, 1);
    head_norm_rope_kernel<<<TT * HKV, HD>>>(qkvf, NQKV, 2048, ksh, ksl,
                                            k_norm_scale, positions, HKV, 1);
    head_norm_rope_kernel<<<TT * HKV, HD>>>(qkvf, NQKV, 3072, vsh, vsl,
                                            v_norm_scale, positions, HKV, 0);
    // 4) attention (heavy-first scheduling)
    {
        dim3 grid(SS / ATQ, HQ, BB);
        fattn_kernel<<<grid, 256, ATT_SMEM_BYTES>>>(qsh, qsl, ksh, ksl, vsh, vsl, obh, obl);
    }
    // 5) output projection + post-attn norm + residual
    gemm(obh, obl, OFF_WOH, OFF_WOL, attnb, TT, DD, HQ * HD,
         nullptr, nullptr, nullptr, nullptr, 0, 0, 1);
    rms_kernel<<<TT, 256>>>(attnb, post_attn_scale, 1.f, x, nullptr, nullptr,
                            hb, nullptr, nullptr);
    // 6) shared FFN
    rms_kernel<<<TT, 256>>>(hb, pre_ffw_scale, 1.f, nullptr, nullptr, nullptr,
                            nullptr, ffinH, ffinL);
    {
        dim3 grid(FS / 64, TT / 128, 1);
        bf16_gated_kernel<<<grid, 256, GEMM_DSMEM>>>(
            ffinH, ffinL, uptr(OFF_WI0H), uptr(OFF_WI0L), uptr(OFF_WI1H), uptr(OFF_WI1L),
            g0H, g0L, TT, FS, DD, nullptr, nullptr, 0, 0, TT);
    }
    gemm(g0H, g0L, OFF_SWOH, OFF_SWOL, shb, TT, DD, FS,
         nullptr, nullptr, nullptr, nullptr, 0, 0, 1);
    rms_kernel<<<TT, 256>>>(shb, post_ff1_scale, 1.f, nullptr, nullptr, nullptr,
                            shb, nullptr, nullptr);
    // 7) router inputs (fused dual RMS over h)
    rms_dual_kernel<<<TT, 256>>>(hb, pre_ff2_scale, rinH, rinL,
                                 router_scale, 0.02209708691207961f, gin);
    // 8) router + batched MoE
    cudaMemsetAsync(cnt, 0, EE * sizeof(int));
    cudaMemsetAsync(psum, 0, EE * sizeof(float));
    cudaMemsetAsync(routb, 0, SZ_TD * sizeof(float));
    router_kernel<<<TT, 256>>>(gin, w_gate, comb, cnt, idx, psum);
    {
        dim3 grid(FE / 64, TT / 128, EE);
        bf16_gated_kernel<<<grid, 256, GEMM_DSMEM>>>(
            rinH, rinL, uptr(OFF_EWI0H), uptr(OFF_EWI0L), uptr(OFF_EWI1H), uptr(OFF_EWI1L),
            egH, egL, TT, FE, DD, idx, cnt,
            (size_t)DD * FE / 2, (size_t)TT * FE / 2, TT);
    }
    {
        dim3 grid(DD / 128, TT / 128, EE);
        bf16_gemm_kernel<<<grid, 256, GEMM_DSMEM>>>(
            egH, egL, uptr(OFF_EWOH), uptr(OFF_EWOL), routb, TT, DD, FE,
            nullptr, idx, cnt, comb,
            (size_t)TT * FE / 2, (size_t)FE * DD / 2, TT);
    }
    // 9) final combine
    rms_kernel<<<TT, 256>>>(routb, post_ff2_scale, 1.f, shb, hb, layer_scalar,
                            out, nullptr, nullptr);
    // 10) lb loss
    if (out_size > TT * DD) {
        lb_kernel<<<1, 1>>>(cnt, psum, out + (size_t)TT * DD);
    }
}

// round 14
// speedup vs baseline: 1.0272x; 1.0061x over previous
#include <cuda_runtime.h>
#include <cuda_bf16.h>
#include <cfloat>
#include <math.h>

#define BB 4
#define SS 1024
#define DD 2048
#define HQ 16
#define HKV 8
#define HD 128
#define GRP 2
#define EE 8
#define FE 1024
#define FS 8192
#define TT (BB*SS)
#define EPS 1e-6f
#define NQKV 4096

#define SZ_TD   ((size_t)TT*DD)
#define SZ_TQ   ((size_t)TT*HQ*HD)
#define SZ_TKV  ((size_t)TT*HKV*HD)
#define SZ_TFS  ((size_t)TT*FS)

#define OFF_LNXH  ((size_t)0)
#define OFF_LNXL  (OFF_LNXH + SZ_TD/2)
#define OFF_QKVF  (OFF_LNXL + SZ_TD/2)
#define OFF_QH    (OFF_QKVF + (size_t)TT*NQKV)
#define OFF_QL    (OFF_QH   + SZ_TQ/2)
#define OFF_KH    (OFF_QL   + SZ_TQ/2)
#define OFF_KL    (OFF_KH   + SZ_TKV/2)
#define OFF_VH    (OFF_KL   + SZ_TKV/2)
#define OFF_VL    (OFF_VH   + SZ_TKV/2)
#define OFF_OBH   (OFF_VL   + SZ_TKV/2)
#define OFF_OBL   (OFF_OBH  + SZ_TQ/2)
#define OFF_ATTN  (OFF_OBL  + SZ_TQ/2)
#define OFF_H     (OFF_ATTN + SZ_TD)
#define OFF_FFINH (OFF_H    + SZ_TD)
#define OFF_FFINL (OFF_FFINH+ SZ_TD/2)
#define OFF_G0H   (OFF_FFINL+ SZ_TD/2)
#define OFF_G0L   (OFF_G0H  + SZ_TFS/2)
#define OFF_SHB   (OFF_G0L  + SZ_TFS/2)
#define OFF_RINH  (OFF_SHB  + SZ_TD)
#define OFF_RINL  (OFF_RINH + SZ_TD/2)
#define OFF_GIN   (OFF_RINL + SZ_TD/2)
#define OFF_ROUT  (OFF_GIN  + SZ_TD)
#define OFF_EGH   (OFF_ROUT + SZ_TD)
#define OFF_EGL   (OFF_EGH  + SZ_TFS/2)
#define OFF_COMB  (OFF_EGL  + SZ_TFS/2)
#define OFF_PSUM  (OFF_COMB + (size_t)TT*EE)
#define SZ_WQKV ((size_t)DD*NQKV)
#define SZ_WQ  ((size_t)DD*HQ*HD)
#define SZ_WFF ((size_t)DD*FS)
#define SZ_EW  ((size_t)EE*DD*FE)
#define OFF_WQKVH (OFF_PSUM + 8)
#define OFF_WQKVL (OFF_WQKVH + SZ_WQKV/2)
#define OFF_WOH   (OFF_WQKVL + SZ_WQKV/2)
#define OFF_WOL   (OFF_WOH + SZ_WQ/2)
#define OFF_WI0H  (OFF_WOL + SZ_WQ/2)
#define OFF_WI0L  (OFF_WI0H + SZ_WFF/2)
#define OFF_WI1H  (OFF_WI0L + SZ_WFF/2)
#define OFF_WI1L  (OFF_WI1H + SZ_WFF/2)
#define OFF_SWOH  (OFF_WI1L + SZ_WFF/2)
#define OFF_SWOL  (OFF_SWOH + SZ_WFF/2)
#define OFF_EWI0H (OFF_SWOL + SZ_WFF/2)
#define OFF_EWI0L (OFF_EWI0H + SZ_EW/2)
#define OFF_EWI1H (OFF_EWI0L + SZ_EW/2)
#define OFF_EWI1L (OFF_EWI1H + SZ_EW/2)
#define OFF_EWOH  (OFF_EWI1L + SZ_EW/2)
#define OFF_EWOL  (OFF_EWOH + SZ_EW/2)
#define SCRATCH_TOTAL (OFF_EWOL + SZ_EW/2)

__device__ float g_scratch[SCRATCH_TOTAL];
__device__ int   g_iscratch[EE*TT + EE];

__device__ __forceinline__ float gelu_tanh(float v) {
    const float c = 0.7978845608028654f;
    float u = c * (v + 0.044715f * v * v * v);
    return 0.5f * v * (1.0f + tanhf(u));
}
__device__ __forceinline__ unsigned pack_bf16(float x, float y) {
    __nv_bfloat162 t = __floats2bfloat162_rn(x, y);
    return *reinterpret_cast<unsigned*>(&t);
}
__device__ __forceinline__ void split_pack(float x, float y,
                                           unsigned &hiW, unsigned &loW0) {
    __nv_bfloat16 bx = __float2bfloat16_rn(x);
    __nv_bfloat16 by = __float2bfloat16_rn(y);
    float hx = __bfloat162float(bx);
    float hy = __bfloat162float(by);
    __nv_bfloat162 h2; h2.x = bx; h2.y = by;
    hiW = *reinterpret_cast<unsigned*>(&h2);
    loW0 = pack_bf16(x - hx, y - hy);
}
__device__ __forceinline__ void cp16(unsigned dst, const void* src, int srcBytes) {
    asm volatile("cp.async.cg.shared.global [%0], [%1], 16, %2;"
                 :: "r"(dst), "l"(src), "r"(srcBytes));
}
#define CP_COMMIT() asm volatile("cp.async.commit_group;")
#define CP_WAIT0()  asm volatile("cp.async.wait_group 0;")

#define LDSM4(r0,r1,r2,r3,addr) \
    asm volatile("ldmatrix.sync.aligned.m8n8.x4.shared.b16 {%0,%1,%2,%3}, [%4];" \
                 : "=r"(r0),"=r"(r1),"=r"(r2),"=r"(r3) : "r"(addr))
#define LDSM4T(r0,r1,r2,r3,addr) \
    asm volatile("ldmatrix.sync.aligned.m8n8.x4.trans.shared.b16 {%0,%1,%2,%3}, [%4];" \
                 : "=r"(r0),"=r"(r1),"=r"(r2),"=r"(r3) : "r"(addr))
#define MMA_BF16(d0,d1,d2,d3,a0,a1,a2,a3,b0,b1) \
    asm volatile("mma.sync.aligned.m16n8k16.row.col.f32.bf16.bf16.f32 " \
                 "{%0,%1,%2,%3}, {%4,%5,%6,%7}, {%8,%9}, {%0,%1,%2,%3};" \
                 : "+f"(d0),"+f"(d1),"+f"(d2),"+f"(d3) \
                 : "r"(a0),"r"(a1),"r"(a2),"r"(a3),"r"(b0),"r"(b1))

// ---------------- splits (vectorized: float4 in, uint2 per plane out) -----
__global__ void split_bf_kernel(const float4* __restrict__ in,
                                uint2* __restrict__ hi,
                                uint2* __restrict__ lo, size_t nQuads)
{
    size_t i = (size_t)blockIdx.x * 256 + threadIdx.x;
    if (i < nQuads) {
        float4 v = in[i];
        uint2 h, l;
        split_pack(v.x, v.y, h.x, l.x);
        split_pack(v.z, v.w, h.y, l.y);
        hi[i] = h; lo[i] = l;
    }
}
__global__ void split_qkv_kernel(const float* __restrict__ wq,
                                 const float* __restrict__ wk,
                                 const float* __restrict__ wv,
                                 uint2* __restrict__ hi,
                                 uint2* __restrict__ lo)
{
    size_t q = (size_t)blockIdx.x * 256 + threadIdx.x;     // quad index
    if (q >= (size_t)DD * (NQKV / 4)) return;
    int d = (int)(q / (NQKV / 4));
    int n0 = 4 * (int)(q % (NQKV / 4));
    float4 v;
    if (n0 < 2048)      v = *(const float4*)(wq + (size_t)d * 2048 + n0);
    else if (n0 < 3072) v = *(const float4*)(wk + (size_t)d * 1024 + (n0 - 2048));
    else                v = *(const float4*)(wv + (size_t)d * 1024 + (n0 - 3072));
    uint2 h, l;
    split_pack(v.x, v.y, h.x, l.x);
    split_pack(v.z, v.w, h.y, l.y);
    hi[q] = h; lo[q] = l;
}

// ---------------- RMS norm (single output) ----------------
__global__ void rms_kernel(const float* __restrict__ in,
                           const float* __restrict__ scale, float cmul,
                           const float* __restrict__ res1,
                           const float* __restrict__ res2,
                           const float* __restrict__ scalarPtr,
                           float* __restrict__ out,
                           unsigned* __restrict__ outH,
                           unsigned* __restrict__ outL)
{
    int row = blockIdx.x;
    int tid = threadIdx.x;
    const float* xr = in + (size_t)row * DD;
    float ss = 0.f;
    for (int d = tid; d < DD; d += 256) { float v = xr[d]; ss += v * v; }
    for (int o = 16; o > 0; o >>= 1) ss += __shfl_xor_sync(0xffffffffu, ss, o);
    __shared__ float wsum[8];
    if ((tid & 31) == 0) wsum[tid >> 5] = ss;
    __syncthreads();
    float tot = 0.f;
    #pragma unroll
    for (int w = 0; w < 8; w++) tot += wsum[w];
    float inv = rsqrtf(tot * (1.0f / DD) + EPS);
    float sc = scalarPtr ? *scalarPtr : 1.0f;
    if (outH) {
        for (int d = 2 * tid; d < DD; d += 512) {
            float y0 = xr[d] * inv, y1 = xr[d + 1] * inv;
            if (scale) { y0 *= scale[d]; y1 *= scale[d + 1]; }
            y0 *= cmul; y1 *= cmul;
            unsigned h, l;
            split_pack(y0, y1, h, l);
            size_t w = (size_t)row * (DD / 2) + d / 2;
            outH[w] = h; outL[w] = l;
        }
    } else {
        for (int d = tid; d < DD; d += 256) {
            float y = xr[d] * inv;
            if (scale) y *= scale[d];
            y *= cmul;
            if (res1) y += res1[(size_t)row * DD + d];
            if (res2) y += res2[(size_t)row * DD + d];
            out[(size_t)row * DD + d] = y * sc;
        }
    }
}

// ---------------- dual RMS: rin (packed) + gin (f32) ----------------
__global__ void rms_dual_kernel(const float* __restrict__ in,
                                const float* __restrict__ scaleA,
                                unsigned* __restrict__ outAH,
                                unsigned* __restrict__ outAL,
                                const float* __restrict__ scaleB,
                                float cmulB,
                                float* __restrict__ outB)
{
    int row = blockIdx.x;
    int tid = threadIdx.x;
    const float* xr = in + (size_t)row * DD;
    float ss = 0.f;
    for (int d = tid; d < DD; d += 256) { float v = xr[d]; ss += v * v; }
    for (int o = 16; o > 0; o >>= 1) ss += __shfl_xor_sync(0xffffffffu, ss, o);
    __shared__ float wsum[8];
    if ((tid & 31) == 0) wsum[tid >> 5] = ss;
    __syncthreads();
    float tot = 0.f;
    #pragma unroll
    for (int w = 0; w < 8; w++) tot += wsum[w];
    float inv = rsqrtf(tot * (1.0f / DD) + EPS);
    for (int d = 2 * tid; d < DD; d += 512) {
        float x0 = xr[d], x1 = xr[d + 1];
        float a0 = x0 * inv * scaleA[d], a1 = x1 * inv * scaleA[d + 1];
        unsigned h, l;
        split_pack(a0, a1, h, l);
        size_t w = (size_t)row * (DD / 2) + d / 2;
        outAH[w] = h; outAL[w] = l;
        outB[(size_t)row * DD + d]     = x0 * inv * scaleB[d] * cmulB;
        outB[(size_t)row * DD + d + 1] = x1 * inv * scaleB[d + 1] * cmulB;
    }
}

// ---------------- per-head RMS (+ RoPE) ----------------
__global__ void head_norm_rope_kernel(const float* __restrict__ in,
                                      int tokStride, int colOff,
                                      unsigned* __restrict__ outH,
                                      unsigned* __restrict__ outL,
                                      const float* __restrict__ scale,
                                      const int* __restrict__ positions,
                                      int H, int doRope)
{
    int idx = blockIdx.x;
    int tid = threadIdx.x;
    int tok = idx / H;
    int h = idx - tok * H;
    int s = tok % SS;
    int b = tok / SS;
    const float* xr = in + (size_t)tok * tokStride + colOff + h * HD;
    float v = xr[tid];
    float ss = v * v;
    for (int o = 16; o > 0; o >>= 1) ss += __shfl_xor_sync(0xffffffffu, ss, o);
    __shared__ float wsum[4];
    __shared__ float tmp[HD];
    if ((tid & 31) == 0) wsum[tid >> 5] = ss;
    __syncthreads();
    float tot = wsum[0] + wsum[1] + wsum[2] + wsum[3];
    float y = v * rsqrtf(tot * (1.0f / HD) + EPS) * scale[tid];
    if (doRope) {
        tmp[tid] = y;
        __syncthreads();
        int pos = positions[b * SS + s];
        int j = tid & 63;
        float invf = powf(10000.0f, -(float)j / 64.0f);
        float ang = (float)pos * invf;
        float sn, cs;
        sincosf(ang, &sn, &cs);
        float x1 = tmp[j], x2 = tmp[64 + j];
        y = (tid < 64) ? (x1 * cs - x2 * sn) : (x2 * cs + x1 * sn);
        __syncthreads();
    }
    tmp[tid] = y;
    __syncthreads();
    if (tid < 64) {
        unsigned h2, l2;
        split_pack(tmp[2 * tid], tmp[2 * tid + 1], h2, l2);
        size_t w = (size_t)idx * 64 + tid;
        outH[w] = h2; outL[w] = l2;
    }
}

// ---------------- flash attention ----------------
#define ATQ 128
#define AKT 64
#define AST 68
#define AQ_WORDS (ATQ*AST)
#define AKV_WORDS (AKT*AST)
#define AKV_STAGE_BYTES (4*AKV_WORDS*4)
#define ATT_SMEM_BYTES ((2*AQ_WORDS + 8*AKV_WORDS)*4)

__global__ void __launch_bounds__(256, 1)
fattn_kernel(const unsigned* __restrict__ qh, const unsigned* __restrict__ ql,
             const unsigned* __restrict__ kh, const unsigned* __restrict__ kl,
             const unsigned* __restrict__ vh, const unsigned* __restrict__ vl,
             unsigned* __restrict__ obh, unsigned* __restrict__ obl)
{
    extern __shared__ __align__(16) unsigned att_smem[];
    int b = blockIdx.z, h = blockIdx.y;
    int q0 = (gridDim.x - 1 - blockIdx.x) * ATQ;
    int hkv = h / GRP;
    int tid = threadIdx.x, wid = tid >> 5, lane = tid & 31;
    int gid = lane >> 2, tgid = lane & 3;
    int l15 = lane & 15, lHi8 = (lane >> 4) << 3;

    unsigned smemBase = (unsigned)__cvta_generic_to_shared(att_smem);
    unsigned qBaseH = smemBase;
    unsigned qBaseL = smemBase + AQ_WORDS * 4;
    unsigned kvBase0 = smemBase + 2 * AQ_WORDS * 4;

    #pragma unroll
    for (int p = 0; p < 16; p++) {
        int ci = tid + p * 256;
        int plane = ci >> 11, rem = ci & 2047;
        int row = rem >> 4, c = rem & 15;
        const unsigned* src = (plane ? ql : qh)
            + ((size_t)(b * SS + q0 + row) * HQ + h) * 64 + c * 4;
        unsigned dst = (plane ? qBaseL : qBaseH) + (row * AST + c * 4) * 4;
        cp16(dst, src, 16);
    }

    int ntiles = (q0 >> 6) + 2;
    auto fillKV = [&](int st, int j0) {
        unsigned base = kvBase0 + st * AKV_STAGE_BYTES;
        #pragma unroll
        for (int p = 0; p < 16; p++) {
            int ci = tid + p * 256;
            int plane = ci >> 10, rem = ci & 1023;
            int row = rem >> 4, c = rem & 15;
            const unsigned* gp = (plane & 2) ? ((plane & 1) ? vl : vh)
                                             : ((plane & 1) ? kl : kh);
            const unsigned* src = gp + ((size_t)(b * SS + j0 + row) * HKV + hkv) * 64 + c * 4;
            unsigned dst = base + plane * (AKV_WORDS * 4) + (row * AST + c * 4) * 4;
            cp16(dst, src, 16);
        }
        CP_COMMIT();
    };

    fillKV(0, 0);
    CP_WAIT0();
    __syncthreads();

    float oacc[16][4];
    #pragma unroll
    for (int i = 0; i < 16; i++)
        #pragma unroll
        for (int c = 0; c < 4; c++) oacc[i][c] = 0.f;
    float m0 = -1e30f, m1 = -1e30f, l0r = 0.f, l1r = 0.f;

    int rowbase = q0 + wid * 16;
    int kKey = (lane & 7) + ((lane >> 4) << 3);
    int kDimOff = (lane & 8) ? 8 : 0;

    for (int jt = 0;;) {
        int j0 = jt * AKT;
        if (jt + 1 < ntiles) fillKV((jt + 1) & 1, (jt + 1) * AKT);

        if (j0 <= rowbase + 15) {
            unsigned base = kvBase0 + (jt & 1) * AKV_STAGE_BYTES;
            unsigned kBaseH = base;
            unsigned kBaseL = base + AKV_WORDS * 4;
            unsigned vBaseH = base + 2 * AKV_WORDS * 4;
            unsigned vBaseL = base + 3 * AKV_WORDS * 4;

            float s[8][4];
            #pragma unroll
            for (int nf = 0; nf < 8; nf++)
                #pragma unroll
                for (int c = 0; c < 4; c++) s[nf][c] = 0.f;

            #pragma unroll
            for (int kt = 0; kt < 8; kt++) {
                unsigned qhf[4], qlf[4];
                unsigned qoff = (unsigned)((wid * 16 + l15) * (AST * 4) + (kt * 16 + lHi8) * 2);
                LDSM4(qhf[0], qhf[1], qhf[2], qhf[3], qBaseH + qoff);
                LDSM4(qlf[0], qlf[1], qlf[2], qlf[3], qBaseL + qoff);
                int kdd = kt * 16 + kDimOff;
                #pragma unroll
                for (int g2 = 0; g2 < 4; g2++) {
                    unsigned koff = (unsigned)((g2 * 16 + kKey) * (AST * 4) + kdd * 2);
                    unsigned kh0, kh1, kh2, kh3, klo0, klo1, klo2, klo3;
                    LDSM4(kh0, kh1, kh2, kh3, kBaseH + koff);
                    LDSM4(klo0, klo1, klo2, klo3, kBaseL + koff);
                    int n0 = 2 * g2, n1 = 2 * g2 + 1;
                    MMA_BF16(s[n0][0], s[n0][1], s[n0][2], s[n0][3],
                             qlf[0], qlf[1], qlf[2], qlf[3], kh0, kh1);
                    MMA_BF16(s[n0][0], s[n0][1], s[n0][2], s[n0][3],
                             qhf[0], qhf[1], qhf[2], qhf[3], klo0, klo1);
                    MMA_BF16(s[n0][0], s[n0][1], s[n0][2], s[n0][3],
                             qhf[0], qhf[1], qhf[2], qhf[3], kh0, kh1);
                    MMA_BF16(s[n1][0], s[n1][1], s[n1][2], s[n1][3],
                             qlf[0], qlf[1], qlf[2], qlf[3], kh2, kh3);
                    MMA_BF16(s[n1][0], s[n1][1], s[n1][2], s[n1][3],
                             qhf[0], qhf[1], qhf[2], qhf[3], klo2, klo3);
                    MMA_BF16(s[n1][0], s[n1][1], s[n1][2], s[n1][3],
                             qhf[0], qhf[1], qhf[2], qhf[3], kh2, kh3);
                }
            }

            int r0 = rowbase + gid, r1 = r0 + 8;
            if (j0 + AKT - 1 > rowbase) {
                #pragma unroll
                for (int nf = 0; nf < 8; nf++) {
                    int c0 = j0 + nf * 8 + 2 * tgid;
                    if (c0 > r0)     s[nf][0] = -1e30f;
                    if (c0 + 1 > r0) s[nf][1] = -1e30f;
                    if (c0 > r1)     s[nf][2] = -1e30f;
                    if (c0 + 1 > r1) s[nf][3] = -1e30f;
                }
            }

            float t0 = -1e30f, t1 = -1e30f;
            #pragma unroll
            for (int nf = 0; nf < 8; nf++) {
                t0 = fmaxf(t0, fmaxf(s[nf][0], s[nf][1]));
                t1 = fmaxf(t1, fmaxf(s[nf][2], s[nf][3]));
            }
            t0 = fmaxf(t0, __shfl_xor_sync(0xffffffffu, t0, 1));
            t0 = fmaxf(t0, __shfl_xor_sync(0xffffffffu, t0, 2));
            t1 = fmaxf(t1, __shfl_xor_sync(0xffffffffu, t1, 1));
            t1 = fmaxf(t1, __shfl_xor_sync(0xffffffffu, t1, 2));
            float mn0 = fmaxf(m0, t0), mn1 = fmaxf(m1, t1);
            float a0 = __expf(m0 - mn0), a1 = __expf(m1 - mn1);
            m0 = mn0; m1 = mn1;
            float rs0 = 0.f, rs1 = 0.f;
            #pragma unroll
            for (int nf = 0; nf < 8; nf++) {
                s[nf][0] = __expf(s[nf][0] - mn0);
                s[nf][1] = __expf(s[nf][1] - mn0);
                s[nf][2] = __expf(s[nf][2] - mn1);
                s[nf][3] = __expf(s[nf][3] - mn1);
                rs0 += s[nf][0] + s[nf][1];
                rs1 += s[nf][2] + s[nf][3];
            }
            rs0 += __shfl_xor_sync(0xffffffffu, rs0, 1);
            rs0 += __shfl_xor_sync(0xffffffffu, rs0, 2);
            rs1 += __shfl_xor_sync(0xffffffffu, rs1, 1);
            rs1 += __shfl_xor_sync(0xffffffffu, rs1, 2);
            l0r = l0r * a0 + rs0;
            l1r = l1r * a1 + rs1;
            #pragma unroll
            for (int nv = 0; nv < 16; nv++) {
                oacc[nv][0] *= a0; oacc[nv][1] *= a0;
                oacc[nv][2] *= a1; oacc[nv][3] *= a1;
            }

            #pragma unroll
            for (int t = 0; t < 4; t++) {
                unsigned ph[4], pl[4];
                split_pack(s[2 * t][0],     s[2 * t][1],     ph[0], pl[0]);
                split_pack(s[2 * t][2],     s[2 * t][3],     ph[1], pl[1]);
                split_pack(s[2 * t + 1][0], s[2 * t + 1][1], ph[2], pl[2]);
                split_pack(s[2 * t + 1][2], s[2 * t + 1][3], ph[3], pl[3]);
                unsigned vf[16][2];
                int krow = t * 16 + l15;
                #pragma unroll
                for (int np = 0; np < 8; np++) {
                    unsigned voff = (unsigned)(krow * (AST * 4) + (np * 16 + lHi8) * 2);
                    LDSM4T(vf[2 * np][0], vf[2 * np][1], vf[2 * np + 1][0], vf[2 * np + 1][1],
                           vBaseH + voff);
                }
                #pragma unroll
                for (int nv = 0; nv < 16; nv++) {
                    MMA_BF16(oacc[nv][0], oacc[nv][1], oacc[nv][2], oacc[nv][3],
                             pl[0], pl[1], pl[2], pl[3], vf[nv][0], vf[nv][1]);
                    MMA_BF16(oacc[nv][0], oacc[nv][1], oacc[nv][2], oacc[nv][3],
                             ph[0], ph[1], ph[2], ph[3], vf[nv][0], vf[nv][1]);
                }
                #pragma unroll
                for (int np = 0; np < 8; np++) {
                    unsigned voff = (unsigned)(krow * (AST * 4) + (np * 16 + lHi8) * 2);
                    LDSM4T(vf[2 * np][0], vf[2 * np][1], vf[2 * np + 1][0], vf[2 * np + 1][1],
                           vBaseL + voff);
                }
                #pragma unroll
                for (int nv = 0; nv < 16; nv++) {
                    MMA_BF16(oacc[nv][0], oacc[nv][1], oacc[nv][2], oacc[nv][3],
                             ph[0], ph[1], ph[2], ph[3], vf[nv][0], vf[nv][1]);
                }
            }
        }

        if (++jt == ntiles) break;
        CP_WAIT0();
        __syncthreads();
    }

    int r0 = rowbase + gid, r1 = r0 + 8;
    float il0 = 1.f / l0r, il1 = 1.f / l1r;
    #pragma unroll
    for (int nv = 0; nv < 16; nv++) {
        int col = nv * 8 + 2 * tgid;
        unsigned hw, lw;
        split_pack(oacc[nv][0] * il0, oacc[nv][1] * il0, hw, lw);
        size_t w0 = ((size_t)(b * SS + r0) * HQ + h) * 64 + col / 2;
        obh[w0] = hw; obl[w0] = lw;
        split_pack(oacc[nv][2] * il1, oacc[nv][3] * il1, hw, lw);
        size_t w1 = ((size_t)(b * SS + r1) * HQ + h) * 64 + col / 2;
        obh[w1] = hw; obl[w1] = lw;
    }
}

// ================= bf16x3 GEMM =================
#define BAST 20
#define BBST 68
#define GA_WORDS (128*BAST)
#define GB_WORDS (32*BBST)
#define GSTAGE_WORDS (2*GA_WORDS + 2*GB_WORDS)
#define GEMM_DSMEM (2*GSTAGE_WORDS*4)

__global__ void __launch_bounds__(256, 2)
bf16_gemm_kernel(const unsigned* __restrict__ AhG, const unsigned* __restrict__ AlG,
                 const unsigned* __restrict__ BhG, const unsigned* __restrict__ BlG,
                 float* __restrict__ C,
                 int M, int N, int K,
                 const int* __restrict__ aIdxg,
                 const int* __restrict__ cIdxg,
                 const int* __restrict__ cntg,
                 const float* __restrict__ combine,
                 size_t aZW, size_t bZW, int idxZ)
{
    extern __shared__ __align__(16) unsigned dsm[];
    int z = blockIdx.z;
    const unsigned* Ah = AhG + (size_t)z * aZW;
    const unsigned* Al = AlG + (size_t)z * aZW;
    const unsigned* Bh = BhG + (size_t)z * bZW;
    const unsigned* Bl = BlG + (size_t)z * bZW;
    const int* aIdx = aIdxg ? aIdxg + (size_t)z * idxZ : nullptr;
    const int* cIdx = cIdxg ? cIdxg + (size_t)z * idxZ : nullptr;
    int Meff = cntg ? min(M, cntg[z]) : M;
    int bm = blockIdx.y * 128;
    int bn = blockIdx.x * 128;
    if (bm >= Meff) return;
    int Kw = K >> 1, Nw = N >> 1, bnw = bn >> 1;

    int tid = threadIdx.x;
    int wid = tid >> 5, lane = tid & 31;
    int gid = lane >> 2, tgid = lane & 3;
    int wm = (wid & 3) * 32;
    int wn = (wid >> 2) * 64;
    int l15 = lane & 15, lHi8 = (lane >> 4) << 3;

    int am = tid >> 1, ac = (tid & 1) * 2;
    int gr = bm + am;
    int ar = (gr < Meff) ? (aIdx ? aIdx[gr] : gr) : 0;
    int aValid = (gr < Meff) ? 16 : 0;
    const unsigned* aRowH = Ah + (size_t)ar * Kw;
    const unsigned* aRowL = Al + (size_t)ar * Kw;
    int bk = tid >> 3, bc = (2 * tid) & 15;

    unsigned smemBase = (unsigned)__cvta_generic_to_shared(dsm);

    auto fillStage = [&](int st, int k0) {
        int kw0 = k0 >> 1;
        unsigned base = smemBase + st * (GSTAGE_WORDS * 4);
        unsigned aHb = base, aLb = base + GA_WORDS * 4;
        unsigned bHb = aLb + GA_WORDS * 4, bLb = bHb + GB_WORDS * 4;
        #pragma unroll
        for (int c2 = 0; c2 < 2; c2++) {
            int c = ac + c2;
            unsigned d = (am * BAST + c * 4) * 4;
            cp16(aHb + d, aRowH + kw0 + c * 4, aValid);
            cp16(aLb + d, aRowL + kw0 + c * 4, aValid);
        }
        size_t bro = (size_t)(k0 + bk) * Nw + bnw;
        #pragma unroll
        for (int c2 = 0; c2 < 2; c2++) {
            int c = bc + c2;
            unsigned d = (bk * BBST + c * 4) * 4;
            cp16(bHb + d, Bh + bro + c * 4, 16);
            cp16(bLb + d, Bl + bro + c * 4, 16);
        }
        CP_COMMIT();
    };

    float acc[2][8][4];
    #pragma unroll
    for (int i = 0; i < 2; i++)
        #pragma unroll
        for (int j = 0; j < 8; j++)
            #pragma unroll
            for (int c = 0; c < 4; c++) acc[i][j][c] = 0.f;

    int KT = K >> 5;
    fillStage(0, 0);
    CP_WAIT0();
    __syncthreads();

    for (int kt = 0;;) {
        if (kt + 1 < KT) fillStage((kt + 1) & 1, (kt + 1) << 5);

        unsigned base = smemBase + (kt & 1) * (GSTAGE_WORDS * 4);
        unsigned aBaseH = base, aBaseL = base + GA_WORDS * 4;
        unsigned bBaseH = aBaseL + GA_WORDS * 4, bBaseL = bBaseH + GB_WORDS * 4;

        #pragma unroll
        for (int ks = 0; ks < 2; ks++) {
            int kk = ks * 16;
            unsigned ah[2][4], al[2][4];
            #pragma unroll
            for (int mf = 0; mf < 2; mf++) {
                int mrow = wm + mf * 16 + l15;
                unsigned off = (unsigned)(mrow * (BAST * 4) + (kk + lHi8) * 2);
                LDSM4(ah[mf][0], ah[mf][1], ah[mf][2], ah[mf][3], aBaseH + off);
                LDSM4(al[mf][0], al[mf][1], al[mf][2], al[mf][3], aBaseL + off);
            }
            unsigned bfr[8][2];
            int krow = kk + l15;
            #pragma unroll
            for (int nfp = 0; nfp < 4; nfp++) {
                int ncol = wn + nfp * 16 + lHi8;
                unsigned off = (unsigned)(krow * (BBST * 4) + ncol * 2);
                LDSM4T(bfr[2 * nfp][0], bfr[2 * nfp][1],
                       bfr[2 * nfp + 1][0], bfr[2 * nfp + 1][1], bBaseH + off);
            }
            #pragma unroll
            for (int mf = 0; mf < 2; mf++)
                #pragma unroll
                for (int nf = 0; nf < 8; nf++) {
                    MMA_BF16(acc[mf][nf][0], acc[mf][nf][1], acc[mf][nf][2], acc[mf][nf][3],
                             ah[mf][0], ah[mf][1], ah[mf][2], ah[mf][3],
                             bfr[nf][0], bfr[nf][1]);
                    MMA_BF16(acc[mf][nf][0], acc[mf][nf][1], acc[mf][nf][2], acc[mf][nf][3],
                             al[mf][0], al[mf][1], al[mf][2], al[mf][3],
                             bfr[nf][0], bfr[nf][1]);
                }
            #pragma unroll
            for (int nfp = 0; nfp < 4; nfp++) {
                int ncol = wn + nfp * 16 + lHi8;
                unsigned off = (unsigned)(krow * (BBST * 4) + ncol * 2);
                LDSM4T(bfr[2 * nfp][0], bfr[2 * nfp][1],
                       bfr[2 * nfp + 1][0], bfr[2 * nfp + 1][1], bBaseL + off);
            }
            #pragma unroll
            for (int mf = 0; mf < 2; mf++)
                #pragma unroll
                for (int nf = 0; nf < 8; nf++) {
                    MMA_BF16(acc[mf][nf][0], acc[mf][nf][1], acc[mf][nf][2], acc[mf][nf][3],
                             ah[mf][0], ah[mf][1], ah[mf][2], ah[mf][3],
                             bfr[nf][0], bfr[nf][1]);
                }
        }

        if (++kt == KT) break;
        CP_WAIT0();
        __syncthreads();
    }

    #pragma unroll
    for (int mf = 0; mf < 2; mf++) {
        #pragma unroll
        for (int half = 0; half < 2; half++) {
            int row = bm + wm + mf * 16 + gid + half * 8;
            if (row >= Meff) continue;
            int crow = cIdx ? cIdx[row] : row;
            float w = 1.f;
            if (combine) w = combine[crow * EE + z];
            #pragma unroll
            for (int nf = 0; nf < 8; nf++) {
                int col = bn + wn + nf * 8 + 2 * tgid;
                float v0 = acc[mf][nf][half * 2 + 0];
                float v1 = acc[mf][nf][half * 2 + 1];
                float* cp = C + (size_t)crow * N + col;
                if (combine) {
                    atomicAdd(cp, w * v0);
                    atomicAdd(cp + 1, w * v1);
                } else {
                    cp[0] = v0;
                    cp[1] = v1;
                }
            }
        }
    }
}

// ========== gated dual-B bf16x3 GEMM ==========
__global__ void __launch_bounds__(256, 2)
bf16_gated_kernel(const unsigned* __restrict__ Ah, const unsigned* __restrict__ Al,
                  const unsigned* __restrict__ B0hG, const unsigned* __restrict__ B0lG,
                  const unsigned* __restrict__ B1hG, const unsigned* __restrict__ B1lG,
                  unsigned* __restrict__ ChG, unsigned* __restrict__ ClG,
                  int M, int Nout, int K,
                  const int* __restrict__ aIdxg,
                  const int* __restrict__ cntg,
                  size_t bZW, size_t cZW, int idxZ)
{
    extern __shared__ __align__(16) unsigned dsm[];
    int z = blockIdx.z;
    const unsigned* B0h = B0hG + (size_t)z * bZW;
    const unsigned* B0l = B0lG + (size_t)z * bZW;
    const unsigned* B1h = B1hG + (size_t)z * bZW;
    const unsigned* B1l = B1lG + (size_t)z * bZW;
    unsigned* Ch = ChG + (size_t)z * cZW;
    unsigned* Cl = ClG + (size_t)z * cZW;
    const int* aIdx = aIdxg ? aIdxg + (size_t)z * idxZ : nullptr;
    int Meff = cntg ? min(M, cntg[z]) : M;
    int bm = blockIdx.y * 128;
    int bnn = blockIdx.x * 64;
    if (bm >= Meff) return;
    int Kw = K >> 1, Nw = Nout >> 1, bnw = bnn >> 1;

    int tid = threadIdx.x;
    int wid = tid >> 5, lane = tid & 31;
    int gid = lane >> 2, tgid = lane & 3;
    int wm = (wid & 3) * 32;
    int wn32 = (wid >> 2) * 32;
    int l15 = lane & 15, lHi8 = (lane >> 4) << 3;

    int am = tid >> 1, ac = (tid & 1) * 2;
    int gr = bm + am;
    int ar = (gr < Meff) ? (aIdx ? aIdx[gr] : gr) : 0;
    int aValid = (gr < Meff) ? 16 : 0;
    const unsigned* aRowH = Ah + (size_t)ar * Kw;
    const unsigned* aRowL = Al + (size_t)ar * Kw;
    int bk = tid >> 3;
    int brest = (2 * tid) & 15;

    unsigned smemBase = (unsigned)__cvta_generic_to_shared(dsm);

    auto fillStage = [&](int st, int k0) {
        int kw0 = k0 >> 1;
        unsigned base = smemBase + st * (GSTAGE_WORDS * 4);
        unsigned aHb = base, aLb = base + GA_WORDS * 4;
        unsigned bHb = aLb + GA_WORDS * 4, bLb = bHb + GB_WORDS * 4;
        #pragma unroll
        for (int c2 = 0; c2 < 2; c2++) {
            int c = ac + c2;
            unsigned d = (am * BAST + c * 4) * 4;
            cp16(aHb + d, aRowH + kw0 + c * 4, aValid);
            cp16(aLb + d, aRowL + kw0 + c * 4, aValid);
        }
        size_t bro = (size_t)(k0 + bk) * Nw + bnw;
        #pragma unroll
        for (int c2 = 0; c2 < 2; c2++) {
            int cc = brest + c2;
            int srcSel = cc >> 3, c = cc & 7;
            unsigned d = (bk * BBST + srcSel * 32 + c * 4) * 4;
            cp16(bHb + d, (srcSel ? B1h : B0h) + bro + c * 4, 16);
            cp16(bLb + d, (srcSel ? B1l : B0l) + bro + c * 4, 16);
        }
        CP_COMMIT();
    };

    float acc0[2][4][4], acc1[2][4][4];
    #pragma unroll
    for (int i = 0; i < 2; i++)
        #pragma unroll
        for (int j = 0; j < 4; j++)
            #pragma unroll
            for (int c = 0; c < 4; c++) { acc0[i][j][c] = 0.f; acc1[i][j][c] = 0.f; }

    int KT = K >> 5;
    fillStage(0, 0);
    CP_WAIT0();
    __syncthreads();

    for (int kt = 0;;) {
        if (kt + 1 < KT) fillStage((kt + 1) & 1, (kt + 1) << 5);

        unsigned base = smemBase + (kt & 1) * (GSTAGE_WORDS * 4);
        unsigned aBaseH = base, aBaseL = base + GA_WORDS * 4;
        unsigned bBaseH = aBaseL + GA_WORDS * 4, bBaseL = bBaseH + GB_WORDS * 4;

        #pragma unroll
        for (int ks = 0; ks < 2; ks++) {
            int kk = ks * 16;
            unsigned ah[2][4], al[2][4];
            #pragma unroll
            for (int mf = 0; mf < 2; mf++) {
                int mrow = wm + mf * 16 + l15;
                unsigned off = (unsigned)(mrow * (BAST * 4) + (kk + lHi8) * 2);
                LDSM4(ah[mf][0], ah[mf][1], ah[mf][2], ah[mf][3], aBaseH + off);
                LDSM4(al[mf][0], al[mf][1], al[mf][2], al[mf][3], aBaseL + off);
            }
            int krow = kk + l15;
            #pragma unroll
            for (int which = 0; which < 2; which++) {
                unsigned bfr[4][2];
                int colbase = which * 64 + wn32;
                #pragma unroll
                for (int nfp = 0; nfp < 2; nfp++) {
                    int ncol = colbase + nfp * 16 + lHi8;
                    unsigned off = (unsigned)(krow * (BBST * 4) + ncol * 2);
                    LDSM4T(bfr[2 * nfp][0], bfr[2 * nfp][1],
                           bfr[2 * nfp + 1][0], bfr[2 * nfp + 1][1], bBaseH + off);
                }
                #pragma unroll
                for (int mf = 0; mf < 2; mf++)
                    #pragma unroll
                    for (int nf = 0; nf < 4; nf++) {
                        float* a = which ? acc1[mf][nf] : acc0[mf][nf];
                        MMA_BF16(a[0], a[1], a[2], a[3],
                                 ah[mf][0], ah[mf][1], ah[mf][2], ah[mf][3],
                                 bfr[nf][0], bfr[nf][1]);
                        MMA_BF16(a[0], a[1], a[2], a[3],
                                 al[mf][0], al[mf][1], al[mf][2], al[mf][3],
                                 bfr[nf][0], bfr[nf][1]);
                    }
                #pragma unroll
                for (int nfp = 0; nfp < 2; nfp++) {
                    int ncol = colbase + nfp * 16 + lHi8;
                    unsigned off = (unsigned)(krow * (BBST * 4) + ncol * 2);
                    LDSM4T(bfr[2 * nfp][0], bfr[2 * nfp][1],
                           bfr[2 * nfp + 1][0], bfr[2 * nfp + 1][1], bBaseL + off);
                }
                #pragma unroll
                for (int mf = 0; mf < 2; mf++)
                    #pragma unroll
                    for (int nf = 0; nf < 4; nf++) {
                        float* a = which ? acc1[mf][nf] : acc0[mf][nf];
                        MMA_BF16(a[0], a[1], a[2], a[3],
                                 ah[mf][0], ah[mf][1], ah[mf][2], ah[mf][3],
                                 bfr[nf][0], bfr[nf][1]);
                    }
            }
        }

        if (++kt == KT) break;
        CP_WAIT0();
        __syncthreads();
    }

    #pragma unroll
    for (int mf = 0; mf < 2; mf++) {
        #pragma unroll
        for (int half = 0; half < 2; half++) {
            int row = bm + wm + mf * 16 + gid + half * 8;
            if (row >= Meff) continue;
            #pragma unroll
            for (int nf = 0; nf < 4; nf++) {
                int col = bnn + wn32 + nf * 8 + 2 * tgid;
                float g0v = gelu_tanh(acc0[mf][nf][half * 2 + 0]) * acc1[mf][nf][half * 2 + 0];
                float g1v = gelu_tanh(acc0[mf][nf][half * 2 + 1]) * acc1[mf][nf][half * 2 + 1];
                unsigned hw, lw;
                split_pack(g0v, g1v, hw, lw);
                size_t w = (size_t)row * Nw + (col >> 1);
                Ch[w] = hw; Cl[w] = lw;
            }
        }
    }
}

// ---------------- router ----------------
__global__ void router_kernel(const float* __restrict__ gin,
                              const float* __restrict__ wg,
                              float* __restrict__ combine,
                              int* __restrict__ cnt,
                              int* __restrict__ idx,
                              float* __restrict__ psum)
{
    int tok = blockIdx.x;
    int tid = threadIdx.x;
    float s[EE] = {};
    const float* g = gin + (size_t)tok * DD;
    for (int d = tid; d < DD; d += 256) {
        float gv = g[d];
        const float* w = wg + d * EE;
        #pragma unroll
        for (int e = 0; e < EE; e++) s[e] += gv * w[e];
    }
    __shared__ float sh[256][EE];
    #pragma unroll
    for (int e = 0; e < EE; e++) sh[tid][e] = s[e];
    __syncthreads();
    for (int str = 128; str > 0; str >>= 1) {
        if (tid < str) {
            #pragma unroll
            for (int e = 0; e < EE; e++) sh[tid][e] += sh[tid + str][e];
        }
        __syncthreads();
    }
    if (tid == 0) {
        float pe[EE];
        float mx = -FLT_MAX;
        #pragma unroll
        for (int e = 0; e < EE; e++) mx = fmaxf(mx, sh[0][e]);
        float sum = 0.f;
        #pragma unroll
        for (int e = 0; e < EE; e++) { pe[e] = expf(sh[0][e] - mx); sum += pe[e]; }
        float inv = 1.0f / sum;
        #pragma unroll
        for (int e = 0; e < EE; e++) { pe[e] *= inv; atomicAdd(&psum[e], pe[e]); }
        int i0 = 0;
        #pragma unroll
        for (int e = 1; e < EE; e++) if (pe[e] > pe[i0]) i0 = e;
        int i1 = (i0 == 0) ? 1 : 0;
        #pragma unroll
        for (int e = 0; e < EE; e++) if (e != i0 && e != i1 && pe[e] > pe[i1]) i1 = e;
        float tot = pe[i0] + pe[i1];
        float w0 = pe[i0] / tot, w1 = pe[i1] / tot;
        float* crow = combine + (size_t)tok * EE;
        #pragma unroll
        for (int e = 0; e < EE; e++) crow[e] = 0.f;
        crow[i0] = w0; crow[i1] = w1;
        int p0 = atomicAdd(&cnt[i0], 1); idx[i0 * TT + p0] = tok;
        int p1 = atomicAdd(&cnt[i1], 1); idx[i1 * TT + p1] = tok;
    }
}

__global__ void lb_kernel(const int* __restrict__ cnt, const float* __restrict__ psum,
                          float* __restrict__ out)
{
    float lb = 0.f;
    #pragma unroll
    for (int e = 0; e < EE; e++)
        lb += ((float)cnt[e] / (float)TT) * (psum[e] / (float)TT);
    out[0] = lb * ((float)(EE * EE) / (float)EE);
}

// ==================== host launcher ====================
extern "C" void kernel_launch(void* const* d_in, const int* in_sizes, int n_in,
                              void* d_out, int out_size)
{
    const int*   positions       = (const int*)  d_in[0];
    const float* x               = (const float*)d_in[1];
    const float* pre_attn_scale  = (const float*)d_in[2];
    const float* wq              = (const float*)d_in[3];
    const float* wk              = (const float*)d_in[4];
    const float* wv              = (const float*)d_in[5];
    const float* wo              = (const float*)d_in[6];
    const float* q_norm_scale    = (const float*)d_in[7];
    const float* k_norm_scale    = (const float*)d_in[8];
    const float* v_norm_scale    = (const float*)d_in[9];
    const float* post_attn_scale = (const float*)d_in[10];
    const float* pre_ffw_scale   = (const float*)d_in[11];
    const float* shared_wi0      = (const float*)d_in[12];
    const float* shared_wi1      = (const float*)d_in[13];
    const float* shared_wo       = (const float*)d_in[14];
    const float* post_ff1_scale  = (const float*)d_in[15];
    const float* pre_ff2_scale   = (const float*)d_in[16];
    const float* router_scale    = (const float*)d_in[17];
    const float* w_gate          = (const float*)d_in[18];
    const float* ewi0            = (const float*)d_in[19];
    const float* ewi1            = (const float*)d_in[20];
    const float* ewo             = (const float*)d_in[21];
    const float* post_ff2_scale  = (const float*)d_in[22];
    const float* layer_scalar    = (const float*)d_in[23];
    float* out = (float*)d_out;

    static int smemConfigured = 0;
    if (!smemConfigured) {
        cudaFuncSetAttribute(fattn_kernel,
                             cudaFuncAttributeMaxDynamicSharedMemorySize, ATT_SMEM_BYTES);
        cudaFuncSetAttribute(bf16_gemm_kernel,
                             cudaFuncAttributeMaxDynamicSharedMemorySize, GEMM_DSMEM);
        cudaFuncSetAttribute(bf16_gated_kernel,
                             cudaFuncAttributeMaxDynamicSharedMemorySize, GEMM_DSMEM);
        smemConfigured = 1;
    }

    float* sc = nullptr;
    int*   isc = nullptr;
    cudaGetSymbolAddress((void**)&sc, g_scratch);
    cudaGetSymbolAddress((void**)&isc, g_iscratch);

    unsigned* U = (unsigned*)sc;
    auto uptr = [&](size_t off) { return U + off; };

    unsigned* lnxH = uptr(OFF_LNXH); unsigned* lnxL = uptr(OFF_LNXL);
    float* qkvf = sc + OFF_QKVF;
    unsigned* qsh = uptr(OFF_QH); unsigned* qsl = uptr(OFF_QL);
    unsigned* ksh = uptr(OFF_KH); unsigned* ksl = uptr(OFF_KL);
    unsigned* vsh = uptr(OFF_VH); unsigned* vsl = uptr(OFF_VL);
    unsigned* obh = uptr(OFF_OBH); unsigned* obl = uptr(OFF_OBL);
    float* attnb = sc + OFF_ATTN; float* hb = sc + OFF_H;
    unsigned* ffinH = uptr(OFF_FFINH); unsigned* ffinL = uptr(OFF_FFINL);
    unsigned* g0H = uptr(OFF_G0H); unsigned* g0L = uptr(OFF_G0L);
    float* shb = sc + OFF_SHB;
    unsigned* rinH = uptr(OFF_RINH); unsigned* rinL = uptr(OFF_RINL);
    float* gin = sc + OFF_GIN; float* routb = sc + OFF_ROUT;
    unsigned* egH = uptr(OFF_EGH); unsigned* egL = uptr(OFF_EGL);
    float* comb = sc + OFF_COMB; float* psum = sc + OFF_PSUM;
    int* idx = isc; int* cnt = isc + EE * TT;

    auto splitBF = [&](const float* src, size_t nElts, size_t offH, size_t offL) {
        size_t nQ = nElts / 4;
        split_bf_kernel<<<(unsigned)((nQ + 255) / 256), 256>>>(
            (const float4*)src, (uint2*)uptr(offH), (uint2*)uptr(offL), nQ);
    };

    // weight pre-split (vectorized)
    split_qkv_kernel<<<(unsigned)(SZ_WQKV / 4 / 256), 256>>>(
        wq, wk, wv, (uint2*)uptr(OFF_WQKVH), (uint2*)uptr(OFF_WQKVL));
    splitBF(wo, SZ_WQ, OFF_WOH, OFF_WOL);
    splitBF(shared_wi0, SZ_WFF, OFF_WI0H, OFF_WI0L);
    splitBF(shared_wi1, SZ_WFF, OFF_WI1H, OFF_WI1L);
    splitBF(shared_wo, SZ_WFF, OFF_SWOH, OFF_SWOL);
    splitBF(ewi0, SZ_EW, OFF_EWI0H, OFF_EWI0L);
    splitBF(ewi1, SZ_EW, OFF_EWI1H, OFF_EWI1L);
    splitBF(ewo, SZ_EW, OFF_EWOH, OFF_EWOL);

    auto gemm = [&](const unsigned* Ah, const unsigned* Al,
                    size_t BhOff, size_t BlOff, float* C, int M, int N, int K,
                    const int* aI, const int* cI, const int* ct, const float* cw,
                    size_t aZW, size_t bZW, int nz) {
        dim3 grid(N / 128, (M + 127) / 128, nz);
        bf16_gemm_kernel<<<grid, 256, GEMM_DSMEM>>>(Ah, Al, uptr(BhOff), uptr(BlOff),
                                                    C, M, N, K, aI, cI, ct, cw,
                                                    aZW, bZW, TT);
    };

    // 1) pre-attn norm
    rms_kernel<<<TT, 256>>>(x, pre_attn_scale, 1.f, nullptr, nullptr, nullptr,
                            nullptr, lnxH, lnxL);
    // 2) fused QKV projection
    gemm(lnxH, lnxL, OFF_WQKVH, OFF_WQKVL, qkvf, TT, NQKV, DD,
         nullptr, nullptr, nullptr, nullptr, 0, 0, 1);
    // 3) per-head norms + rope
    head_norm_rope_kernel<<<TT * HQ, HD>>>(qkvf, NQKV, 0, qsh, qsl,
                                           q_norm_scale, positions, HQ, 1);
    head_norm_rope_kernel<<<TT * HKV, HD>>>(qkvf, NQKV, 2048, ksh, ksl,
                                            k_norm_scale, positions, HKV, 1);
    head_norm_rope_kernel<<<TT * HKV, HD>>>(qkvf, NQKV, 3072, vsh, vsl,
                                            v_norm_scale, positions, HKV, 0);
    // 4) attention
    {
        dim3 grid(SS / ATQ, HQ, BB);
        fattn_kernel<<<grid, 256, ATT_SMEM_BYTES>>>(qsh, qsl, ksh, ksl, vsh, vsl, obh, obl);
    }
    // 5) output projection + post-attn norm + residual
    gemm(obh, obl, OFF_WOH, OFF_WOL, attnb, TT, DD, HQ * HD,
         nullptr, nullptr, nullptr, nullptr, 0, 0, 1);
    rms_kernel<<<TT, 256>>>(attnb, post_attn_scale, 1.f, x, nullptr, nullptr,
                            hb, nullptr, nullptr);
    // 6) shared FFN
    rms_kernel<<<TT, 256>>>(hb, pre_ffw_scale, 1.f, nullptr, nullptr, nullptr,
                            nullptr, ffinH, ffinL);
    {
        dim3 grid(FS / 64, TT / 128, 1);
        bf16_gated_kernel<<<grid, 256, GEMM_DSMEM>>>(
            ffinH, ffinL, uptr(OFF_WI0H), uptr(OFF_WI0L), uptr(OFF_WI1H), uptr(OFF_WI1L),
            g0H, g0L, TT, FS, DD, nullptr, nullptr, 0, 0, TT);
    }
    gemm(g0H, g0L, OFF_SWOH, OFF_SWOL, shb, TT, DD, FS,
         nullptr, nullptr, nullptr, nullptr, 0, 0, 1);
    rms_kernel<<<TT, 256>>>(shb, post_ff1_scale, 1.f, nullptr, nullptr, nullptr,
                            shb, nullptr, nullptr);
    // 7) router inputs (fused dual RMS)
    rms_dual_kernel<<<TT, 256>>>(hb, pre_ff2_scale, rinH, rinL,
                                 router_scale, 0.02209708691207961f, gin);
    // 8) router + batched MoE
    cudaMemsetAsync(cnt, 0, EE * sizeof(int));
    cudaMemsetAsync(psum, 0, EE * sizeof(float));
    cudaMemsetAsync(routb, 0, SZ_TD * sizeof(float));
    router_kernel<<<TT, 256>>>(gin, w_gate, comb, cnt, idx, psum);
    {
        dim3 grid(FE / 64, TT / 128, EE);
        bf16_gated_kernel<<<grid, 256, GEMM_DSMEM>>>(
            rinH, rinL, uptr(OFF_EWI0H), uptr(OFF_EWI0L), uptr(OFF_EWI1H), uptr(OFF_EWI1L),
            egH, egL, TT, FE, DD, idx, cnt,
            (size_t)DD * FE / 2, (size_t)TT * FE / 2, TT);
    }
    {
        dim3 grid(DD / 128, TT / 128, EE);
        bf16_gemm_kernel<<<grid, 256, GEMM_DSMEM>>>(
            egH, egL, uptr(OFF_EWOH), uptr(OFF_EWOL), routb, TT, DD, FE,
            nullptr, idx, cnt, comb,
            (size_t)TT * FE / 2, (size_t)FE * DD / 2, TT);
    }
    // 9) final combine
    rms_kernel<<<TT, 256>>>(routb, post_ff2_scale, 1.f, shb, hb, layer_scalar,
                            out, nullptr, nullptr);
    // 10) lb loss
    if (out_size > TT * DD) {
        lb_kernel<<<1, 1>>>(cnt, psum, out + (size_t)TT * DD);
    }
}

// round 15
// speedup vs baseline: 1.0379x; 1.0104x over previous
#include <cuda_runtime.h>
#include <cuda_bf16.h>
#include <cfloat>
#include <math.h>

#define BB 4
#define SS 1024
#define DD 2048
#define HQ 16
#define HKV 8
#define HD 128
#define GRP 2
#define EE 8
#define FE 1024
#define FS 8192
#define TT (BB*SS)
#define EPS 1e-6f
#define NQKV 4096

#define SZ_TD   ((size_t)TT*DD)
#define SZ_TQ   ((size_t)TT*HQ*HD)
#define SZ_TKV  ((size_t)TT*HKV*HD)
#define SZ_TFS  ((size_t)TT*FS)

#define OFF_LNXH  ((size_t)0)
#define OFF_LNXL  (OFF_LNXH + SZ_TD/2)
#define OFF_QKVF  (OFF_LNXL + SZ_TD/2)
#define OFF_QH    (OFF_QKVF + (size_t)TT*NQKV)
#define OFF_QL    (OFF_QH   + SZ_TQ/2)
#define OFF_KH    (OFF_QL   + SZ_TQ/2)
#define OFF_KL    (OFF_KH   + SZ_TKV/2)
#define OFF_VH    (OFF_KL   + SZ_TKV/2)
#define OFF_VL    (OFF_VH   + SZ_TKV/2)
#define OFF_OBH   (OFF_VL   + SZ_TKV/2)
#define OFF_OBL   (OFF_OBH  + SZ_TQ/2)
#define OFF_ATTN  (OFF_OBL  + SZ_TQ/2)
#define OFF_H     (OFF_ATTN + SZ_TD)
#define OFF_FFINH (OFF_H    + SZ_TD)
#define OFF_FFINL (OFF_FFINH+ SZ_TD/2)
#define OFF_G0H   (OFF_FFINL+ SZ_TD/2)
#define OFF_G0L   (OFF_G0H  + SZ_TFS/2)
#define OFF_SHB   (OFF_G0L  + SZ_TFS/2)
#define OFF_RINH  (OFF_SHB  + SZ_TD)
#define OFF_RINL  (OFF_RINH + SZ_TD/2)
#define OFF_GIN   (OFF_RINL + SZ_TD/2)
#define OFF_ROUT  (OFF_GIN  + SZ_TD)
#define OFF_EGH   (OFF_ROUT + SZ_TD)
#define OFF_EGL   (OFF_EGH  + SZ_TFS/2)
#define OFF_COMB  (OFF_EGL  + SZ_TFS/2)
#define OFF_PSUM  (OFF_COMB + (size_t)TT*EE)
#define SZ_WQKV ((size_t)DD*NQKV)
#define SZ_WQ  ((size_t)DD*HQ*HD)
#define SZ_WFF ((size_t)DD*FS)
#define SZ_EW  ((size_t)EE*DD*FE)
#define OFF_WQKVH (OFF_PSUM + 8)
#define OFF_WQKVL (OFF_WQKVH + SZ_WQKV/2)
#define OFF_WOH   (OFF_WQKVL + SZ_WQKV/2)
#define OFF_WOL   (OFF_WOH + SZ_WQ/2)
#define OFF_WI0H  (OFF_WOL + SZ_WQ/2)
#define OFF_WI0L  (OFF_WI0H + SZ_WFF/2)
#define OFF_WI1H  (OFF_WI0L + SZ_WFF/2)
#define OFF_WI1L  (OFF_WI1H + SZ_WFF/2)
#define OFF_SWOH  (OFF_WI1L + SZ_WFF/2)
#define OFF_SWOL  (OFF_SWOH + SZ_WFF/2)
#define OFF_EWI0H (OFF_SWOL + SZ_WFF/2)
#define OFF_EWI0L (OFF_EWI0H + SZ_EW/2)
#define OFF_EWI1H (OFF_EWI0L + SZ_EW/2)
#define OFF_EWI1L (OFF_EWI1H + SZ_EW/2)
#define OFF_EWOH  (OFF_EWI1L + SZ_EW/2)
#define OFF_EWOL  (OFF_EWOH + SZ_EW/2)
#define SCRATCH_TOTAL (OFF_EWOL + SZ_EW/2)

__device__ float g_scratch[SCRATCH_TOTAL];
__device__ int   g_iscratch[EE*TT + EE];

__device__ __forceinline__ float gelu_tanh(float v) {
    const float c = 0.7978845608028654f;
    float u = c * (v + 0.044715f * v * v * v);
    return 0.5f * v * (1.0f + tanhf(u));
}
__device__ __forceinline__ unsigned pack_bf16(float x, float y) {
    __nv_bfloat162 t = __floats2bfloat162_rn(x, y);
    return *reinterpret_cast<unsigned*>(&t);
}
__device__ __forceinline__ void split_pack(float x, float y,
                                           unsigned &hiW, unsigned &loW0) {
    __nv_bfloat16 bx = __float2bfloat16_rn(x);
    __nv_bfloat16 by = __float2bfloat16_rn(y);
    float hx = __bfloat162float(bx);
    float hy = __bfloat162float(by);
    __nv_bfloat162 h2; h2.x = bx; h2.y = by;
    hiW = *reinterpret_cast<unsigned*>(&h2);
    loW0 = pack_bf16(x - hx, y - hy);
}
__device__ __forceinline__ void cp16(unsigned dst, const void* src, int srcBytes) {
    asm volatile("cp.async.cg.shared.global [%0], [%1], 16, %2;"
                 :: "r"(dst), "l"(src), "r"(srcBytes));
}
#define CP_COMMIT() asm volatile("cp.async.commit_group;")
#define CP_WAIT0()  asm volatile("cp.async.wait_group 0;")

#define LDSM4(r0,r1,r2,r3,addr) \
    asm volatile("ldmatrix.sync.aligned.m8n8.x4.shared.b16 {%0,%1,%2,%3}, [%4];" \
                 : "=r"(r0),"=r"(r1),"=r"(r2),"=r"(r3) : "r"(addr))
#define LDSM4T(r0,r1,r2,r3,addr) \
    asm volatile("ldmatrix.sync.aligned.m8n8.x4.trans.shared.b16 {%0,%1,%2,%3}, [%4];" \
                 : "=r"(r0),"=r"(r1),"=r"(r2),"=r"(r3) : "r"(addr))
#define MMA_BF16(d0,d1,d2,d3,a0,a1,a2,a3,b0,b1) \
    asm volatile("mma.sync.aligned.m16n8k16.row.col.f32.bf16.bf16.f32 " \
                 "{%0,%1,%2,%3}, {%4,%5,%6,%7}, {%8,%9}, {%0,%1,%2,%3};" \
                 : "+f"(d0),"+f"(d1),"+f"(d2),"+f"(d3) \
                 : "r"(a0),"r"(a1),"r"(a2),"r"(a3),"r"(b0),"r"(b1))

// ---------------- splits (vectorized) ----------------
__global__ void split_bf_kernel(const float4* __restrict__ in,
                                uint2* __restrict__ hi,
                                uint2* __restrict__ lo, size_t nQuads)
{
    size_t i = (size_t)blockIdx.x * 256 + threadIdx.x;
    if (i < nQuads) {
        float4 v = in[i];
        uint2 h, l;
        split_pack(v.x, v.y, h.x, l.x);
        split_pack(v.z, v.w, h.y, l.y);
        hi[i] = h; lo[i] = l;
    }
}
__global__ void split_qkv_kernel(const float* __restrict__ wq,
                                 const float* __restrict__ wk,
                                 const float* __restrict__ wv,
                                 uint2* __restrict__ hi,
                                 uint2* __restrict__ lo)
{
    size_t q = (size_t)blockIdx.x * 256 + threadIdx.x;
    if (q >= (size_t)DD * (NQKV / 4)) return;
    int d = (int)(q / (NQKV / 4));
    int n0 = 4 * (int)(q % (NQKV / 4));
    float4 v;
    if (n0 < 2048)      v = *(const float4*)(wq + (size_t)d * 2048 + n0);
    else if (n0 < 3072) v = *(const float4*)(wk + (size_t)d * 1024 + (n0 - 2048));
    else                v = *(const float4*)(wv + (size_t)d * 1024 + (n0 - 3072));
    uint2 h, l;
    split_pack(v.x, v.y, h.x, l.x);
    split_pack(v.z, v.w, h.y, l.y);
    hi[q] = h; lo[q] = l;
}

// ---------------- RMS norm ----------------
__global__ void rms_kernel(const float* __restrict__ in,
                           const float* __restrict__ scale, float cmul,
                           const float* __restrict__ res1,
                           const float* __restrict__ res2,
                           const float* __restrict__ scalarPtr,
                           float* __restrict__ out,
                           unsigned* __restrict__ outH,
                           unsigned* __restrict__ outL)
{
    int row = blockIdx.x;
    int tid = threadIdx.x;
    const float* xr = in + (size_t)row * DD;
    float ss = 0.f;
    for (int d = tid; d < DD; d += 256) { float v = xr[d]; ss += v * v; }
    for (int o = 16; o > 0; o >>= 1) ss += __shfl_xor_sync(0xffffffffu, ss, o);
    __shared__ float wsum[8];
    if ((tid & 31) == 0) wsum[tid >> 5] = ss;
    __syncthreads();
    float tot = 0.f;
    #pragma unroll
    for (int w = 0; w < 8; w++) tot += wsum[w];
    float inv = rsqrtf(tot * (1.0f / DD) + EPS);
    float sc = scalarPtr ? *scalarPtr : 1.0f;
    if (outH) {
        for (int d = 2 * tid; d < DD; d += 512) {
            float y0 = xr[d] * inv, y1 = xr[d + 1] * inv;
            if (scale) { y0 *= scale[d]; y1 *= scale[d + 1]; }
            y0 *= cmul; y1 *= cmul;
            unsigned h, l;
            split_pack(y0, y1, h, l);
            size_t w = (size_t)row * (DD / 2) + d / 2;
            outH[w] = h; outL[w] = l;
        }
    } else {
        for (int d = tid; d < DD; d += 256) {
            float y = xr[d] * inv;
            if (scale) y *= scale[d];
            y *= cmul;
            if (res1) y += res1[(size_t)row * DD + d];
            if (res2) y += res2[(size_t)row * DD + d];
            out[(size_t)row * DD + d] = y * sc;
        }
    }
}

// ---------------- dual RMS ----------------
__global__ void rms_dual_kernel(const float* __restrict__ in,
                                const float* __restrict__ scaleA,
                                unsigned* __restrict__ outAH,
                                unsigned* __restrict__ outAL,
                                const float* __restrict__ scaleB,
                                float cmulB,
                                float* __restrict__ outB)
{
    int row = blockIdx.x;
    int tid = threadIdx.x;
    const float* xr = in + (size_t)row * DD;
    float ss = 0.f;
    for (int d = tid; d < DD; d += 256) { float v = xr[d]; ss += v * v; }
    for (int o = 16; o > 0; o >>= 1) ss += __shfl_xor_sync(0xffffffffu, ss, o);
    __shared__ float wsum[8];
    if ((tid & 31) == 0) wsum[tid >> 5] = ss;
    __syncthreads();
    float tot = 0.f;
    #pragma unroll
    for (int w = 0; w < 8; w++) tot += wsum[w];
    float inv = rsqrtf(tot * (1.0f / DD) + EPS);
    for (int d = 2 * tid; d < DD; d += 512) {
        float x0 = xr[d], x1 = xr[d + 1];
        float a0 = x0 * inv * scaleA[d], a1 = x1 * inv * scaleA[d + 1];
        unsigned h, l;
        split_pack(a0, a1, h, l);
        size_t w = (size_t)row * (DD / 2) + d / 2;
        outAH[w] = h; outAL[w] = l;
        outB[(size_t)row * DD + d]     = x0 * inv * scaleB[d] * cmulB;
        outB[(size_t)row * DD + d + 1] = x1 * inv * scaleB[d + 1] * cmulB;
    }
}

// ---------------- per-head RMS (+ RoPE) ----------------
__global__ void head_norm_rope_kernel(const float* __restrict__ in,
                                      int tokStride, int colOff,
                                      unsigned* __restrict__ outH,
                                      unsigned* __restrict__ outL,
                                      const float* __restrict__ scale,
                                      const int* __restrict__ positions,
                                      int H, int doRope)
{
    int idx = blockIdx.x;
    int tid = threadIdx.x;
    int tok = idx / H;
    int h = idx - tok * H;
    int s = tok % SS;
    int b = tok / SS;
    const float* xr = in + (size_t)tok * tokStride + colOff + h * HD;
    float v = xr[tid];
    float ss = v * v;
    for (int o = 16; o > 0; o >>= 1) ss += __shfl_xor_sync(0xffffffffu, ss, o);
    __shared__ float wsum[4];
    __shared__ float tmp[HD];
    if ((tid & 31) == 0) wsum[tid >> 5] = ss;
    __syncthreads();
    float tot = wsum[0] + wsum[1] + wsum[2] + wsum[3];
    float y = v * rsqrtf(tot * (1.0f / HD) + EPS) * scale[tid];
    if (doRope) {
        tmp[tid] = y;
        __syncthreads();
        int pos = positions[b * SS + s];
        int j = tid & 63;
        float invf = powf(10000.0f, -(float)j / 64.0f);
        float ang = (float)pos * invf;
        float sn, cs;
        sincosf(ang, &sn, &cs);
        float x1 = tmp[j], x2 = tmp[64 + j];
        y = (tid < 64) ? (x1 * cs - x2 * sn) : (x2 * cs + x1 * sn);
        __syncthreads();
    }
    tmp[tid] = y;
    __syncthreads();
    if (tid < 64) {
        unsigned h2, l2;
        split_pack(tmp[2 * tid], tmp[2 * tid + 1], h2, l2);
        size_t w = (size_t)idx * 64 + tid;
        outH[w] = h2; outL[w] = l2;
    }
}

// ---------------- flash attention ----------------
#define ATQ 128
#define AKT 64
#define AST 68
#define AQ_WORDS (ATQ*AST)
#define AKV_WORDS (AKT*AST)
#define AKV_STAGE_BYTES (4*AKV_WORDS*4)
#define ATT_SMEM_BYTES ((2*AQ_WORDS + 8*AKV_WORDS)*4)

__global__ void __launch_bounds__(256, 1)
fattn_kernel(const unsigned* __restrict__ qh, const unsigned* __restrict__ ql,
             const unsigned* __restrict__ kh, const unsigned* __restrict__ kl,
             const unsigned* __restrict__ vh, const unsigned* __restrict__ vl,
             unsigned* __restrict__ obh, unsigned* __restrict__ obl)
{
    extern __shared__ __align__(16) unsigned att_smem[];
    int b = blockIdx.z, h = blockIdx.y;
    int q0 = (gridDim.x - 1 - blockIdx.x) * ATQ;
    int hkv = h / GRP;
    int tid = threadIdx.x, wid = tid >> 5, lane = tid & 31;
    int gid = lane >> 2, tgid = lane & 3;
    int l15 = lane & 15, lHi8 = (lane >> 4) << 3;

    unsigned smemBase = (unsigned)__cvta_generic_to_shared(att_smem);
    unsigned qBaseH = smemBase;
    unsigned qBaseL = smemBase + AQ_WORDS * 4;
    unsigned kvBase0 = smemBase + 2 * AQ_WORDS * 4;

    #pragma unroll
    for (int p = 0; p < 16; p++) {
        int ci = tid + p * 256;
        int plane = ci >> 11, rem = ci & 2047;
        int row = rem >> 4, c = rem & 15;
        const unsigned* src = (plane ? ql : qh)
            + ((size_t)(b * SS + q0 + row) * HQ + h) * 64 + c * 4;
        unsigned dst = (plane ? qBaseL : qBaseH) + (row * AST + c * 4) * 4;
        cp16(dst, src, 16);
    }

    int ntiles = (q0 >> 6) + 2;
    auto fillKV = [&](int st, int j0) {
        unsigned base = kvBase0 + st * AKV_STAGE_BYTES;
        #pragma unroll
        for (int p = 0; p < 16; p++) {
            int ci = tid + p * 256;
            int plane = ci >> 10, rem = ci & 1023;
            int row = rem >> 4, c = rem & 15;
            const unsigned* gp = (plane & 2) ? ((plane & 1) ? vl : vh)
                                             : ((plane & 1) ? kl : kh);
            const unsigned* src = gp + ((size_t)(b * SS + j0 + row) * HKV + hkv) * 64 + c * 4;
            unsigned dst = base + plane * (AKV_WORDS * 4) + (row * AST + c * 4) * 4;
            cp16(dst, src, 16);
        }
        CP_COMMIT();
    };

    fillKV(0, 0);
    CP_WAIT0();
    __syncthreads();

    float oacc[16][4];
    #pragma unroll
    for (int i = 0; i < 16; i++)
        #pragma unroll
        for (int c = 0; c < 4; c++) oacc[i][c] = 0.f;
    float m0 = -1e30f, m1 = -1e30f, l0r = 0.f, l1r = 0.f;

    int rowbase = q0 + wid * 16;
    int kKey = (lane & 7) + ((lane >> 4) << 3);
    int kDimOff = (lane & 8) ? 8 : 0;

    for (int jt = 0;;) {
        int j0 = jt * AKT;
        if (jt + 1 < ntiles) fillKV((jt + 1) & 1, (jt + 1) * AKT);

        if (j0 <= rowbase + 15) {
            unsigned base = kvBase0 + (jt & 1) * AKV_STAGE_BYTES;
            unsigned kBaseH = base;
            unsigned kBaseL = base + AKV_WORDS * 4;
            unsigned vBaseH = base + 2 * AKV_WORDS * 4;
            unsigned vBaseL = base + 3 * AKV_WORDS * 4;

            float s[8][4];
            #pragma unroll
            for (int nf = 0; nf < 8; nf++)
                #pragma unroll
                for (int c = 0; c < 4; c++) s[nf][c] = 0.f;

            #pragma unroll
            for (int kt = 0; kt < 8; kt++) {
                unsigned qhf[4], qlf[4];
                unsigned qoff = (unsigned)((wid * 16 + l15) * (AST * 4) + (kt * 16 + lHi8) * 2);
                LDSM4(qhf[0], qhf[1], qhf[2], qhf[3], qBaseH + qoff);
                LDSM4(qlf[0], qlf[1], qlf[2], qlf[3], qBaseL + qoff);
                int kdd = kt * 16 + kDimOff;
                #pragma unroll
                for (int g2 = 0; g2 < 4; g2++) {
                    unsigned koff = (unsigned)((g2 * 16 + kKey) * (AST * 4) + kdd * 2);
                    unsigned kh0, kh1, kh2, kh3, klo0, klo1, klo2, klo3;
                    LDSM4(kh0, kh1, kh2, kh3, kBaseH + koff);
                    LDSM4(klo0, klo1, klo2, klo3, kBaseL + koff);
                    int n0 = 2 * g2, n1 = 2 * g2 + 1;
                    MMA_BF16(s[n0][0], s[n0][1], s[n0][2], s[n0][3],
                             qlf[0], qlf[1], qlf[2], qlf[3], kh0, kh1);
                    MMA_BF16(s[n0][0], s[n0][1], s[n0][2], s[n0][3],
                             qhf[0], qhf[1], qhf[2], qhf[3], klo0, klo1);
                    MMA_BF16(s[n0][0], s[n0][1], s[n0][2], s[n0][3],
                             qhf[0], qhf[1], qhf[2], qhf[3], kh0, kh1);
                    MMA_BF16(s[n1][0], s[n1][1], s[n1][2], s[n1][3],
                             qlf[0], qlf[1], qlf[2], qlf[3], kh2, kh3);
                    MMA_BF16(s[n1][0], s[n1][1], s[n1][2], s[n1][3],
                             qhf[0], qhf[1], qhf[2], qhf[3], klo2, klo3);
                    MMA_BF16(s[n1][0], s[n1][1], s[n1][2], s[n1][3],
                             qhf[0], qhf[1], qhf[2], qhf[3], kh2, kh3);
                }
            }

            int r0 = rowbase + gid, r1 = r0 + 8;
            if (j0 + AKT - 1 > rowbase) {
                #pragma unroll
                for (int nf = 0; nf < 8; nf++) {
                    int c0 = j0 + nf * 8 + 2 * tgid;
                    if (c0 > r0)     s[nf][0] = -1e30f;
                    if (c0 + 1 > r0) s[nf][1] = -1e30f;
                    if (c0 > r1)     s[nf][2] = -1e30f;
                    if (c0 + 1 > r1) s[nf][3] = -1e30f;
                }
            }

            float t0 = -1e30f, t1 = -1e30f;
            #pragma unroll
            for (int nf = 0; nf < 8; nf++) {
                t0 = fmaxf(t0, fmaxf(s[nf][0], s[nf][1]));
                t1 = fmaxf(t1, fmaxf(s[nf][2], s[nf][3]));
            }
            t0 = fmaxf(t0, __shfl_xor_sync(0xffffffffu, t0, 1));
            t0 = fmaxf(t0, __shfl_xor_sync(0xffffffffu, t0, 2));
            t1 = fmaxf(t1, __shfl_xor_sync(0xffffffffu, t1, 1));
            t1 = fmaxf(t1, __shfl_xor_sync(0xffffffffu, t1, 2));
            float mn0 = fmaxf(m0, t0), mn1 = fmaxf(m1, t1);
            float a0 = __expf(m0 - mn0), a1 = __expf(m1 - mn1);
            m0 = mn0; m1 = mn1;
            float rs0 = 0.f, rs1 = 0.f;
            #pragma unroll
            for (int nf = 0; nf < 8; nf++) {
                s[nf][0] = __expf(s[nf][0] - mn0);
                s[nf][1] = __expf(s[nf][1] - mn0);
                s[nf][2] = __expf(s[nf][2] - mn1);
                s[nf][3] = __expf(s[nf][3] - mn1);
                rs0 += s[nf][0] + s[nf][1];
                rs1 += s[nf][2] + s[nf][3];
            }
            rs0 += __shfl_xor_sync(0xffffffffu, rs0, 1);
            rs0 += __shfl_xor_sync(0xffffffffu, rs0, 2);
            rs1 += __shfl_xor_sync(0xffffffffu, rs1, 1);
            rs1 += __shfl_xor_sync(0xffffffffu, rs1, 2);
            l0r = l0r * a0 + rs0;
            l1r = l1r * a1 + rs1;
            #pragma unroll
            for (int nv = 0; nv < 16; nv++) {
                oacc[nv][0] *= a0; oacc[nv][1] *= a0;
                oacc[nv][2] *= a1; oacc[nv][3] *= a1;
            }

            #pragma unroll
            for (int t = 0; t < 4; t++) {
                unsigned ph[4], pl[4];
                split_pack(s[2 * t][0],     s[2 * t][1],     ph[0], pl[0]);
                split_pack(s[2 * t][2],     s[2 * t][3],     ph[1], pl[1]);
                split_pack(s[2 * t + 1][0], s[2 * t + 1][1], ph[2], pl[2]);
                split_pack(s[2 * t + 1][2], s[2 * t + 1][3], ph[3], pl[3]);
                unsigned vf[16][2];
                int krow = t * 16 + l15;
                #pragma unroll
                for (int np = 0; np < 8; np++) {
                    unsigned voff = (unsigned)(krow * (AST * 4) + (np * 16 + lHi8) * 2);
                    LDSM4T(vf[2 * np][0], vf[2 * np][1], vf[2 * np + 1][0], vf[2 * np + 1][1],
                           vBaseH + voff);
                }
                #pragma unroll
                for (int nv = 0; nv < 16; nv++) {
                    MMA_BF16(oacc[nv][0], oacc[nv][1], oacc[nv][2], oacc[nv][3],
                             pl[0], pl[1], pl[2], pl[3], vf[nv][0], vf[nv][1]);
                    MMA_BF16(oacc[nv][0], oacc[nv][1], oacc[nv][2], oacc[nv][3],
                             ph[0], ph[1], ph[2], ph[3], vf[nv][0], vf[nv][1]);
                }
                #pragma unroll
                for (int np = 0; np < 8; np++) {
                    unsigned voff = (unsigned)(krow * (AST * 4) + (np * 16 + lHi8) * 2);
                    LDSM4T(vf[2 * np][0], vf[2 * np][1], vf[2 * np + 1][0], vf[2 * np + 1][1],
                           vBaseL + voff);
                }
                #pragma unroll
                for (int nv = 0; nv < 16; nv++) {
                    MMA_BF16(oacc[nv][0], oacc[nv][1], oacc[nv][2], oacc[nv][3],
                             ph[0], ph[1], ph[2], ph[3], vf[nv][0], vf[nv][1]);
                }
            }
        }

        if (++jt == ntiles) break;
        CP_WAIT0();
        __syncthreads();
    }

    int r0 = rowbase + gid, r1 = r0 + 8;
    float il0 = 1.f / l0r, il1 = 1.f / l1r;
    #pragma unroll
    for (int nv = 0; nv < 16; nv++) {
        int col = nv * 8 + 2 * tgid;
        unsigned hw, lw;
        split_pack(oacc[nv][0] * il0, oacc[nv][1] * il0, hw, lw);
        size_t w0 = ((size_t)(b * SS + r0) * HQ + h) * 64 + col / 2;
        obh[w0] = hw; obl[w0] = lw;
        split_pack(oacc[nv][2] * il1, oacc[nv][3] * il1, hw, lw);
        size_t w1 = ((size_t)(b * SS + r1) * HQ + h) * 64 + col / 2;
        obh[w1] = hw; obl[w1] = lw;
    }
}

// ================= bf16x3 GEMM =================
#define BAST 20
#define BBST 68
#define GA_WORDS (128*BAST)
#define GB_WORDS (32*BBST)
#define GSTAGE_WORDS (2*GA_WORDS + 2*GB_WORDS)
#define GEMM_DSMEM (2*GSTAGE_WORDS*4)

__global__ void __launch_bounds__(256, 2)
bf16_gemm_kernel(const unsigned* __restrict__ AhG, const unsigned* __restrict__ AlG,
                 const unsigned* __restrict__ BhG, const unsigned* __restrict__ BlG,
                 float* __restrict__ C,
                 int M, int N, int K,
                 const int* __restrict__ aIdxg,
                 const int* __restrict__ cIdxg,
                 const int* __restrict__ cntg,
                 const float* __restrict__ combine,
                 size_t aZW, size_t bZW, int idxZ)
{
    extern __shared__ __align__(16) unsigned dsm[];
    int z = blockIdx.z;
    const unsigned* Ah = AhG + (size_t)z * aZW;
    const unsigned* Al = AlG + (size_t)z * aZW;
    const unsigned* Bh = BhG + (size_t)z * bZW;
    const unsigned* Bl = BlG + (size_t)z * bZW;
    const int* aIdx = aIdxg ? aIdxg + (size_t)z * idxZ : nullptr;
    const int* cIdx = cIdxg ? cIdxg + (size_t)z * idxZ : nullptr;
    int Meff = cntg ? min(M, cntg[z]) : M;
    int bm = blockIdx.y * 128;
    int bn = blockIdx.x * 128;
    if (bm >= Meff) return;
    int Kw = K >> 1, Nw = N >> 1, bnw = bn >> 1;

    int tid = threadIdx.x;
    int wid = tid >> 5, lane = tid & 31;
    int gid = lane >> 2, tgid = lane & 3;
    int wm = (wid & 3) * 32;
    int wn = (wid >> 2) * 64;
    int l15 = lane & 15, lHi8 = (lane >> 4) << 3;

    int am = tid >> 1, ac = (tid & 1) * 2;
    int gr = bm + am;
    int ar = (gr < Meff) ? (aIdx ? aIdx[gr] : gr) : 0;
    int aValid = (gr < Meff) ? 16 : 0;
    const unsigned* aRowH = Ah + (size_t)ar * Kw;
    const unsigned* aRowL = Al + (size_t)ar * Kw;
    int bk = tid >> 3, bc = (2 * tid) & 15;

    unsigned smemBase = (unsigned)__cvta_generic_to_shared(dsm);

    auto fillStage = [&](int st, int k0) {
        int kw0 = k0 >> 1;
        unsigned base = smemBase + st * (GSTAGE_WORDS * 4);
        unsigned aHb = base, aLb = base + GA_WORDS * 4;
        unsigned bHb = aLb + GA_WORDS * 4, bLb = bHb + GB_WORDS * 4;
        #pragma unroll
        for (int c2 = 0; c2 < 2; c2++) {
            int c = ac + c2;
            unsigned d = (am * BAST + c * 4) * 4;
            cp16(aHb + d, aRowH + kw0 + c * 4, aValid);
            cp16(aLb + d, aRowL + kw0 + c * 4, aValid);
        }
        size_t bro = (size_t)(k0 + bk) * Nw + bnw;
        #pragma unroll
        for (int c2 = 0; c2 < 2; c2++) {
            int c = bc + c2;
            unsigned d = (bk * BBST + c * 4) * 4;
            cp16(bHb + d, Bh + bro + c * 4, 16);
            cp16(bLb + d, Bl + bro + c * 4, 16);
        }
        CP_COMMIT();
    };

    float acc[2][8][4];
    #pragma unroll
    for (int i = 0; i < 2; i++)
        #pragma unroll
        for (int j = 0; j < 8; j++)
            #pragma unroll
            for (int c = 0; c < 4; c++) acc[i][j][c] = 0.f;

    int KT = K >> 5;
    fillStage(0, 0);
    CP_WAIT0();
    __syncthreads();

    for (int kt = 0;;) {
        if (kt + 1 < KT) fillStage((kt + 1) & 1, (kt + 1) << 5);

        unsigned base = smemBase + (kt & 1) * (GSTAGE_WORDS * 4);
        unsigned aBaseH = base, aBaseL = base + GA_WORDS * 4;
        unsigned bBaseH = aBaseL + GA_WORDS * 4, bBaseL = bBaseH + GB_WORDS * 4;

        #pragma unroll
        for (int ks = 0; ks < 2; ks++) {
            int kk = ks * 16;
            unsigned ah[2][4], al[2][4];
            #pragma unroll
            for (int mf = 0; mf < 2; mf++) {
                int mrow = wm + mf * 16 + l15;
                unsigned off = (unsigned)(mrow * (BAST * 4) + (kk + lHi8) * 2);
                LDSM4(ah[mf][0], ah[mf][1], ah[mf][2], ah[mf][3], aBaseH + off);
                LDSM4(al[mf][0], al[mf][1], al[mf][2], al[mf][3], aBaseL + off);
            }
            unsigned bfr[8][2];
            int krow = kk + l15;
            #pragma unroll
            for (int nfp = 0; nfp < 4; nfp++) {
                int ncol = wn + nfp * 16 + lHi8;
                unsigned off = (unsigned)(krow * (BBST * 4) + ncol * 2);
                LDSM4T(bfr[2 * nfp][0], bfr[2 * nfp][1],
                       bfr[2 * nfp + 1][0], bfr[2 * nfp + 1][1], bBaseH + off);
            }
            #pragma unroll
            for (int mf = 0; mf < 2; mf++)
                #pragma unroll
                for (int nf = 0; nf < 8; nf++) {
                    MMA_BF16(acc[mf][nf][0], acc[mf][nf][1], acc[mf][nf][2], acc[mf][nf][3],
                             ah[mf][0], ah[mf][1], ah[mf][2], ah[mf][3],
                             bfr[nf][0], bfr[nf][1]);
                    MMA_BF16(acc[mf][nf][0], acc[mf][nf][1], acc[mf][nf][2], acc[mf][nf][3],
                             al[mf][0], al[mf][1], al[mf][2], al[mf][3],
                             bfr[nf][0], bfr[nf][1]);
                }
            #pragma unroll
            for (int nfp = 0; nfp < 4; nfp++) {
                int ncol = wn + nfp * 16 + lHi8;
                unsigned off = (unsigned)(krow * (BBST * 4) + ncol * 2);
                LDSM4T(bfr[2 * nfp][0], bfr[2 * nfp][1],
                       bfr[2 * nfp + 1][0], bfr[2 * nfp + 1][1], bBaseL + off);
            }
            #pragma unroll
            for (int mf = 0; mf < 2; mf++)
                #pragma unroll
                for (int nf = 0; nf < 8; nf++) {
                    MMA_BF16(acc[mf][nf][0], acc[mf][nf][1], acc[mf][nf][2], acc[mf][nf][3],
                             ah[mf][0], ah[mf][1], ah[mf][2], ah[mf][3],
                             bfr[nf][0], bfr[nf][1]);
                }
        }

        if (++kt == KT) break;
        CP_WAIT0();
        __syncthreads();
    }

    #pragma unroll
    for (int mf = 0; mf < 2; mf++) {
        #pragma unroll
        for (int half = 0; half < 2; half++) {
            int row = bm + wm + mf * 16 + gid + half * 8;
            if (row >= Meff) continue;
            int crow = cIdx ? cIdx[row] : row;
            float w = 1.f;
            if (combine) w = combine[crow * EE + z];
            #pragma unroll
            for (int nf = 0; nf < 8; nf++) {
                int col = bn + wn + nf * 8 + 2 * tgid;
                float v0 = acc[mf][nf][half * 2 + 0];
                float v1 = acc[mf][nf][half * 2 + 1];
                float* cp = C + (size_t)crow * N + col;
                if (combine) {
                    atomicAdd(cp, w * v0);
                    atomicAdd(cp + 1, w * v1);
                } else {
                    cp[0] = v0;
                    cp[1] = v1;
                }
            }
        }
    }
}

// ========== gated dual-B bf16x3 GEMM ==========
__global__ void __launch_bounds__(256, 2)
bf16_gated_kernel(const unsigned* __restrict__ Ah, const unsigned* __restrict__ Al,
                  const unsigned* __restrict__ B0hG, const unsigned* __restrict__ B0lG,
                  const unsigned* __restrict__ B1hG, const unsigned* __restrict__ B1lG,
                  unsigned* __restrict__ ChG, unsigned* __restrict__ ClG,
                  int M, int Nout, int K,
                  const int* __restrict__ aIdxg,
                  const int* __restrict__ cntg,
                  size_t bZW, size_t cZW, int idxZ)
{
    extern __shared__ __align__(16) unsigned dsm[];
    int z = blockIdx.z;
    const unsigned* B0h = B0hG + (size_t)z * bZW;
    const unsigned* B0l = B0lG + (size_t)z * bZW;
    const unsigned* B1h = B1hG + (size_t)z * bZW;
    const unsigned* B1l = B1lG + (size_t)z * bZW;
    unsigned* Ch = ChG + (size_t)z * cZW;
    unsigned* Cl = ClG + (size_t)z * cZW;
    const int* aIdx = aIdxg ? aIdxg + (size_t)z * idxZ : nullptr;
    int Meff = cntg ? min(M, cntg[z]) : M;
    int bm = blockIdx.y * 128;
    int bnn = blockIdx.x * 64;
    if (bm >= Meff) return;
    int Kw = K >> 1, Nw = Nout >> 1, bnw = bnn >> 1;

    int tid = threadIdx.x;
    int wid = tid >> 5, lane = tid & 31;
    int gid = lane >> 2, tgid = lane & 3;
    int wm = (wid & 3) * 32;
    int wn32 = (wid >> 2) * 32;
    int l15 = lane & 15, lHi8 = (lane >> 4) << 3;

    int am = tid >> 1, ac = (tid & 1) * 2;
    int gr = bm + am;
    int ar = (gr < Meff) ? (aIdx ? aIdx[gr] : gr) : 0;
    int aValid = (gr < Meff) ? 16 : 0;
    const unsigned* aRowH = Ah + (size_t)ar * Kw;
    const unsigned* aRowL = Al + (size_t)ar * Kw;
    int bk = tid >> 3;
    int brest = (2 * tid) & 15;

    unsigned smemBase = (unsigned)__cvta_generic_to_shared(dsm);

    auto fillStage = [&](int st, int k0) {
        int kw0 = k0 >> 1;
        unsigned base = smemBase + st * (GSTAGE_WORDS * 4);
        unsigned aHb = base, aLb = base + GA_WORDS * 4;
        unsigned bHb = aLb + GA_WORDS * 4, bLb = bHb + GB_WORDS * 4;
        #pragma unroll
        for (int c2 = 0; c2 < 2; c2++) {
            int c = ac + c2;
            unsigned d = (am * BAST + c * 4) * 4;
            cp16(aHb + d, aRowH + kw0 + c * 4, aValid);
            cp16(aLb + d, aRowL + kw0 + c * 4, aValid);
        }
        size_t bro = (size_t)(k0 + bk) * Nw + bnw;
        #pragma unroll
        for (int c2 = 0; c2 < 2; c2++) {
            int cc = brest + c2;
            int srcSel = cc >> 3, c = cc & 7;
            unsigned d = (bk * BBST + srcSel * 32 + c * 4) * 4;
            cp16(bHb + d, (srcSel ? B1h : B0h) + bro + c * 4, 16);
            cp16(bLb + d, (srcSel ? B1l : B0l) + bro + c * 4, 16);
        }
        CP_COMMIT();
    };

    float acc0[2][4][4], acc1[2][4][4];
    #pragma unroll
    for (int i = 0; i < 2; i++)
        #pragma unroll
        for (int j = 0; j < 4; j++)
            #pragma unroll
            for (int c = 0; c < 4; c++) { acc0[i][j][c] = 0.f; acc1[i][j][c] = 0.f; }

    int KT = K >> 5;
    fillStage(0, 0);
    CP_WAIT0();
    __syncthreads();

    for (int kt = 0;;) {
        if (kt + 1 < KT) fillStage((kt + 1) & 1, (kt + 1) << 5);

        unsigned base = smemBase + (kt & 1) * (GSTAGE_WORDS * 4);
        unsigned aBaseH = base, aBaseL = base + GA_WORDS * 4;
        unsigned bBaseH = aBaseL + GA_WORDS * 4, bBaseL = bBaseH + GB_WORDS * 4;

        #pragma unroll
        for (int ks = 0; ks < 2; ks++) {
            int kk = ks * 16;
            unsigned ah[2][4], al[2][4];
            #pragma unroll
            for (int mf = 0; mf < 2; mf++) {
                int mrow = wm + mf * 16 + l15;
                unsigned off = (unsigned)(mrow * (BAST * 4) + (kk + lHi8) * 2);
                LDSM4(ah[mf][0], ah[mf][1], ah[mf][2], ah[mf][3], aBaseH + off);
                LDSM4(al[mf][0], al[mf][1], al[mf][2], al[mf][3], aBaseL + off);
            }
            int krow = kk + l15;
            #pragma unroll
            for (int which = 0; which < 2; which++) {
                unsigned bfr[4][2];
                int colbase = which * 64 + wn32;
                #pragma unroll
                for (int nfp = 0; nfp < 2; nfp++) {
                    int ncol = colbase + nfp * 16 + lHi8;
                    unsigned off = (unsigned)(krow * (BBST * 4) + ncol * 2);
                    LDSM4T(bfr[2 * nfp][0], bfr[2 * nfp][1],
                           bfr[2 * nfp + 1][0], bfr[2 * nfp + 1][1], bBaseH + off);
                }
                #pragma unroll
                for (int mf = 0; mf < 2; mf++)
                    #pragma unroll
                    for (int nf = 0; nf < 4; nf++) {
                        float* a = which ? acc1[mf][nf] : acc0[mf][nf];
                        MMA_BF16(a[0], a[1], a[2], a[3],
                                 ah[mf][0], ah[mf][1], ah[mf][2], ah[mf][3],
                                 bfr[nf][0], bfr[nf][1]);
                        MMA_BF16(a[0], a[1], a[2], a[3],
                                 al[mf][0], al[mf][1], al[mf][2], al[mf][3],
                                 bfr[nf][0], bfr[nf][1]);
                    }
                #pragma unroll
                for (int nfp = 0; nfp < 2; nfp++) {
                    int ncol = colbase + nfp * 16 + lHi8;
                    unsigned off = (unsigned)(krow * (BBST * 4) + ncol * 2);
                    LDSM4T(bfr[2 * nfp][0], bfr[2 * nfp][1],
                           bfr[2 * nfp + 1][0], bfr[2 * nfp + 1][1], bBaseL + off);
                }
                #pragma unroll
                for (int mf = 0; mf < 2; mf++)
                    #pragma unroll
                    for (int nf = 0; nf < 4; nf++) {
                        float* a = which ? acc1[mf][nf] : acc0[mf][nf];
                        MMA_BF16(a[0], a[1], a[2], a[3],
                                 ah[mf][0], ah[mf][1], ah[mf][2], ah[mf][3],
                                 bfr[nf][0], bfr[nf][1]);
                    }
            }
        }

        if (++kt == KT) break;
        CP_WAIT0();
        __syncthreads();
    }

    #pragma unroll
    for (int mf = 0; mf < 2; mf++) {
        #pragma unroll
        for (int half = 0; half < 2; half++) {
            int row = bm + wm + mf * 16 + gid + half * 8;
            if (row >= Meff) continue;
            #pragma unroll
            for (int nf = 0; nf < 4; nf++) {
                int col = bnn + wn32 + nf * 8 + 2 * tgid;
                float g0v = gelu_tanh(acc0[mf][nf][half * 2 + 0]) * acc1[mf][nf][half * 2 + 0];
                float g1v = gelu_tanh(acc0[mf][nf][half * 2 + 1]) * acc1[mf][nf][half * 2 + 1];
                unsigned hw, lw;
                split_pack(g0v, g1v, hw, lw);
                size_t w = (size_t)row * Nw + (col >> 1);
                Ch[w] = hw; Cl[w] = lw;
            }
        }
    }
}

// ---------------- router ----------------
__global__ void router_kernel(const float* __restrict__ gin,
                              const float* __restrict__ wg,
                              float* __restrict__ combine,
                              int* __restrict__ cnt,
                              int* __restrict__ idx,
                              float* __restrict__ psum)
{
    int tok = blockIdx.x;
    int tid = threadIdx.x;
    float s[EE] = {};
    const float* g = gin + (size_t)tok * DD;
    for (int d = tid; d < DD; d += 256) {
        float gv = g[d];
        const float* w = wg + d * EE;
        #pragma unroll
        for (int e = 0; e < EE; e++) s[e] += gv * w[e];
    }
    __shared__ float sh[256][EE];
    #pragma unroll
    for (int e = 0; e < EE; e++) sh[tid][e] = s[e];
    __syncthreads();
    for (int str = 128; str > 0; str >>= 1) {
        if (tid < str) {
            #pragma unroll
            for (int e = 0; e < EE; e++) sh[tid][e] += sh[tid + str][e];
        }
        __syncthreads();
    }
    if (tid == 0) {
        float pe[EE];
        float mx = -FLT_MAX;
        #pragma unroll
        for (int e = 0; e < EE; e++) mx = fmaxf(mx, sh[0][e]);
        float sum = 0.f;
        #pragma unroll
        for (int e = 0; e < EE; e++) { pe[e] = expf(sh[0][e] - mx); sum += pe[e]; }
        float inv = 1.0f / sum;
        #pragma unroll
        for (int e = 0; e < EE; e++) { pe[e] *= inv; atomicAdd(&psum[e], pe[e]); }
        int i0 = 0;
        #pragma unroll
        for (int e = 1; e < EE; e++) if (pe[e] > pe[i0]) i0 = e;
        int i1 = (i0 == 0) ? 1 : 0;
        #pragma unroll
        for (int e = 0; e < EE; e++) if (e != i0 && e != i1 && pe[e] > pe[i1]) i1 = e;
        float tot = pe[i0] + pe[i1];
        float w0 = pe[i0] / tot, w1 = pe[i1] / tot;
        float* crow = combine + (size_t)tok * EE;
        #pragma unroll
        for (int e = 0; e < EE; e++) crow[e] = 0.f;
        crow[i0] = w0; crow[i1] = w1;
        int p0 = atomicAdd(&cnt[i0], 1); idx[i0 * TT + p0] = tok;
        int p1 = atomicAdd(&cnt[i1], 1); idx[i1 * TT + p1] = tok;
    }
}

__global__ void lb_kernel(const int* __restrict__ cnt, const float* __restrict__ psum,
                          float* __restrict__ out)
{
    float lb = 0.f;
    #pragma unroll
    for (int e = 0; e < EE; e++)
        lb += ((float)cnt[e] / (float)TT) * (psum[e] / (float)TT);
    out[0] = lb * ((float)(EE * EE) / (float)EE);
}

// ==================== host launcher ====================
extern "C" void kernel_launch(void* const* d_in, const int* in_sizes, int n_in,
                              void* d_out, int out_size)
{
    const int*   positions       = (const int*)  d_in[0];
    const float* x               = (const float*)d_in[1];
    const float* pre_attn_scale  = (const float*)d_in[2];
    const float* wq              = (const float*)d_in[3];
    const float* wk              = (const float*)d_in[4];
    const float* wv              = (const float*)d_in[5];
    const float* wo              = (const float*)d_in[6];
    const float* q_norm_scale    = (const float*)d_in[7];
    const float* k_norm_scale    = (const float*)d_in[8];
    const float* v_norm_scale    = (const float*)d_in[9];
    const float* post_attn_scale = (const float*)d_in[10];
    const float* pre_ffw_scale   = (const float*)d_in[11];
    const float* shared_wi0      = (const float*)d_in[12];
    const float* shared_wi1      = (const float*)d_in[13];
    const float* shared_wo       = (const float*)d_in[14];
    const float* post_ff1_scale  = (const float*)d_in[15];
    const float* pre_ff2_scale   = (const float*)d_in[16];
    const float* router_scale    = (const float*)d_in[17];
    const float* w_gate          = (const float*)d_in[18];
    const float* ewi0            = (const float*)d_in[19];
    const float* ewi1            = (const float*)d_in[20];
    const float* ewo             = (const float*)d_in[21];
    const float* post_ff2_scale  = (const float*)d_in[22];
    const float* layer_scalar    = (const float*)d_in[23];
    float* out = (float*)d_out;

    static cudaStream_t s2 = nullptr;
    static cudaEvent_t evFork = nullptr, evJoin = nullptr;
    static int inited = 0;
    if (!inited) {
        cudaFuncSetAttribute(fattn_kernel,
                             cudaFuncAttributeMaxDynamicSharedMemorySize, ATT_SMEM_BYTES);
        cudaFuncSetAttribute(bf16_gemm_kernel,
                             cudaFuncAttributeMaxDynamicSharedMemorySize, GEMM_DSMEM);
        cudaFuncSetAttribute(bf16_gated_kernel,
                             cudaFuncAttributeMaxDynamicSharedMemorySize, GEMM_DSMEM);
        cudaStreamCreateWithFlags(&s2, cudaStreamNonBlocking);
        cudaEventCreateWithFlags(&evFork, cudaEventDisableTiming);
        cudaEventCreateWithFlags(&evJoin, cudaEventDisableTiming);
        inited = 1;
    }

    float* sc = nullptr;
    int*   isc = nullptr;
    cudaGetSymbolAddress((void**)&sc, g_scratch);
    cudaGetSymbolAddress((void**)&isc, g_iscratch);

    unsigned* U = (unsigned*)sc;
    auto uptr = [&](size_t off) { return U + off; };

    unsigned* lnxH = uptr(OFF_LNXH); unsigned* lnxL = uptr(OFF_LNXL);
    float* qkvf = sc + OFF_QKVF;
    unsigned* qsh = uptr(OFF_QH); unsigned* qsl = uptr(OFF_QL);
    unsigned* ksh = uptr(OFF_KH); unsigned* ksl = uptr(OFF_KL);
    unsigned* vsh = uptr(OFF_VH); unsigned* vsl = uptr(OFF_VL);
    unsigned* obh = uptr(OFF_OBH); unsigned* obl = uptr(OFF_OBL);
    float* attnb = sc + OFF_ATTN; float* hb = sc + OFF_H;
    unsigned* ffinH = uptr(OFF_FFINH); unsigned* ffinL = uptr(OFF_FFINL);
    unsigned* g0H = uptr(OFF_G0H); unsigned* g0L = uptr(OFF_G0L);
    float* shb = sc + OFF_SHB;
    unsigned* rinH = uptr(OFF_RINH); unsigned* rinL = uptr(OFF_RINL);
    float* gin = sc + OFF_GIN; float* routb = sc + OFF_ROUT;
    unsigned* egH = uptr(OFF_EGH); unsigned* egL = uptr(OFF_EGL);
    float* comb = sc + OFF_COMB; float* psum = sc + OFF_PSUM;
    int* idx = isc; int* cnt = isc + EE * TT;

    auto splitBF = [&](const float* src, size_t nElts, size_t offH, size_t offL,
                       cudaStream_t st) {
        size_t nQ = nElts / 4;
        split_bf_kernel<<<(unsigned)((nQ + 255) / 256), 256, 0, st>>>(
            (const float4*)src, (uint2*)uptr(offH), (uint2*)uptr(offL), nQ);
    };

    // QKV concat split on main stream (needed at step 2)
    split_qkv_kernel<<<(unsigned)(SZ_WQKV / 4 / 256), 256>>>(
        wq, wk, wv, (uint2*)uptr(OFF_WQKVH), (uint2*)uptr(OFF_WQKVL));

    // Remaining weight splits forked to s2, overlapping steps 1-4
    cudaEventRecord(evFork, 0);
    cudaStreamWaitEvent(s2, evFork, 0);
    splitBF(wo, SZ_WQ, OFF_WOH, OFF_WOL, s2);
    splitBF(shared_wi0, SZ_WFF, OFF_WI0H, OFF_WI0L, s2);
    splitBF(shared_wi1, SZ_WFF, OFF_WI1H, OFF_WI1L, s2);
    splitBF(shared_wo, SZ_WFF, OFF_SWOH, OFF_SWOL, s2);
    splitBF(ewi0, SZ_EW, OFF_EWI0H, OFF_EWI0L, s2);
    splitBF(ewi1, SZ_EW, OFF_EWI1H, OFF_EWI1L, s2);
    splitBF(ewo, SZ_EW, OFF_EWOH, OFF_EWOL, s2);
    cudaEventRecord(evJoin, s2);

    auto gemm = [&](const unsigned* Ah, const unsigned* Al,
                    size_t BhOff, size_t BlOff, float* C, int M, int N, int K,
                    const int* aI, const int* cI, const int* ct, const float* cw,
                    size_t aZW, size_t bZW, int nz) {
        dim3 grid(N / 128, (M + 127) / 128, nz);
        bf16_gemm_kernel<<<grid, 256, GEMM_DSMEM>>>(Ah, Al, uptr(BhOff), uptr(BlOff),
                                                    C, M, N, K, aI, cI, ct, cw,
                                                    aZW, bZW, TT);
    };

    // 1) pre-attn norm
    rms_kernel<<<TT, 256>>>(x, pre_attn_scale, 1.f, nullptr, nullptr, nullptr,
                            nullptr, lnxH, lnxL);
    // 2) fused QKV projection
    gemm(lnxH, lnxL, OFF_WQKVH, OFF_WQKVL, qkvf, TT, NQKV, DD,
         nullptr, nullptr, nullptr, nullptr, 0, 0, 1);
    // 3) per-head norms + rope
    head_norm_rope_kernel<<<TT * HQ, HD>>>(qkvf, NQKV, 0, qsh, qsl,
                                           q_norm_scale, positions, HQ, 1);
    head_norm_rope_kernel<<<TT * HKV, HD>>>(qkvf, NQKV, 2048, ksh, ksl,
                                            k_norm_scale, positions, HKV, 1);
    head_norm_rope_kernel<<<TT * HKV, HD>>>(qkvf, NQKV, 3072, vsh, vsl,
                                            v_norm_scale, positions, HKV, 0);
    // 4) attention
    {
        dim3 grid(SS / ATQ, HQ, BB);
        fattn_kernel<<<grid, 256, ATT_SMEM_BYTES>>>(qsh, qsl, ksh, ksl, vsh, vsl, obh, obl);
    }
    // join: all s2 weight splits must be done before wo GEMM
    cudaStreamWaitEvent(0, evJoin, 0);
    // 5) output projection + post-attn norm + residual
    gemm(obh, obl, OFF_WOH, OFF_WOL, attnb, TT, DD, HQ * HD,
         nullptr, nullptr, nullptr, nullptr, 0, 0, 1);
    rms_kernel<<<TT, 256>>>(attnb, post_attn_scale, 1.f, x, nullptr, nullptr,
                            hb, nullptr, nullptr);
    // 6) shared FFN
    rms_kernel<<<TT, 256>>>(hb, pre_ffw_scale, 1.f, nullptr, nullptr, nullptr,
                            nullptr, ffinH, ffinL);
    {
        dim3 grid(FS / 64, TT / 128, 1);
        bf16_gated_kernel<<<grid, 256, GEMM_DSMEM>>>(
            ffinH, ffinL, uptr(OFF_WI0H), uptr(OFF_WI0L), uptr(OFF_WI1H), uptr(OFF_WI1L),
            g0H, g0L, TT, FS, DD, nullptr, nullptr, 0, 0, TT);
    }
    gemm(g0H, g0L, OFF_SWOH, OFF_SWOL, shb, TT, DD, FS,
         nullptr, nullptr, nullptr, nullptr, 0, 0, 1);
    rms_kernel<<<TT, 256>>>(shb, post_ff1_scale, 1.f, nullptr, nullptr, nullptr,
                            shb, nullptr, nullptr);
    // 7) router inputs (fused dual RMS)
    rms_dual_kernel<<<TT, 256>>>(hb, pre_ff2_scale, rinH, rinL,
                                 router_scale, 0.02209708691207961f, gin);
    // 8) router + batched MoE
    cudaMemsetAsync(cnt, 0, EE * sizeof(int));
    cudaMemsetAsync(psum, 0, EE * sizeof(float));
    cudaMemsetAsync(routb, 0, SZ_TD * sizeof(float));
    router_kernel<<<TT, 256>>>(gin, w_gate, comb, cnt, idx, psum);
    {
        dim3 grid(FE / 64, TT / 128, EE);
        bf16_gated_kernel<<<grid, 256, GEMM_DSMEM>>>(
            rinH, rinL, uptr(OFF_EWI0H), uptr(OFF_EWI0L), uptr(OFF_EWI1H), uptr(OFF_EWI1L),
            egH, egL, TT, FE, DD, idx, cnt,
            (size_t)DD * FE / 2, (size_t)TT * FE / 2, TT);
    }
    {
        dim3 grid(DD / 128, TT / 128, EE);
        bf16_gemm_kernel<<<grid, 256, GEMM_DSMEM>>>(
            egH, egL, uptr(OFF_EWOH), uptr(OFF_EWOL), routb, TT, DD, FE,
            nullptr, idx, cnt, comb,
            (size_t)TT * FE / 2, (size_t)FE * DD / 2, TT);
    }
    // 9) final combine
    rms_kernel<<<TT, 256>>>(routb, post_ff2_scale, 1.f, shb, hb, layer_scalar,
                            out, nullptr, nullptr);
    // 10) lb loss
    if (out_size > TT * DD) {
        lb_kernel<<<1, 1>>>(cnt, psum, out + (size_t)TT * DD);
    }
}

// round 16
// speedup vs baseline: 1.0995x; 1.0594x over previous
#include <cuda_runtime.h>
#include <cuda_bf16.h>
#include <cfloat>
#include <math.h>

#define BB 4
#define SS 1024
#define DD 2048
#define HQ 16
#define HKV 8
#define HD 128
#define GRP 2
#define EE 8
#define FE 1024
#define FS 8192
#define TT (BB*SS)
#define EPS 1e-6f
#define NQKV 4096

#define SZ_TD   ((size_t)TT*DD)
#define SZ_TQ   ((size_t)TT*HQ*HD)
#define SZ_TKV  ((size_t)TT*HKV*HD)
#define SZ_TFS  ((size_t)TT*FS)

#define OFF_LNXH  ((size_t)0)
#define OFF_LNXL  (OFF_LNXH + SZ_TD/2)
#define OFF_QKVF  (OFF_LNXL + SZ_TD/2)
#define OFF_QH    (OFF_QKVF + (size_t)TT*NQKV)
#define OFF_QL    (OFF_QH   + SZ_TQ/2)
#define OFF_KH    (OFF_QL   + SZ_TQ/2)
#define OFF_KL    (OFF_KH   + SZ_TKV/2)
#define OFF_VH    (OFF_KL   + SZ_TKV/2)
#define OFF_VL    (OFF_VH   + SZ_TKV/2)
#define OFF_OBH   (OFF_VL   + SZ_TKV/2)
#define OFF_OBL   (OFF_OBH  + SZ_TQ/2)
#define OFF_ATTN  (OFF_OBL  + SZ_TQ/2)
#define OFF_H     (OFF_ATTN + SZ_TD)
#define OFF_FFINH (OFF_H    + SZ_TD)
#define OFF_FFINL (OFF_FFINH+ SZ_TD/2)
#define OFF_G0H   (OFF_FFINL+ SZ_TD/2)
#define OFF_G0L   (OFF_G0H  + SZ_TFS/2)
#define OFF_SHB   (OFF_G0L  + SZ_TFS/2)
#define OFF_RINH  (OFF_SHB  + SZ_TD)
#define OFF_RINL  (OFF_RINH + SZ_TD/2)
#define OFF_GIN   (OFF_RINL + SZ_TD/2)
#define OFF_ROUT  (OFF_GIN  + SZ_TD)
#define OFF_EGH   (OFF_ROUT + SZ_TD)
#define OFF_EGL   (OFF_EGH  + SZ_TFS/2)
#define OFF_COMB  (OFF_EGL  + SZ_TFS/2)
#define OFF_PSUM  (OFF_COMB + (size_t)TT*EE)
#define SZ_WQKV ((size_t)DD*NQKV)
#define SZ_WQ  ((size_t)DD*HQ*HD)
#define SZ_WFF ((size_t)DD*FS)
#define SZ_EW  ((size_t)EE*DD*FE)
#define OFF_WQKVH (OFF_PSUM + 8)
#define OFF_WQKVL (OFF_WQKVH + SZ_WQKV/2)
#define OFF_WOH   (OFF_WQKVL + SZ_WQKV/2)
#define OFF_WOL   (OFF_WOH + SZ_WQ/2)
#define OFF_WI0H  (OFF_WOL + SZ_WQ/2)
#define OFF_WI0L  (OFF_WI0H + SZ_WFF/2)
#define OFF_WI1H  (OFF_WI0L + SZ_WFF/2)
#define OFF_WI1L  (OFF_WI1H + SZ_WFF/2)
#define OFF_SWOH  (OFF_WI1L + SZ_WFF/2)
#define OFF_SWOL  (OFF_SWOH + SZ_WFF/2)
#define OFF_EWI0H (OFF_SWOL + SZ_WFF/2)
#define OFF_EWI0L (OFF_EWI0H + SZ_EW/2)
#define OFF_EWI1H (OFF_EWI0L + SZ_EW/2)
#define OFF_EWI1L (OFF_EWI1H + SZ_EW/2)
#define OFF_EWOH  (OFF_EWI1L + SZ_EW/2)
#define OFF_EWOL  (OFF_EWOH + SZ_EW/2)
#define SCRATCH_TOTAL (OFF_EWOL + SZ_EW/2)

__device__ float g_scratch[SCRATCH_TOTAL];
__device__ int   g_iscratch[EE*TT + EE];

__device__ __forceinline__ float gelu_tanh(float v) {
    const float c = 0.7978845608028654f;
    float u = c * (v + 0.044715f * v * v * v);
    return 0.5f * v * (1.0f + tanhf(u));
}
__device__ __forceinline__ unsigned pack_bf16(float x, float y) {
    __nv_bfloat162 t = __floats2bfloat162_rn(x, y);
    return *reinterpret_cast<unsigned*>(&t);
}
__device__ __forceinline__ void split_pack(float x, float y,
                                           unsigned &hiW, unsigned &loW0) {
    __nv_bfloat16 bx = __float2bfloat16_rn(x);
    __nv_bfloat16 by = __float2bfloat16_rn(y);
    float hx = __bfloat162float(bx);
    float hy = __bfloat162float(by);
    __nv_bfloat162 h2; h2.x = bx; h2.y = by;
    hiW = *reinterpret_cast<unsigned*>(&h2);
    loW0 = pack_bf16(x - hx, y - hy);
}
__device__ __forceinline__ void cp16(unsigned dst, const void* src, int srcBytes) {
    asm volatile("cp.async.cg.shared.global [%0], [%1], 16, %2;"
                 :: "r"(dst), "l"(src), "r"(srcBytes));
}
#define CP_COMMIT() asm volatile("cp.async.commit_group;")
#define CP_WAIT0()  asm volatile("cp.async.wait_group 0;")

#define LDSM4(r0,r1,r2,r3,addr) \
    asm volatile("ldmatrix.sync.aligned.m8n8.x4.shared.b16 {%0,%1,%2,%3}, [%4];" \
                 : "=r"(r0),"=r"(r1),"=r"(r2),"=r"(r3) : "r"(addr))
#define LDSM4T(r0,r1,r2,r3,addr) \
    asm volatile("ldmatrix.sync.aligned.m8n8.x4.trans.shared.b16 {%0,%1,%2,%3}, [%4];" \
                 : "=r"(r0),"=r"(r1),"=r"(r2),"=r"(r3) : "r"(addr))
#define MMA_BF16(d0,d1,d2,d3,a0,a1,a2,a3,b0,b1) \
    asm volatile("mma.sync.aligned.m16n8k16.row.col.f32.bf16.bf16.f32 " \
                 "{%0,%1,%2,%3}, {%4,%5,%6,%7}, {%8,%9}, {%0,%1,%2,%3};" \
                 : "+f"(d0),"+f"(d1),"+f"(d2),"+f"(d3) \
                 : "r"(a0),"r"(a1),"r"(a2),"r"(a3),"r"(b0),"r"(b1))

// ---------------- splits (vectorized) ----------------
__global__ void split_bf_kernel(const float4* __restrict__ in,
                                uint2* __restrict__ hi,
                                uint2* __restrict__ lo, size_t nQuads)
{
    size_t i = (size_t)blockIdx.x * 256 + threadIdx.x;
    if (i < nQuads) {
        float4 v = in[i];
        uint2 h, l;
        split_pack(v.x, v.y, h.x, l.x);
        split_pack(v.z, v.w, h.y, l.y);
        hi[i] = h; lo[i] = l;
    }
}
__global__ void split_qkv_kernel(const float* __restrict__ wq,
                                 const float* __restrict__ wk,
                                 const float* __restrict__ wv,
                                 uint2* __restrict__ hi,
                                 uint2* __restrict__ lo)
{
    size_t q = (size_t)blockIdx.x * 256 + threadIdx.x;
    if (q >= (size_t)DD * (NQKV / 4)) return;
    int d = (int)(q / (NQKV / 4));
    int n0 = 4 * (int)(q % (NQKV / 4));
    float4 v;
    if (n0 < 2048)      v = *(const float4*)(wq + (size_t)d * 2048 + n0);
    else if (n0 < 3072) v = *(const float4*)(wk + (size_t)d * 1024 + (n0 - 2048));
    else                v = *(const float4*)(wv + (size_t)d * 1024 + (n0 - 3072));
    uint2 h, l;
    split_pack(v.x, v.y, h.x, l.x);
    split_pack(v.z, v.w, h.y, l.y);
    hi[q] = h; lo[q] = l;
}

// ---------------- RMS norm ----------------
__global__ void rms_kernel(const float* __restrict__ in,
                           const float* __restrict__ scale, float cmul,
                           const float* __restrict__ res1,
                           const float* __restrict__ res2,
                           const float* __restrict__ scalarPtr,
                           float* __restrict__ out,
                           unsigned* __restrict__ outH,
                           unsigned* __restrict__ outL)
{
    int row = blockIdx.x;
    int tid = threadIdx.x;
    const float* xr = in + (size_t)row * DD;
    float ss = 0.f;
    for (int d = tid; d < DD; d += 256) { float v = xr[d]; ss += v * v; }
    for (int o = 16; o > 0; o >>= 1) ss += __shfl_xor_sync(0xffffffffu, ss, o);
    __shared__ float wsum[8];
    if ((tid & 31) == 0) wsum[tid >> 5] = ss;
    __syncthreads();
    float tot = 0.f;
    #pragma unroll
    for (int w = 0; w < 8; w++) tot += wsum[w];
    float inv = rsqrtf(tot * (1.0f / DD) + EPS);
    float sc = scalarPtr ? *scalarPtr : 1.0f;
    if (outH) {
        for (int d = 2 * tid; d < DD; d += 512) {
            float y0 = xr[d] * inv, y1 = xr[d + 1] * inv;
            if (scale) { y0 *= scale[d]; y1 *= scale[d + 1]; }
            y0 *= cmul; y1 *= cmul;
            unsigned h, l;
            split_pack(y0, y1, h, l);
            size_t w = (size_t)row * (DD / 2) + d / 2;
            outH[w] = h; outL[w] = l;
        }
    } else {
        for (int d = tid; d < DD; d += 256) {
            float y = xr[d] * inv;
            if (scale) y *= scale[d];
            y *= cmul;
            if (res1) y += res1[(size_t)row * DD + d];
            if (res2) y += res2[(size_t)row * DD + d];
            out[(size_t)row * DD + d] = y * sc;
        }
    }
}

// ---------------- dual RMS ----------------
__global__ void rms_dual_kernel(const float* __restrict__ in,
                                const float* __restrict__ scaleA,
                                unsigned* __restrict__ outAH,
                                unsigned* __restrict__ outAL,
                                const float* __restrict__ scaleB,
                                float cmulB,
                                float* __restrict__ outB)
{
    int row = blockIdx.x;
    int tid = threadIdx.x;
    const float* xr = in + (size_t)row * DD;
    float ss = 0.f;
    for (int d = tid; d < DD; d += 256) { float v = xr[d]; ss += v * v; }
    for (int o = 16; o > 0; o >>= 1) ss += __shfl_xor_sync(0xffffffffu, ss, o);
    __shared__ float wsum[8];
    if ((tid & 31) == 0) wsum[tid >> 5] = ss;
    __syncthreads();
    float tot = 0.f;
    #pragma unroll
    for (int w = 0; w < 8; w++) tot += wsum[w];
    float inv = rsqrtf(tot * (1.0f / DD) + EPS);
    for (int d = 2 * tid; d < DD; d += 512) {
        float x0 = xr[d], x1 = xr[d + 1];
        float a0 = x0 * inv * scaleA[d], a1 = x1 * inv * scaleA[d + 1];
        unsigned h, l;
        split_pack(a0, a1, h, l);
        size_t w = (size_t)row * (DD / 2) + d / 2;
        outAH[w] = h; outAL[w] = l;
        outB[(size_t)row * DD + d]     = x0 * inv * scaleB[d] * cmulB;
        outB[(size_t)row * DD + d + 1] = x1 * inv * scaleB[d + 1] * cmulB;
    }
}

// ---------------- per-head RMS (+ RoPE) ----------------
__global__ void head_norm_rope_kernel(const float* __restrict__ in,
                                      int tokStride, int colOff,
                                      unsigned* __restrict__ outH,
                                      unsigned* __restrict__ outL,
                                      const float* __restrict__ scale,
                                      const int* __restrict__ positions,
                                      int H, int doRope)
{
    int idx = blockIdx.x;
    int tid = threadIdx.x;
    int tok = idx / H;
    int h = idx - tok * H;
    int s = tok % SS;
    int b = tok / SS;
    const float* xr = in + (size_t)tok * tokStride + colOff + h * HD;
    float v = xr[tid];
    float ss = v * v;
    for (int o = 16; o > 0; o >>= 1) ss += __shfl_xor_sync(0xffffffffu, ss, o);
    __shared__ float wsum[4];
    __shared__ float tmp[HD];
    if ((tid & 31) == 0) wsum[tid >> 5] = ss;
    __syncthreads();
    float tot = wsum[0] + wsum[1] + wsum[2] + wsum[3];
    float y = v * rsqrtf(tot * (1.0f / HD) + EPS) * scale[tid];
    if (doRope) {
        tmp[tid] = y;
        __syncthreads();
        int pos = positions[b * SS + s];
        int j = tid & 63;
        float invf = powf(10000.0f, -(float)j / 64.0f);
        float ang = (float)pos * invf;
        float sn, cs;
        sincosf(ang, &sn, &cs);
        float x1 = tmp[j], x2 = tmp[64 + j];
        y = (tid < 64) ? (x1 * cs - x2 * sn) : (x2 * cs + x1 * sn);
        __syncthreads();
    }
    tmp[tid] = y;
    __syncthreads();
    if (tid < 64) {
        unsigned h2, l2;
        split_pack(tmp[2 * tid], tmp[2 * tid + 1], h2, l2);
        size_t w = (size_t)idx * 64 + tid;
        outH[w] = h2; outL[w] = l2;
    }
}

// ---------------- flash attention ----------------
#define ATQ 128
#define AKT 64
#define AST 68
#define AQ_WORDS (ATQ*AST)
#define AKV_WORDS (AKT*AST)
#define AKV_STAGE_BYTES (4*AKV_WORDS*4)
#define ATT_SMEM_BYTES ((2*AQ_WORDS + 8*AKV_WORDS)*4)

__global__ void __launch_bounds__(256, 1)
fattn_kernel(const unsigned* __restrict__ qh, const unsigned* __restrict__ ql,
             const unsigned* __restrict__ kh, const unsigned* __restrict__ kl,
             const unsigned* __restrict__ vh, const unsigned* __restrict__ vl,
             unsigned* __restrict__ obh, unsigned* __restrict__ obl)
{
    extern __shared__ __align__(16) unsigned att_smem[];
    int b = blockIdx.z, h = blockIdx.y;
    int q0 = (gridDim.x - 1 - blockIdx.x) * ATQ;
    int hkv = h / GRP;
    int tid = threadIdx.x, wid = tid >> 5, lane = tid & 31;
    int gid = lane >> 2, tgid = lane & 3;
    int l15 = lane & 15, lHi8 = (lane >> 4) << 3;

    unsigned smemBase = (unsigned)__cvta_generic_to_shared(att_smem);
    unsigned qBaseH = smemBase;
    unsigned qBaseL = smemBase + AQ_WORDS * 4;
    unsigned kvBase0 = smemBase + 2 * AQ_WORDS * 4;

    #pragma unroll
    for (int p = 0; p < 16; p++) {
        int ci = tid + p * 256;
        int plane = ci >> 11, rem = ci & 2047;
        int row = rem >> 4, c = rem & 15;
        const unsigned* src = (plane ? ql : qh)
            + ((size_t)(b * SS + q0 + row) * HQ + h) * 64 + c * 4;
        unsigned dst = (plane ? qBaseL : qBaseH) + (row * AST + c * 4) * 4;
        cp16(dst, src, 16);
    }

    int ntiles = (q0 >> 6) + 2;
    auto fillKV = [&](int st, int j0) {
        unsigned base = kvBase0 + st * AKV_STAGE_BYTES;
        #pragma unroll
        for (int p = 0; p < 16; p++) {
            int ci = tid + p * 256;
            int plane = ci >> 10, rem = ci & 1023;
            int row = rem >> 4, c = rem & 15;
            const unsigned* gp = (plane & 2) ? ((plane & 1) ? vl : vh)
                                             : ((plane & 1) ? kl : kh);
            const unsigned* src = gp + ((size_t)(b * SS + j0 + row) * HKV + hkv) * 64 + c * 4;
            unsigned dst = base + plane * (AKV_WORDS * 4) + (row * AST + c * 4) * 4;
            cp16(dst, src, 16);
        }
        CP_COMMIT();
    };

    fillKV(0, 0);
    CP_WAIT0();
    __syncthreads();

    float oacc[16][4];
    #pragma unroll
    for (int i = 0; i < 16; i++)
        #pragma unroll
        for (int c = 0; c < 4; c++) oacc[i][c] = 0.f;
    float m0 = -1e30f, m1 = -1e30f, l0r = 0.f, l1r = 0.f;

    int rowbase = q0 + wid * 16;
    int kKey = (lane & 7) + ((lane >> 4) << 3);
    int kDimOff = (lane & 8) ? 8 : 0;

    for (int jt = 0;;) {
        int j0 = jt * AKT;
        if (jt + 1 < ntiles) fillKV((jt + 1) & 1, (jt + 1) * AKT);

        if (j0 <= rowbase + 15) {
            unsigned base = kvBase0 + (jt & 1) * AKV_STAGE_BYTES;
            unsigned kBaseH = base;
            unsigned kBaseL = base + AKV_WORDS * 4;
            unsigned vBaseH = base + 2 * AKV_WORDS * 4;
            unsigned vBaseL = base + 3 * AKV_WORDS * 4;

            float s[8][4];
            #pragma unroll
            for (int nf = 0; nf < 8; nf++)
                #pragma unroll
                for (int c = 0; c < 4; c++) s[nf][c] = 0.f;

            #pragma unroll
            for (int kt = 0; kt < 8; kt++) {
                unsigned qhf[4], qlf[4];
                unsigned qoff = (unsigned)((wid * 16 + l15) * (AST * 4) + (kt * 16 + lHi8) * 2);
                LDSM4(qhf[0], qhf[1], qhf[2], qhf[3], qBaseH + qoff);
                LDSM4(qlf[0], qlf[1], qlf[2], qlf[3], qBaseL + qoff);
                int kdd = kt * 16 + kDimOff;
                #pragma unroll
                for (int g2 = 0; g2 < 4; g2++) {
                    unsigned koff = (unsigned)((g2 * 16 + kKey) * (AST * 4) + kdd * 2);
                    unsigned kh0, kh1, kh2, kh3, klo0, klo1, klo2, klo3;
                    LDSM4(kh0, kh1, kh2, kh3, kBaseH + koff);
                    LDSM4(klo0, klo1, klo2, klo3, kBaseL + koff);
                    int n0 = 2 * g2, n1 = 2 * g2 + 1;
                    MMA_BF16(s[n0][0], s[n0][1], s[n0][2], s[n0][3],
                             qlf[0], qlf[1], qlf[2], qlf[3], kh0, kh1);
                    MMA_BF16(s[n0][0], s[n0][1], s[n0][2], s[n0][3],
                             qhf[0], qhf[1], qhf[2], qhf[3], klo0, klo1);
                    MMA_BF16(s[n0][0], s[n0][1], s[n0][2], s[n0][3],
                             qhf[0], qhf[1], qhf[2], qhf[3], kh0, kh1);
                    MMA_BF16(s[n1][0], s[n1][1], s[n1][2], s[n1][3],
                             qlf[0], qlf[1], qlf[2], qlf[3], kh2, kh3);
                    MMA_BF16(s[n1][0], s[n1][1], s[n1][2], s[n1][3],
                             qhf[0], qhf[1], qhf[2], qhf[3], klo2, klo3);
                    MMA_BF16(s[n1][0], s[n1][1], s[n1][2], s[n1][3],
                             qhf[0], qhf[1], qhf[2], qhf[3], kh2, kh3);
                }
            }

            int r0 = rowbase + gid, r1 = r0 + 8;
            if (j0 + AKT - 1 > rowbase) {
                #pragma unroll
                for (int nf = 0; nf < 8; nf++) {
                    int c0 = j0 + nf * 8 + 2 * tgid;
                    if (c0 > r0)     s[nf][0] = -1e30f;
                    if (c0 + 1 > r0) s[nf][1] = -1e30f;
                    if (c0 > r1)     s[nf][2] = -1e30f;
                    if (c0 + 1 > r1) s[nf][3] = -1e30f;
                }
            }

            float t0 = -1e30f, t1 = -1e30f;
            #pragma unroll
            for (int nf = 0; nf < 8; nf++) {
                t0 = fmaxf(t0, fmaxf(s[nf][0], s[nf][1]));
                t1 = fmaxf(t1, fmaxf(s[nf][2], s[nf][3]));
            }
            t0 = fmaxf(t0, __shfl_xor_sync(0xffffffffu, t0, 1));
            t0 = fmaxf(t0, __shfl_xor_sync(0xffffffffu, t0, 2));
            t1 = fmaxf(t1, __shfl_xor_sync(0xffffffffu, t1, 1));
            t1 = fmaxf(t1, __shfl_xor_sync(0xffffffffu, t1, 2));
            float mn0 = fmaxf(m0, t0), mn1 = fmaxf(m1, t1);
            float a0 = __expf(m0 - mn0), a1 = __expf(m1 - mn1);
            m0 = mn0; m1 = mn1;
            float rs0 = 0.f, rs1 = 0.f;
            #pragma unroll
            for (int nf = 0; nf < 8; nf++) {
                s[nf][0] = __expf(s[nf][0] - mn0);
                s[nf][1] = __expf(s[nf][1] - mn0);
                s[nf][2] = __expf(s[nf][2] - mn1);
                s[nf][3] = __expf(s[nf][3] - mn1);
                rs0 += s[nf][0] + s[nf][1];
                rs1 += s[nf][2] + s[nf][3];
            }
            rs0 += __shfl_xor_sync(0xffffffffu, rs0, 1);
            rs0 += __shfl_xor_sync(0xffffffffu, rs0, 2);
            rs1 += __shfl_xor_sync(0xffffffffu, rs1, 1);
            rs1 += __shfl_xor_sync(0xffffffffu, rs1, 2);
            l0r = l0r * a0 + rs0;
            l1r = l1r * a1 + rs1;
            #pragma unroll
            for (int nv = 0; nv < 16; nv++) {
                oacc[nv][0] *= a0; oacc[nv][1] *= a0;
                oacc[nv][2] *= a1; oacc[nv][3] *= a1;
            }

            #pragma unroll
            for (int t = 0; t < 4; t++) {
                unsigned ph[4], pl[4];
                split_pack(s[2 * t][0],     s[2 * t][1],     ph[0], pl[0]);
                split_pack(s[2 * t][2],     s[2 * t][3],     ph[1], pl[1]);
                split_pack(s[2 * t + 1][0], s[2 * t + 1][1], ph[2], pl[2]);
                split_pack(s[2 * t + 1][2], s[2 * t + 1][3], ph[3], pl[3]);
                unsigned vf[16][2];
                int krow = t * 16 + l15;
                #pragma unroll
                for (int np = 0; np < 8; np++) {
                    unsigned voff = (unsigned)(krow * (AST * 4) + (np * 16 + lHi8) * 2);
                    LDSM4T(vf[2 * np][0], vf[2 * np][1], vf[2 * np + 1][0], vf[2 * np + 1][1],
                           vBaseH + voff);
                }
                #pragma unroll
                for (int nv = 0; nv < 16; nv++) {
                    MMA_BF16(oacc[nv][0], oacc[nv][1], oacc[nv][2], oacc[nv][3],
                             pl[0], pl[1], pl[2], pl[3], vf[nv][0], vf[nv][1]);
                    MMA_BF16(oacc[nv][0], oacc[nv][1], oacc[nv][2], oacc[nv][3],
                             ph[0], ph[1], ph[2], ph[3], vf[nv][0], vf[nv][1]);
                }
                #pragma unroll
                for (int np = 0; np < 8; np++) {
                    unsigned voff = (unsigned)(krow * (AST * 4) + (np * 16 + lHi8) * 2);
                    LDSM4T(vf[2 * np][0], vf[2 * np][1], vf[2 * np + 1][0], vf[2 * np + 1][1],
                           vBaseL + voff);
                }
                #pragma unroll
                for (int nv = 0; nv < 16; nv++) {
                    MMA_BF16(oacc[nv][0], oacc[nv][1], oacc[nv][2], oacc[nv][3],
                             ph[0], ph[1], ph[2], ph[3], vf[nv][0], vf[nv][1]);
                }
            }
        }

        if (++jt == ntiles) break;
        CP_WAIT0();
        __syncthreads();
    }

    int r0 = rowbase + gid, r1 = r0 + 8;
    float il0 = 1.f / l0r, il1 = 1.f / l1r;
    #pragma unroll
    for (int nv = 0; nv < 16; nv++) {
        int col = nv * 8 + 2 * tgid;
        unsigned hw, lw;
        split_pack(oacc[nv][0] * il0, oacc[nv][1] * il0, hw, lw);
        size_t w0 = ((size_t)(b * SS + r0) * HQ + h) * 64 + col / 2;
        obh[w0] = hw; obl[w0] = lw;
        split_pack(oacc[nv][2] * il1, oacc[nv][3] * il1, hw, lw);
        size_t w1 = ((size_t)(b * SS + r1) * HQ + h) * 64 + col / 2;
        obh[w1] = hw; obl[w1] = lw;
    }
}

// ================= bf16x3 GEMM =================
#define BAST 20
#define BBST 68
#define GA_WORDS (128*BAST)
#define GB_WORDS (32*BBST)
#define GSTAGE_WORDS (2*GA_WORDS + 2*GB_WORDS)
#define GEMM_DSMEM (2*GSTAGE_WORDS*4)

__global__ void __launch_bounds__(256, 2)
bf16_gemm_kernel(const unsigned* __restrict__ AhG, const unsigned* __restrict__ AlG,
                 const unsigned* __restrict__ BhG, const unsigned* __restrict__ BlG,
                 float* __restrict__ C,
                 int M, int N, int K,
                 const int* __restrict__ aIdxg,
                 const int* __restrict__ cIdxg,
                 const int* __restrict__ cntg,
                 const float* __restrict__ combine,
                 size_t aZW, size_t bZW, int idxZ)
{
    extern __shared__ __align__(16) unsigned dsm[];
    int z = blockIdx.z;
    const unsigned* Ah = AhG + (size_t)z * aZW;
    const unsigned* Al = AlG + (size_t)z * aZW;
    const unsigned* Bh = BhG + (size_t)z * bZW;
    const unsigned* Bl = BlG + (size_t)z * bZW;
    const int* aIdx = aIdxg ? aIdxg + (size_t)z * idxZ : nullptr;
    const int* cIdx = cIdxg ? cIdxg + (size_t)z * idxZ : nullptr;
    int Meff = cntg ? min(M, cntg[z]) : M;
    int bm = blockIdx.y * 128;
    int bn = blockIdx.x * 128;
    if (bm >= Meff) return;
    int Kw = K >> 1, Nw = N >> 1, bnw = bn >> 1;

    int tid = threadIdx.x;
    int wid = tid >> 5, lane = tid & 31;
    int gid = lane >> 2, tgid = lane & 3;
    int wm = (wid & 3) * 32;
    int wn = (wid >> 2) * 64;
    int l15 = lane & 15, lHi8 = (lane >> 4) << 3;

    int am = tid >> 1, ac = (tid & 1) * 2;
    int gr = bm + am;
    int ar = (gr < Meff) ? (aIdx ? aIdx[gr] : gr) : 0;
    int aValid = (gr < Meff) ? 16 : 0;
    const unsigned* aRowH = Ah + (size_t)ar * Kw;
    const unsigned* aRowL = Al + (size_t)ar * Kw;
    int bk = tid >> 3, bc = (2 * tid) & 15;

    unsigned smemBase = (unsigned)__cvta_generic_to_shared(dsm);

    auto fillStage = [&](int st, int k0) {
        int kw0 = k0 >> 1;
        unsigned base = smemBase + st * (GSTAGE_WORDS * 4);
        unsigned aHb = base, aLb = base + GA_WORDS * 4;
        unsigned bHb = aLb + GA_WORDS * 4, bLb = bHb + GB_WORDS * 4;
        #pragma unroll
        for (int c2 = 0; c2 < 2; c2++) {
            int c = ac + c2;
            unsigned d = (am * BAST + c * 4) * 4;
            cp16(aHb + d, aRowH + kw0 + c * 4, aValid);
            cp16(aLb + d, aRowL + kw0 + c * 4, aValid);
        }
        size_t bro = (size_t)(k0 + bk) * Nw + bnw;
        #pragma unroll
        for (int c2 = 0; c2 < 2; c2++) {
            int c = bc + c2;
            unsigned d = (bk * BBST + c * 4) * 4;
            cp16(bHb + d, Bh + bro + c * 4, 16);
            cp16(bLb + d, Bl + bro + c * 4, 16);
        }
        CP_COMMIT();
    };

    float acc[2][8][4];
    #pragma unroll
    for (int i = 0; i < 2; i++)
        #pragma unroll
        for (int j = 0; j < 8; j++)
            #pragma unroll
            for (int c = 0; c < 4; c++) acc[i][j][c] = 0.f;

    int KT = K >> 5;
    fillStage(0, 0);
    CP_WAIT0();
    __syncthreads();

    for (int kt = 0;;) {
        if (kt + 1 < KT) fillStage((kt + 1) & 1, (kt + 1) << 5);

        unsigned base = smemBase + (kt & 1) * (GSTAGE_WORDS * 4);
        unsigned aBaseH = base, aBaseL = base + GA_WORDS * 4;
        unsigned bBaseH = aBaseL + GA_WORDS * 4, bBaseL = bBaseH + GB_WORDS * 4;

        #pragma unroll
        for (int ks = 0; ks < 2; ks++) {
            int kk = ks * 16;
            unsigned ah[2][4], al[2][4];
            #pragma unroll
            for (int mf = 0; mf < 2; mf++) {
                int mrow = wm + mf * 16 + l15;
                unsigned off = (unsigned)(mrow * (BAST * 4) + (kk + lHi8) * 2);
                LDSM4(ah[mf][0], ah[mf][1], ah[mf][2], ah[mf][3], aBaseH + off);
                LDSM4(al[mf][0], al[mf][1], al[mf][2], al[mf][3], aBaseL + off);
            }
            unsigned bfr[8][2];
            int krow = kk + l15;
            #pragma unroll
            for (int nfp = 0; nfp < 4; nfp++) {
                int ncol = wn + nfp * 16 + lHi8;
                unsigned off = (unsigned)(krow * (BBST * 4) + ncol * 2);
                LDSM4T(bfr[2 * nfp][0], bfr[2 * nfp][1],
                       bfr[2 * nfp + 1][0], bfr[2 * nfp + 1][1], bBaseH + off);
            }
            #pragma unroll
            for (int mf = 0; mf < 2; mf++)
                #pragma unroll
                for (int nf = 0; nf < 8; nf++) {
                    MMA_BF16(acc[mf][nf][0], acc[mf][nf][1], acc[mf][nf][2], acc[mf][nf][3],
                             ah[mf][0], ah[mf][1], ah[mf][2], ah[mf][3],
                             bfr[nf][0], bfr[nf][1]);
                    MMA_BF16(acc[mf][nf][0], acc[mf][nf][1], acc[mf][nf][2], acc[mf][nf][3],
                             al[mf][0], al[mf][1], al[mf][2], al[mf][3],
                             bfr[nf][0], bfr[nf][1]);
                }
            #pragma unroll
            for (int nfp = 0; nfp < 4; nfp++) {
                int ncol = wn + nfp * 16 + lHi8;
                unsigned off = (unsigned)(krow * (BBST * 4) + ncol * 2);
                LDSM4T(bfr[2 * nfp][0], bfr[2 * nfp][1],
                       bfr[2 * nfp + 1][0], bfr[2 * nfp + 1][1], bBaseL + off);
            }
            #pragma unroll
            for (int mf = 0; mf < 2; mf++)
                #pragma unroll
                for (int nf = 0; nf < 8; nf++) {
                    MMA_BF16(acc[mf][nf][0], acc[mf][nf][1], acc[mf][nf][2], acc[mf][nf][3],
                             ah[mf][0], ah[mf][1], ah[mf][2], ah[mf][3],
                             bfr[nf][0], bfr[nf][1]);
                }
        }

        if (++kt == KT) break;
        CP_WAIT0();
        __syncthreads();
    }

    #pragma unroll
    for (int mf = 0; mf < 2; mf++) {
        #pragma unroll
        for (int half = 0; half < 2; half++) {
            int row = bm + wm + mf * 16 + gid + half * 8;
            if (row >= Meff) continue;
            int crow = cIdx ? cIdx[row] : row;
            float w = 1.f;
            if (combine) w = combine[crow * EE + z];
            #pragma unroll
            for (int nf = 0; nf < 8; nf++) {
                int col = bn + wn + nf * 8 + 2 * tgid;
                float v0 = acc[mf][nf][half * 2 + 0];
                float v1 = acc[mf][nf][half * 2 + 1];
                float* cp = C + (size_t)crow * N + col;
                if (combine) {
                    atomicAdd(cp, w * v0);
                    atomicAdd(cp + 1, w * v1);
                } else {
                    cp[0] = v0;
                    cp[1] = v1;
                }
            }
        }
    }
}

// ========== gated dual-B bf16x3 GEMM ==========
__global__ void __launch_bounds__(256, 2)
bf16_gated_kernel(const unsigned* __restrict__ Ah, const unsigned* __restrict__ Al,
                  const unsigned* __restrict__ B0hG, const unsigned* __restrict__ B0lG,
                  const unsigned* __restrict__ B1hG, const unsigned* __restrict__ B1lG,
                  unsigned* __restrict__ ChG, unsigned* __restrict__ ClG,
                  int M, int Nout, int K,
                  const int* __restrict__ aIdxg,
                  const int* __restrict__ cntg,
                  size_t bZW, size_t cZW, int idxZ)
{
    extern __shared__ __align__(16) unsigned dsm[];
    int z = blockIdx.z;
    const unsigned* B0h = B0hG + (size_t)z * bZW;
    const unsigned* B0l = B0lG + (size_t)z * bZW;
    const unsigned* B1h = B1hG + (size_t)z * bZW;
    const unsigned* B1l = B1lG + (size_t)z * bZW;
    unsigned* Ch = ChG + (size_t)z * cZW;
    unsigned* Cl = ClG + (size_t)z * cZW;
    const int* aIdx = aIdxg ? aIdxg + (size_t)z * idxZ : nullptr;
    int Meff = cntg ? min(M, cntg[z]) : M;
    int bm = blockIdx.y * 128;
    int bnn = blockIdx.x * 64;
    if (bm >= Meff) return;
    int Kw = K >> 1, Nw = Nout >> 1, bnw = bnn >> 1;

    int tid = threadIdx.x;
    int wid = tid >> 5, lane = tid & 31;
    int gid = lane >> 2, tgid = lane & 3;
    int wm = (wid & 3) * 32;
    int wn32 = (wid >> 2) * 32;
    int l15 = lane & 15, lHi8 = (lane >> 4) << 3;

    int am = tid >> 1, ac = (tid & 1) * 2;
    int gr = bm + am;
    int ar = (gr < Meff) ? (aIdx ? aIdx[gr] : gr) : 0;
    int aValid = (gr < Meff) ? 16 : 0;
    const unsigned* aRowH = Ah + (size_t)ar * Kw;
    const unsigned* aRowL = Al + (size_t)ar * Kw;
    int bk = tid >> 3;
    int brest = (2 * tid) & 15;

    unsigned smemBase = (unsigned)__cvta_generic_to_shared(dsm);

    auto fillStage = [&](int st, int k0) {
        int kw0 = k0 >> 1;
        unsigned base = smemBase + st * (GSTAGE_WORDS * 4);
        unsigned aHb = base, aLb = base + GA_WORDS * 4;
        unsigned bHb = aLb + GA_WORDS * 4, bLb = bHb + GB_WORDS * 4;
        #pragma unroll
        for (int c2 = 0; c2 < 2; c2++) {
            int c = ac + c2;
            unsigned d = (am * BAST + c * 4) * 4;
            cp16(aHb + d, aRowH + kw0 + c * 4, aValid);
            cp16(aLb + d, aRowL + kw0 + c * 4, aValid);
        }
        size_t bro = (size_t)(k0 + bk) * Nw + bnw;
        #pragma unroll
        for (int c2 = 0; c2 < 2; c2++) {
            int cc = brest + c2;
            int srcSel = cc >> 3, c = cc & 7;
            unsigned d = (bk * BBST + srcSel * 32 + c * 4) * 4;
            cp16(bHb + d, (srcSel ? B1h : B0h) + bro + c * 4, 16);
            cp16(bLb + d, (srcSel ? B1l : B0l) + bro + c * 4, 16);
        }
        CP_COMMIT();
    };

    float acc0[2][4][4], acc1[2][4][4];
    #pragma unroll
    for (int i = 0; i < 2; i++)
        #pragma unroll
        for (int j = 0; j < 4; j++)
            #pragma unroll
            for (int c = 0; c < 4; c++) { acc0[i][j][c] = 0.f; acc1[i][j][c] = 0.f; }

    int KT = K >> 5;
    fillStage(0, 0);
    CP_WAIT0();
    __syncthreads();

    for (int kt = 0;;) {
        if (kt + 1 < KT) fillStage((kt + 1) & 1, (kt + 1) << 5);

        unsigned base = smemBase + (kt & 1) * (GSTAGE_WORDS * 4);
        unsigned aBaseH = base, aBaseL = base + GA_WORDS * 4;
        unsigned bBaseH = aBaseL + GA_WORDS * 4, bBaseL = bBaseH + GB_WORDS * 4;

        #pragma unroll
        for (int ks = 0; ks < 2; ks++) {
            int kk = ks * 16;
            unsigned ah[2][4], al[2][4];
            #pragma unroll
            for (int mf = 0; mf < 2; mf++) {
                int mrow = wm + mf * 16 + l15;
                unsigned off = (unsigned)(mrow * (BAST * 4) + (kk + lHi8) * 2);
                LDSM4(ah[mf][0], ah[mf][1], ah[mf][2], ah[mf][3], aBaseH + off);
                LDSM4(al[mf][0], al[mf][1], al[mf][2], al[mf][3], aBaseL + off);
            }
            int krow = kk + l15;
            #pragma unroll
            for (int which = 0; which < 2; which++) {
                unsigned bfr[4][2];
                int colbase = which * 64 + wn32;
                #pragma unroll
                for (int nfp = 0; nfp < 2; nfp++) {
                    int ncol = colbase + nfp * 16 + lHi8;
                    unsigned off = (unsigned)(krow * (BBST * 4) + ncol * 2);
                    LDSM4T(bfr[2 * nfp][0], bfr[2 * nfp][1],
                           bfr[2 * nfp + 1][0], bfr[2 * nfp + 1][1], bBaseH + off);
                }
                #pragma unroll
                for (int mf = 0; mf < 2; mf++)
                    #pragma unroll
                    for (int nf = 0; nf < 4; nf++) {
                        float* a = which ? acc1[mf][nf] : acc0[mf][nf];
                        MMA_BF16(a[0], a[1], a[2], a[3],
                                 ah[mf][0], ah[mf][1], ah[mf][2], ah[mf][3],
                                 bfr[nf][0], bfr[nf][1]);
                        MMA_BF16(a[0], a[1], a[2], a[3],
                                 al[mf][0], al[mf][1], al[mf][2], al[mf][3],
                                 bfr[nf][0], bfr[nf][1]);
                    }
                #pragma unroll
                for (int nfp = 0; nfp < 2; nfp++) {
                    int ncol = colbase + nfp * 16 + lHi8;
                    unsigned off = (unsigned)(krow * (BBST * 4) + ncol * 2);
                    LDSM4T(bfr[2 * nfp][0], bfr[2 * nfp][1],
                           bfr[2 * nfp + 1][0], bfr[2 * nfp + 1][1], bBaseL + off);
                }
                #pragma unroll
                for (int mf = 0; mf < 2; mf++)
                    #pragma unroll
                    for (int nf = 0; nf < 4; nf++) {
                        float* a = which ? acc1[mf][nf] : acc0[mf][nf];
                        MMA_BF16(a[0], a[1], a[2], a[3],
                                 ah[mf][0], ah[mf][1], ah[mf][2], ah[mf][3],
                                 bfr[nf][0], bfr[nf][1]);
                    }
            }
        }

        if (++kt == KT) break;
        CP_WAIT0();
        __syncthreads();
    }

    #pragma unroll
    for (int mf = 0; mf < 2; mf++) {
        #pragma unroll
        for (int half = 0; half < 2; half++) {
            int row = bm + wm + mf * 16 + gid + half * 8;
            if (row >= Meff) continue;
            #pragma unroll
            for (int nf = 0; nf < 4; nf++) {
                int col = bnn + wn32 + nf * 8 + 2 * tgid;
                float g0v = gelu_tanh(acc0[mf][nf][half * 2 + 0]) * acc1[mf][nf][half * 2 + 0];
                float g1v = gelu_tanh(acc0[mf][nf][half * 2 + 1]) * acc1[mf][nf][half * 2 + 1];
                unsigned hw, lw;
                split_pack(g0v, g1v, hw, lw);
                size_t w = (size_t)row * Nw + (col >> 1);
                Ch[w] = hw; Cl[w] = lw;
            }
        }
    }
}

// ---------------- router ----------------
__global__ void router_kernel(const float* __restrict__ gin,
                              const float* __restrict__ wg,
                              float* __restrict__ combine,
                              int* __restrict__ cnt,
                              int* __restrict__ idx,
                              float* __restrict__ psum)
{
    int tok = blockIdx.x;
    int tid = threadIdx.x;
    float s[EE] = {};
    const float* g = gin + (size_t)tok * DD;
    for (int d = tid; d < DD; d += 256) {
        float gv = g[d];
        const float* w = wg + d * EE;
        #pragma unroll
        for (int e = 0; e < EE; e++) s[e] += gv * w[e];
    }
    __shared__ float sh[256][EE];
    #pragma unroll
    for (int e = 0; e < EE; e++) sh[tid][e] = s[e];
    __syncthreads();
    for (int str = 128; str > 0; str >>= 1) {
        if (tid < str) {
            #pragma unroll
            for (int e = 0; e < EE; e++) sh[tid][e] += sh[tid + str][e];
        }
        __syncthreads();
    }
    if (tid == 0) {
        float pe[EE];
        float mx = -FLT_MAX;
        #pragma unroll
        for (int e = 0; e < EE; e++) mx = fmaxf(mx, sh[0][e]);
        float sum = 0.f;
        #pragma unroll
        for (int e = 0; e < EE; e++) { pe[e] = expf(sh[0][e] - mx); sum += pe[e]; }
        float inv = 1.0f / sum;
        #pragma unroll
        for (int e = 0; e < EE; e++) { pe[e] *= inv; atomicAdd(&psum[e], pe[e]); }
        int i0 = 0;
        #pragma unroll
        for (int e = 1; e < EE; e++) if (pe[e] > pe[i0]) i0 = e;
        int i1 = (i0 == 0) ? 1 : 0;
        #pragma unroll
        for (int e = 0; e < EE; e++) if (e != i0 && e != i1 && pe[e] > pe[i1]) i1 = e;
        float tot = pe[i0] + pe[i1];
        float w0 = pe[i0] / tot, w1 = pe[i1] / tot;
        float* crow = combine + (size_t)tok * EE;
        #pragma unroll
        for (int e = 0; e < EE; e++) crow[e] = 0.f;
        crow[i0] = w0; crow[i1] = w1;
        int p0 = atomicAdd(&cnt[i0], 1); idx[i0 * TT + p0] = tok;
        int p1 = atomicAdd(&cnt[i1], 1); idx[i1 * TT + p1] = tok;
    }
}

__global__ void lb_kernel(const int* __restrict__ cnt, const float* __restrict__ psum,
                          float* __restrict__ out)
{
    float lb = 0.f;
    #pragma unroll
    for (int e = 0; e < EE; e++)
        lb += ((float)cnt[e] / (float)TT) * (psum[e] / (float)TT);
    out[0] = lb * ((float)(EE * EE) / (float)EE);
}

// ==================== host launcher ====================
extern "C" void kernel_launch(void* const* d_in, const int* in_sizes, int n_in,
                              void* d_out, int out_size)
{
    const int*   positions       = (const int*)  d_in[0];
    const float* x               = (const float*)d_in[1];
    const float* pre_attn_scale  = (const float*)d_in[2];
    const float* wq              = (const float*)d_in[3];
    const float* wk              = (const float*)d_in[4];
    const float* wv              = (const float*)d_in[5];
    const float* wo              = (const float*)d_in[6];
    const float* q_norm_scale    = (const float*)d_in[7];
    const float* k_norm_scale    = (const float*)d_in[8];
    const float* v_norm_scale    = (const float*)d_in[9];
    const float* post_attn_scale = (const float*)d_in[10];
    const float* pre_ffw_scale   = (const float*)d_in[11];
    const float* shared_wi0      = (const float*)d_in[12];
    const float* shared_wi1      = (const float*)d_in[13];
    const float* shared_wo       = (const float*)d_in[14];
    const float* post_ff1_scale  = (const float*)d_in[15];
    const float* pre_ff2_scale   = (const float*)d_in[16];
    const float* router_scale    = (const float*)d_in[17];
    const float* w_gate          = (const float*)d_in[18];
    const float* ewi0            = (const float*)d_in[19];
    const float* ewi1            = (const float*)d_in[20];
    const float* ewo             = (const float*)d_in[21];
    const float* post_ff2_scale  = (const float*)d_in[22];
    const float* layer_scalar    = (const float*)d_in[23];
    float* out = (float*)d_out;

    static cudaStream_t s2 = nullptr;
    static cudaEvent_t evFork = nullptr, evJoin = nullptr;
    static cudaEvent_t evFork2 = nullptr, evJoin2 = nullptr;
    static int inited = 0;
    if (!inited) {
        cudaFuncSetAttribute(fattn_kernel,
                             cudaFuncAttributeMaxDynamicSharedMemorySize, ATT_SMEM_BYTES);
        cudaFuncSetAttribute(bf16_gemm_kernel,
                             cudaFuncAttributeMaxDynamicSharedMemorySize, GEMM_DSMEM);
        cudaFuncSetAttribute(bf16_gated_kernel,
                             cudaFuncAttributeMaxDynamicSharedMemorySize, GEMM_DSMEM);
        cudaStreamCreateWithFlags(&s2, cudaStreamNonBlocking);
        cudaEventCreateWithFlags(&evFork, cudaEventDisableTiming);
        cudaEventCreateWithFlags(&evJoin, cudaEventDisableTiming);
        cudaEventCreateWithFlags(&evFork2, cudaEventDisableTiming);
        cudaEventCreateWithFlags(&evJoin2, cudaEventDisableTiming);
        inited = 1;
    }

    float* sc = nullptr;
    int*   isc = nullptr;
    cudaGetSymbolAddress((void**)&sc, g_scratch);
    cudaGetSymbolAddress((void**)&isc, g_iscratch);

    unsigned* U = (unsigned*)sc;
    auto uptr = [&](size_t off) { return U + off; };

    unsigned* lnxH = uptr(OFF_LNXH); unsigned* lnxL = uptr(OFF_LNXL);
    float* qkvf = sc + OFF_QKVF;
    unsigned* qsh = uptr(OFF_QH); unsigned* qsl = uptr(OFF_QL);
    unsigned* ksh = uptr(OFF_KH); unsigned* ksl = uptr(OFF_KL);
    unsigned* vsh = uptr(OFF_VH); unsigned* vsl = uptr(OFF_VL);
    unsigned* obh = uptr(OFF_OBH); unsigned* obl = uptr(OFF_OBL);
    float* attnb = sc + OFF_ATTN; float* hb = sc + OFF_H;
    unsigned* ffinH = uptr(OFF_FFINH); unsigned* ffinL = uptr(OFF_FFINL);
    unsigned* g0H = uptr(OFF_G0H); unsigned* g0L = uptr(OFF_G0L);
    float* shb = sc + OFF_SHB;
    unsigned* rinH = uptr(OFF_RINH); unsigned* rinL = uptr(OFF_RINL);
    float* gin = sc + OFF_GIN; float* routb = sc + OFF_ROUT;
    unsigned* egH = uptr(OFF_EGH); unsigned* egL = uptr(OFF_EGL);
    float* comb = sc + OFF_COMB; float* psum = sc + OFF_PSUM;
    int* idx = isc; int* cnt = isc + EE * TT;

    auto splitBF = [&](const float* src, size_t nElts, size_t offH, size_t offL,
                       cudaStream_t st) {
        size_t nQ = nElts / 4;
        split_bf_kernel<<<(unsigned)((nQ + 255) / 256), 256, 0, st>>>(
            (const float4*)src, (uint2*)uptr(offH), (uint2*)uptr(offL), nQ);
    };

    // QKV concat split on main stream (needed at step 2)
    split_qkv_kernel<<<(unsigned)(SZ_WQKV / 4 / 256), 256>>>(
        wq, wk, wv, (uint2*)uptr(OFF_WQKVH), (uint2*)uptr(OFF_WQKVL));

    // Weight splits + MoE memsets forked to s2, overlapping steps 1-4
    cudaEventRecord(evFork, 0);
    cudaStreamWaitEvent(s2, evFork, 0);
    splitBF(wo, SZ_WQ, OFF_WOH, OFF_WOL, s2);
    splitBF(shared_wi0, SZ_WFF, OFF_WI0H, OFF_WI0L, s2);
    splitBF(shared_wi1, SZ_WFF, OFF_WI1H, OFF_WI1L, s2);
    splitBF(shared_wo, SZ_WFF, OFF_SWOH, OFF_SWOL, s2);
    splitBF(ewi0, SZ_EW, OFF_EWI0H, OFF_EWI0L, s2);
    splitBF(ewi1, SZ_EW, OFF_EWI1H, OFF_EWI1L, s2);
    splitBF(ewo, SZ_EW, OFF_EWOH, OFF_EWOL, s2);
    cudaMemsetAsync(cnt, 0, EE * sizeof(int), s2);
    cudaMemsetAsync(psum, 0, EE * sizeof(float), s2);
    cudaMemsetAsync(routb, 0, SZ_TD * sizeof(float), s2);
    cudaEventRecord(evJoin, s2);

    auto gemm = [&](const unsigned* Ah, const unsigned* Al,
                    size_t BhOff, size_t BlOff, float* C, int M, int N, int K,
                    const int* aI, const int* cI, const int* ct, const float* cw,
                    size_t aZW, size_t bZW, int nz, cudaStream_t st) {
        dim3 grid(N / 128, (M + 127) / 128, nz);
        bf16_gemm_kernel<<<grid, 256, GEMM_DSMEM, st>>>(Ah, Al, uptr(BhOff), uptr(BlOff),
                                                        C, M, N, K, aI, cI, ct, cw,
                                                        aZW, bZW, TT);
    };

    // 1) pre-attn norm
    rms_kernel<<<TT, 256>>>(x, pre_attn_scale, 1.f, nullptr, nullptr, nullptr,
                            nullptr, lnxH, lnxL);
    // 2) fused QKV projection
    gemm(lnxH, lnxL, OFF_WQKVH, OFF_WQKVL, qkvf, TT, NQKV, DD,
         nullptr, nullptr, nullptr, nullptr, 0, 0, 1, 0);
    // 3) per-head norms + rope
    head_norm_rope_kernel<<<TT * HQ, HD>>>(qkvf, NQKV, 0, qsh, qsl,
                                           q_norm_scale, positions, HQ, 1);
    head_norm_rope_kernel<<<TT * HKV, HD>>>(qkvf, NQKV, 2048, ksh, ksl,
                                            k_norm_scale, positions, HKV, 1);
    head_norm_rope_kernel<<<TT * HKV, HD>>>(qkvf, NQKV, 3072, vsh, vsl,
                                            v_norm_scale, positions, HKV, 0);
    // 4) attention
    {
        dim3 grid(SS / ATQ, HQ, BB);
        fattn_kernel<<<grid, 256, ATT_SMEM_BYTES>>>(qsh, qsl, ksh, ksl, vsh, vsl, obh, obl);
    }
    // join: s2 weight splits + memsets must be done
    cudaStreamWaitEvent(0, evJoin, 0);
    // 5) output projection + post-attn norm + residual  -> hb
    gemm(obh, obl, OFF_WOH, OFF_WOL, attnb, TT, DD, HQ * HD,
         nullptr, nullptr, nullptr, nullptr, 0, 0, 1, 0);
    rms_kernel<<<TT, 256>>>(attnb, post_attn_scale, 1.f, x, nullptr, nullptr,
                            hb, nullptr, nullptr);

    // ---- fork 2: shared FFN on s2, MoE on main (both depend only on hb) ----
    cudaEventRecord(evFork2, 0);
    cudaStreamWaitEvent(s2, evFork2, 0);

    // 6) shared FFN (on s2)
    rms_kernel<<<TT, 256, 0, s2>>>(hb, pre_ffw_scale, 1.f, nullptr, nullptr, nullptr,
                                   nullptr, ffinH, ffinL);
    {
        dim3 grid(FS / 64, TT / 128, 1);
        bf16_gated_kernel<<<grid, 256, GEMM_DSMEM, s2>>>(
            ffinH, ffinL, uptr(OFF_WI0H), uptr(OFF_WI0L), uptr(OFF_WI1H), uptr(OFF_WI1L),
            g0H, g0L, TT, FS, DD, nullptr, nullptr, 0, 0, TT);
    }
    gemm(g0H, g0L, OFF_SWOH, OFF_SWOL, shb, TT, DD, FS,
         nullptr, nullptr, nullptr, nullptr, 0, 0, 1, s2);
    rms_kernel<<<TT, 256, 0, s2>>>(shb, post_ff1_scale, 1.f, nullptr, nullptr, nullptr,
                                   shb, nullptr, nullptr);
    cudaEventRecord(evJoin2, s2);

    // 7+8) MoE path (on main)
    rms_dual_kernel<<<TT, 256>>>(hb, pre_ff2_scale, rinH, rinL,
                                 router_scale, 0.02209708691207961f, gin);
    router_kernel<<<TT, 256>>>(gin, w_gate, comb, cnt, idx, psum);
    {
        dim3 grid(FE / 64, TT / 128, EE);
        bf16_gated_kernel<<<grid, 256, GEMM_DSMEM>>>(
            rinH, rinL, uptr(OFF_EWI0H), uptr(OFF_EWI0L), uptr(OFF_EWI1H), uptr(OFF_EWI1L),
            egH, egL, TT, FE, DD, idx, cnt,
            (size_t)DD * FE / 2, (size_t)TT * FE / 2, TT);
    }
    {
        dim3 grid(DD / 128, TT / 128, EE);
        bf16_gemm_kernel<<<grid, 256, GEMM_DSMEM>>>(
            egH, egL, uptr(OFF_EWOH), uptr(OFF_EWOL), routb, TT, DD, FE,
            nullptr, idx, cnt, comb,
            (size_t)TT * FE / 2, (size_t)FE * DD / 2, TT);
    }

    // join shared-FFN branch before final combine
    cudaStreamWaitEvent(0, evJoin2, 0);
    // 9) final combine
    rms_kernel<<<TT, 256>>>(routb, post_ff2_scale, 1.f, shb, hb, layer_scalar,
                            out, nullptr, nullptr);
    // 10) lb loss
    if (out_size > TT * DD) {
        lb_kernel<<<1, 1>>>(cnt, psum, out + (size_t)TT * DD);
    }
}